// round 1
// baseline (speedup 1.0000x reference)
#include <cuda_runtime.h>
#include <math.h>

// Problem constants (fixed shapes per metadata)
constexpr int NN   = 10000;   // nodes
constexpr int NE   = 160000;  // edges
constexpr int DIN  = 128;     // input feature dim
constexpr int EDIM = 16;      // edge feature dim
constexpr int H_   = 4;       // heads
constexpr int C_   = 256;     // channels per head
constexpr int HC   = 1024;    // H*C
constexpr int DOUT = 25088;   // final output dim

// ---------------- scratch (static device globals: allocation-free) ----------
__device__ float g_xw[NN * HC];        // x @ W  (per layer)
__device__ float g_h[NN * HC];         // layer output
__device__ float g_al_src[NN * H_];
__device__ float g_al_dst[NN * H_];
__device__ float g_al_e[NE * H_];
__device__ float g_al_esum[NN * H_];   // segment_sum of al_e by dst (for self-loop mean attr)
__device__ float g_alpha[NE * H_];     // leaky logits, later overwritten with exp()
__device__ float g_aself[NN * H_];     // self-loop leaky logits
__device__ float g_V[EDIM * H_];       // We folded with a_edge:  al_e = ea @ V
__device__ int   g_deg[NN];
__device__ int   g_rowptr[NN + 1];
__device__ int   g_cursor[NN];
__device__ int   g_esorted[NE];        // edge ids sorted by dst (CSR)

// ---------------- graph structure kernels ----------------------------------
__global__ void k_zero_deg() {
    int i = blockIdx.x * blockDim.x + threadIdx.x;
    if (i < NN) g_deg[i] = 0;
}

__global__ void k_zero_esum() {
    int i = blockIdx.x * blockDim.x + threadIdx.x;
    if (i < NN * H_) g_al_esum[i] = 0.f;
}

__global__ void k_count(const int* __restrict__ dst) {
    int e = blockIdx.x * blockDim.x + threadIdx.x;
    if (e < NE) atomicAdd(&g_deg[dst[e]], 1);
}

// single-block scan over NN degrees -> rowptr + cursor
__global__ void k_scan() {
    __shared__ int sh[1024];
    __shared__ int carry;
    int t = threadIdx.x;
    if (t == 0) carry = 0;
    __syncthreads();
    for (int base = 0; base < NN; base += 1024) {
        int i = base + t;
        int v = (i < NN) ? g_deg[i] : 0;
        sh[t] = v;
        __syncthreads();
        for (int off = 1; off < 1024; off <<= 1) {
            int xv = (t >= off) ? sh[t - off] : 0;
            __syncthreads();
            if (t >= off) sh[t] += xv;
            __syncthreads();
        }
        int excl = sh[t] - v + carry;
        if (i < NN) { g_rowptr[i] = excl; g_cursor[i] = excl; }
        int tot = sh[1023];
        __syncthreads();
        if (t == 0) carry += tot;
        __syncthreads();
    }
    if (t == 0) g_rowptr[NN] = carry;
}

__global__ void k_fill(const int* __restrict__ dst) {
    int e = blockIdx.x * blockDim.x + threadIdx.x;
    if (e < NE) {
        int p = atomicAdd(&g_cursor[dst[e]], 1);
        g_esorted[p] = e;
    }
}

// ---------------- SGEMM: C[M,N] = A[M,K] @ B[K,N] (+bias) ------------------
// 128x128 tile, 256 threads, 8x8 per thread, BK=8. K % 8 == 0, N % 128 == 0.
template <bool BIAS>
__global__ void __launch_bounds__(256)
k_sgemm(const float* __restrict__ A, const float* __restrict__ B,
        const float* __restrict__ bias, float* __restrict__ Cm,
        int M, int Nn, int K) {
    __shared__ float As[8][128];
    __shared__ float Bs[8][128];
    const int bm = blockIdx.y * 128, bn = blockIdx.x * 128;
    const int tid  = threadIdx.x;
    const int tx   = tid & 15, ty = tid >> 4;
    const int arow = tid >> 1, acol = (tid & 1) * 4;
    const int brow = tid >> 5, bcol = (tid & 31) * 4;

    float acc[8][8];
#pragma unroll
    for (int i = 0; i < 8; i++)
#pragma unroll
        for (int j = 0; j < 8; j++) acc[i][j] = 0.f;

    for (int k0 = 0; k0 < K; k0 += 8) {
        float4 av = make_float4(0.f, 0.f, 0.f, 0.f);
        if (bm + arow < M)
            av = *reinterpret_cast<const float4*>(A + (size_t)(bm + arow) * K + k0 + acol);
        As[acol + 0][arow] = av.x;
        As[acol + 1][arow] = av.y;
        As[acol + 2][arow] = av.z;
        As[acol + 3][arow] = av.w;
        float4 bv = *reinterpret_cast<const float4*>(B + (size_t)(k0 + brow) * Nn + bn + bcol);
        *reinterpret_cast<float4*>(&Bs[brow][bcol]) = bv;
        __syncthreads();
#pragma unroll
        for (int k = 0; k < 8; k++) {
            float a[8], b[8];
            float4 t0 = *reinterpret_cast<const float4*>(&As[k][ty * 8]);
            float4 t1 = *reinterpret_cast<const float4*>(&As[k][ty * 8 + 4]);
            float4 t2 = *reinterpret_cast<const float4*>(&Bs[k][tx * 8]);
            float4 t3 = *reinterpret_cast<const float4*>(&Bs[k][tx * 8 + 4]);
            a[0]=t0.x; a[1]=t0.y; a[2]=t0.z; a[3]=t0.w; a[4]=t1.x; a[5]=t1.y; a[6]=t1.z; a[7]=t1.w;
            b[0]=t2.x; b[1]=t2.y; b[2]=t2.z; b[3]=t2.w; b[4]=t3.x; b[5]=t3.y; b[6]=t3.z; b[7]=t3.w;
#pragma unroll
            for (int i = 0; i < 8; i++)
#pragma unroll
                for (int j = 0; j < 8; j++) acc[i][j] = fmaf(a[i], b[j], acc[i][j]);
        }
        __syncthreads();
    }

#pragma unroll
    for (int i = 0; i < 8; i++) {
        int m = bm + ty * 8 + i;
        if (m >= M) continue;
#pragma unroll
        for (int j = 0; j < 8; j += 4) {
            int n = bn + tx * 8 + j;
            float4 v;
            v.x = acc[i][j]; v.y = acc[i][j + 1]; v.z = acc[i][j + 2]; v.w = acc[i][j + 3];
            if (BIAS) { v.x += bias[n]; v.y += bias[n + 1]; v.z += bias[n + 2]; v.w += bias[n + 3]; }
            *reinterpret_cast<float4*>(Cm + (size_t)m * Nn + n) = v;
        }
    }
}

// ---------------- attention logit pieces ------------------------------------
// al_src[n,h] = <xw[n,h,:], a_src[h,:]> ; same for dst.  1 block/node, warp/head.
__global__ void k_al(const float* __restrict__ xw,
                     const float* __restrict__ asrc, const float* __restrict__ adst) {
    int n = blockIdx.x;
    int w = threadIdx.x >> 5, l = threadIdx.x & 31;
    const float* row = xw + (size_t)n * HC + w * C_;
    const float* as  = asrc + w * C_;
    const float* ad  = adst + w * C_;
    float s = 0.f, d = 0.f;
    for (int c = l; c < C_; c += 32) {
        float v = row[c];
        s += v * as[c];
        d += v * ad[c];
    }
#pragma unroll
    for (int off = 16; off; off >>= 1) {
        s += __shfl_xor_sync(0xffffffffu, s, off);
        d += __shfl_xor_sync(0xffffffffu, d, off);
    }
    if (l == 0) { g_al_src[n * H_ + w] = s; g_al_dst[n * H_ + w] = d; }
}

// V[d,h] = sum_c We[d, h*C+c] * a_edge[h,c]   (folds edge GEMM to [16,4])
__global__ void k_V(const float* __restrict__ We, const float* __restrict__ aedge) {
    int w = threadIdx.x >> 5, l = threadIdx.x & 31;
    for (int o = w; o < EDIM * H_; o += 8) {
        int d = o / H_, h = o % H_;
        float s = 0.f;
        for (int c = l; c < C_; c += 32)
            s += We[(size_t)d * HC + h * C_ + c] * aedge[h * C_ + c];
#pragma unroll
        for (int off = 16; off; off >>= 1) s += __shfl_xor_sync(0xffffffffu, s, off);
        if (l == 0) g_V[o] = s;
    }
}

// al_e[e,h] = ea[e,:] @ V[:,h]; also segment-sum by dst for the self-loop mean
__global__ void k_edge_al(const float* __restrict__ ef, const int* __restrict__ dst) {
    int e = blockIdx.x * blockDim.x + threadIdx.x;
    if (e >= NE) return;
    float ea[EDIM];
#pragma unroll
    for (int d = 0; d < EDIM; d++) ea[d] = ef[(size_t)e * EDIM + d];
    int dn = dst[e];
#pragma unroll
    for (int h = 0; h < H_; h++) {
        float s = 0.f;
#pragma unroll
        for (int d = 0; d < EDIM; d++) s += ea[d] * g_V[d * H_ + h];
        g_al_e[e * H_ + h] = s;
        atomicAdd(&g_al_esum[dn * H_ + h], s);
    }
}

__global__ void k_alpha(const int* __restrict__ src, const int* __restrict__ dst) {
    int e = blockIdx.x * blockDim.x + threadIdx.x;
    if (e >= NE) return;
    int sn = src[e], dn = dst[e];
#pragma unroll
    for (int h = 0; h < H_; h++) {
        float v = g_al_src[sn * H_ + h] + g_al_dst[dn * H_ + h] + g_al_e[e * H_ + h];
        g_alpha[e * H_ + h] = v > 0.f ? v : 0.2f * v;
    }
}

__global__ void k_aself() {
    int n = blockIdx.x * blockDim.x + threadIdx.x;
    if (n >= NN) return;
    float invd = 1.0f / fmaxf((float)g_deg[n], 1.0f);
#pragma unroll
    for (int h = 0; h < H_; h++) {
        float v = g_al_src[n * H_ + h] + g_al_dst[n * H_ + h] + g_al_esum[n * H_ + h] * invd;
        g_aself[n * H_ + h] = v > 0.f ? v : 0.2f * v;
    }
}

// ---------------- segment softmax + aggregation (1 block / node) ------------
__global__ void __launch_bounds__(256)
k_aggregate(const float* __restrict__ xw, const int* __restrict__ src,
            const float* __restrict__ bias, float* __restrict__ out, int do_elu) {
    int n = blockIdx.x;
    int beg = g_rowptr[n], end = g_rowptr[n + 1];
    __shared__ float sm[H_], ss[H_];
    int t = threadIdx.x, w = t >> 5, l = t & 31;

    // phase 1: per-head max (incl. self loop)
    if (w < H_) {
        float mx = g_aself[n * H_ + w];
        for (int i = beg + l; i < end; i += 32)
            mx = fmaxf(mx, g_alpha[g_esorted[i] * H_ + w]);
#pragma unroll
        for (int off = 16; off; off >>= 1)
            mx = fmaxf(mx, __shfl_xor_sync(0xffffffffu, mx, off));
        if (l == 0) sm[w] = mx;
    }
    __syncthreads();

    // phase 2: exp + sum; overwrite g_alpha with exp values
    if (w < H_) {
        float mm = sm[w];
        float acc = (l == 0) ? expf(g_aself[n * H_ + w] - mm) : 0.f;
        for (int i = beg + l; i < end; i += 32) {
            int e = g_esorted[i];
            float ex = expf(g_alpha[e * H_ + w] - mm);
            g_alpha[e * H_ + w] = ex;
            acc += ex;
        }
#pragma unroll
        for (int off = 16; off; off >>= 1) acc += __shfl_xor_sync(0xffffffffu, acc, off);
        if (l == 0) ss[w] = acc;
    }
    __syncthreads();

    // phase 3: weighted gather. thread t owns channel t of each head.
    float inv[H_];
#pragma unroll
    for (int h = 0; h < H_; h++) inv[h] = 1.0f / (ss[h] + 1e-16f);
    float acc[H_] = {0.f, 0.f, 0.f, 0.f};
    for (int i = beg; i < end; i++) {
        int e = g_esorted[i];
        int sn = src[e];
        const float* row = xw + (size_t)sn * HC;
#pragma unroll
        for (int h = 0; h < H_; h++) {
            float wg = g_alpha[e * H_ + h] * inv[h];
            acc[h] += wg * row[h * C_ + t];
        }
    }
    // self loop
    const float* srow = xw + (size_t)n * HC;
#pragma unroll
    for (int h = 0; h < H_; h++) {
        float wg = expf(g_aself[n * H_ + h] - sm[h]) * inv[h];
        acc[h] += wg * srow[h * C_ + t];
    }
    // bias + ELU + store
#pragma unroll
    for (int h = 0; h < H_; h++) {
        float v = acc[h] + bias[h * C_ + t];
        if (do_elu) v = v > 0.f ? v : expm1f(v);
        out[(size_t)n * HC + h * C_ + t] = v;
    }
}

// ---------------- launch -----------------------------------------------------
extern "C" void kernel_launch(void* const* d_in, const int* in_sizes, int n_in,
                              void* d_out, int out_size) {
    const float* x      = (const float*)d_in[0];
    const int*   ei     = (const int*)d_in[1];
    const float* ef     = (const float*)d_in[2];
    const float* W1     = (const float*)d_in[3];
    const float* asrc1  = (const float*)d_in[4];
    const float* adst1  = (const float*)d_in[5];
    const float* aedge1 = (const float*)d_in[6];
    const float* We1    = (const float*)d_in[7];
    const float* b1     = (const float*)d_in[8];
    const float* W2     = (const float*)d_in[9];
    const float* asrc2  = (const float*)d_in[10];
    const float* adst2  = (const float*)d_in[11];
    const float* aedge2 = (const float*)d_in[12];
    const float* We2    = (const float*)d_in[13];
    const float* b2     = (const float*)d_in[14];
    const float* Wf     = (const float*)d_in[15];
    const float* bf     = (const float*)d_in[16];
    const int* src = ei;
    const int* dst = ei + NE;
    float* out = (float*)d_out;

    void* p;
    cudaGetSymbolAddress(&p, g_xw);  float* xw   = (float*)p;
    cudaGetSymbolAddress(&p, g_h);   float* hbuf = (float*)p;

    // graph structure (CSR by dst) — shared by both layers
    k_zero_deg<<<(NN + 255) / 256, 256>>>();
    k_count<<<(NE + 255) / 256, 256>>>(dst);
    k_scan<<<1, 1024>>>();
    k_fill<<<(NE + 255) / 256, 256>>>(dst);

    dim3 gL(HC / 128, (NN + 127) / 128);

    // ---- layer 1 ----
    k_sgemm<false><<<gL, 256>>>(x, W1, nullptr, xw, NN, HC, DIN);
    k_al<<<NN, 128>>>(xw, asrc1, adst1);
    k_V<<<1, 256>>>(We1, aedge1);
    k_zero_esum<<<(NN * H_ + 255) / 256, 256>>>();
    k_edge_al<<<(NE + 255) / 256, 256>>>(ef, dst);
    k_alpha<<<(NE + 255) / 256, 256>>>(src, dst);
    k_aself<<<(NN + 255) / 256, 256>>>();
    k_aggregate<<<NN, 256>>>(xw, src, b1, hbuf, 1);

    // ---- layer 2 ----
    k_sgemm<false><<<gL, 256>>>(hbuf, W2, nullptr, xw, NN, HC, HC);
    k_al<<<NN, 128>>>(xw, asrc2, adst2);
    k_V<<<1, 256>>>(We2, aedge2);
    k_zero_esum<<<(NN * H_ + 255) / 256, 256>>>();
    k_edge_al<<<(NE + 255) / 256, 256>>>(ef, dst);
    k_alpha<<<(NE + 255) / 256, 256>>>(src, dst);
    k_aself<<<(NN + 255) / 256, 256>>>();
    k_aggregate<<<NN, 256>>>(xw, src, b2, hbuf, 1);

    // ---- final linear: out = h2 @ Wf + bf ----
    dim3 gF(DOUT / 128, (NN + 127) / 128);
    k_sgemm<true><<<gF, 256>>>(hbuf, Wf, bf, out, NN, DOUT, HC);
}

// round 2
// speedup vs baseline: 1.0003x; 1.0003x over previous
#include <cuda_runtime.h>
#include <math.h>

// Problem constants (fixed shapes per metadata)
constexpr int NN   = 10000;   // nodes
constexpr int NE   = 160000;  // edges
constexpr int DIN  = 128;     // input feature dim
constexpr int EDIM = 16;      // edge feature dim
constexpr int H_   = 4;       // heads
constexpr int C_   = 256;     // channels per head
constexpr int HC   = 1024;    // H*C
constexpr int DOUT = 25088;   // final output dim

// ---------------- scratch (static device globals: allocation-free) ----------
__device__ float g_xw[NN * HC];        // x @ W  (per layer)
__device__ float g_h[NN * HC];         // layer output
__device__ float g_al_src[NN * H_];
__device__ float g_al_dst[NN * H_];
__device__ float g_al_e[NE * H_];
__device__ float g_al_esum[NN * H_];   // segment_sum of al_e by dst (for self-loop mean attr)
__device__ float g_alpha[NE * H_];     // leaky logits, later overwritten with exp()
__device__ float g_aself[NN * H_];     // self-loop leaky logits
__device__ float g_V[EDIM * H_];       // We folded with a_edge:  al_e = ea @ V
__device__ int   g_deg[NN];
__device__ int   g_rowptr[NN + 1];
__device__ int   g_cursor[NN];
__device__ int   g_esorted[NE];        // edge ids sorted by dst (CSR)

// ---------------- graph structure kernels ----------------------------------
__global__ void k_zero_deg() {
    int i = blockIdx.x * blockDim.x + threadIdx.x;
    if (i < NN) g_deg[i] = 0;
}

__global__ void k_zero_esum() {
    int i = blockIdx.x * blockDim.x + threadIdx.x;
    if (i < NN * H_) g_al_esum[i] = 0.f;
}

__global__ void k_count(const int* __restrict__ dst) {
    int e = blockIdx.x * blockDim.x + threadIdx.x;
    if (e < NE) atomicAdd(&g_deg[dst[e]], 1);
}

// single-block scan over NN degrees -> rowptr + cursor
__global__ void k_scan() {
    __shared__ int sh[1024];
    __shared__ int carry;
    int t = threadIdx.x;
    if (t == 0) carry = 0;
    __syncthreads();
    for (int base = 0; base < NN; base += 1024) {
        int i = base + t;
        int v = (i < NN) ? g_deg[i] : 0;
        sh[t] = v;
        __syncthreads();
        for (int off = 1; off < 1024; off <<= 1) {
            int xv = (t >= off) ? sh[t - off] : 0;
            __syncthreads();
            if (t >= off) sh[t] += xv;
            __syncthreads();
        }
        int excl = sh[t] - v + carry;
        if (i < NN) { g_rowptr[i] = excl; g_cursor[i] = excl; }
        int tot = sh[1023];
        __syncthreads();
        if (t == 0) carry += tot;
        __syncthreads();
    }
    if (t == 0) g_rowptr[NN] = carry;
}

__global__ void k_fill(const int* __restrict__ dst) {
    int e = blockIdx.x * blockDim.x + threadIdx.x;
    if (e < NE) {
        int p = atomicAdd(&g_cursor[dst[e]], 1);
        g_esorted[p] = e;
    }
}

// ---------------- SGEMM: C[M,N] = A[M,K] @ B[K,N] (+bias) ------------------
// 128x128 tile, 256 threads, 8x8 per thread, BK=8. K % 8 == 0, N % 128 == 0.
template <bool BIAS>
__global__ void __launch_bounds__(256)
k_sgemm(const float* __restrict__ A, const float* __restrict__ B,
        const float* __restrict__ bias, float* __restrict__ Cm,
        int M, int Nn, int K) {
    __shared__ float As[8][128];
    __shared__ float Bs[8][128];
    const int bm = blockIdx.y * 128, bn = blockIdx.x * 128;
    const int tid  = threadIdx.x;
    const int tx   = tid & 15, ty = tid >> 4;
    const int arow = tid >> 1, acol = (tid & 1) * 4;
    const int brow = tid >> 5, bcol = (tid & 31) * 4;

    float acc[8][8];
#pragma unroll
    for (int i = 0; i < 8; i++)
#pragma unroll
        for (int j = 0; j < 8; j++) acc[i][j] = 0.f;

    for (int k0 = 0; k0 < K; k0 += 8) {
        float4 av = make_float4(0.f, 0.f, 0.f, 0.f);
        if (bm + arow < M)
            av = *reinterpret_cast<const float4*>(A + (size_t)(bm + arow) * K + k0 + acol);
        As[acol + 0][arow] = av.x;
        As[acol + 1][arow] = av.y;
        As[acol + 2][arow] = av.z;
        As[acol + 3][arow] = av.w;
        float4 bv = *reinterpret_cast<const float4*>(B + (size_t)(k0 + brow) * Nn + bn + bcol);
        *reinterpret_cast<float4*>(&Bs[brow][bcol]) = bv;
        __syncthreads();
#pragma unroll
        for (int k = 0; k < 8; k++) {
            float a[8], b[8];
            float4 t0 = *reinterpret_cast<const float4*>(&As[k][ty * 8]);
            float4 t1 = *reinterpret_cast<const float4*>(&As[k][ty * 8 + 4]);
            float4 t2 = *reinterpret_cast<const float4*>(&Bs[k][tx * 8]);
            float4 t3 = *reinterpret_cast<const float4*>(&Bs[k][tx * 8 + 4]);
            a[0]=t0.x; a[1]=t0.y; a[2]=t0.z; a[3]=t0.w; a[4]=t1.x; a[5]=t1.y; a[6]=t1.z; a[7]=t1.w;
            b[0]=t2.x; b[1]=t2.y; b[2]=t2.z; b[3]=t2.w; b[4]=t3.x; b[5]=t3.y; b[6]=t3.z; b[7]=t3.w;
#pragma unroll
            for (int i = 0; i < 8; i++)
#pragma unroll
                for (int j = 0; j < 8; j++) acc[i][j] = fmaf(a[i], b[j], acc[i][j]);
        }
        __syncthreads();
    }

#pragma unroll
    for (int i = 0; i < 8; i++) {
        int m = bm + ty * 8 + i;
        if (m >= M) continue;
#pragma unroll
        for (int j = 0; j < 8; j += 4) {
            int n = bn + tx * 8 + j;
            float4 v;
            v.x = acc[i][j]; v.y = acc[i][j + 1]; v.z = acc[i][j + 2]; v.w = acc[i][j + 3];
            if (BIAS) { v.x += bias[n]; v.y += bias[n + 1]; v.z += bias[n + 2]; v.w += bias[n + 3]; }
            *reinterpret_cast<float4*>(Cm + (size_t)m * Nn + n) = v;
        }
    }
}

// ---------------- attention logit pieces ------------------------------------
// al_src[n,h] = <xw[n,h,:], a_src[h,:]> ; same for dst.  1 block/node, warp/head.
__global__ void k_al(const float* __restrict__ xw,
                     const float* __restrict__ asrc, const float* __restrict__ adst) {
    int n = blockIdx.x;
    int w = threadIdx.x >> 5, l = threadIdx.x & 31;
    const float* row = xw + (size_t)n * HC + w * C_;
    const float* as  = asrc + w * C_;
    const float* ad  = adst + w * C_;
    float s = 0.f, d = 0.f;
    for (int c = l; c < C_; c += 32) {
        float v = row[c];
        s += v * as[c];
        d += v * ad[c];
    }
#pragma unroll
    for (int off = 16; off; off >>= 1) {
        s += __shfl_xor_sync(0xffffffffu, s, off);
        d += __shfl_xor_sync(0xffffffffu, d, off);
    }
    if (l == 0) { g_al_src[n * H_ + w] = s; g_al_dst[n * H_ + w] = d; }
}

// V[d,h] = sum_c We[d, h*C+c] * a_edge[h,c]   (folds edge GEMM to [16,4])
__global__ void k_V(const float* __restrict__ We, const float* __restrict__ aedge) {
    int w = threadIdx.x >> 5, l = threadIdx.x & 31;
    for (int o = w; o < EDIM * H_; o += 8) {
        int d = o / H_, h = o % H_;
        float s = 0.f;
        for (int c = l; c < C_; c += 32)
            s += We[(size_t)d * HC + h * C_ + c] * aedge[h * C_ + c];
#pragma unroll
        for (int off = 16; off; off >>= 1) s += __shfl_xor_sync(0xffffffffu, s, off);
        if (l == 0) g_V[o] = s;
    }
}

// al_e[e,h] = ea[e,:] @ V[:,h]; also segment-sum by dst for the self-loop mean
__global__ void k_edge_al(const float* __restrict__ ef, const int* __restrict__ dst) {
    int e = blockIdx.x * blockDim.x + threadIdx.x;
    if (e >= NE) return;
    float ea[EDIM];
#pragma unroll
    for (int d = 0; d < EDIM; d++) ea[d] = ef[(size_t)e * EDIM + d];
    int dn = dst[e];
#pragma unroll
    for (int h = 0; h < H_; h++) {
        float s = 0.f;
#pragma unroll
        for (int d = 0; d < EDIM; d++) s += ea[d] * g_V[d * H_ + h];
        g_al_e[e * H_ + h] = s;
        atomicAdd(&g_al_esum[dn * H_ + h], s);
    }
}

__global__ void k_alpha(const int* __restrict__ src, const int* __restrict__ dst) {
    int e = blockIdx.x * blockDim.x + threadIdx.x;
    if (e >= NE) return;
    int sn = src[e], dn = dst[e];
#pragma unroll
    for (int h = 0; h < H_; h++) {
        float v = g_al_src[sn * H_ + h] + g_al_dst[dn * H_ + h] + g_al_e[e * H_ + h];
        g_alpha[e * H_ + h] = v > 0.f ? v : 0.2f * v;
    }
}

__global__ void k_aself() {
    int n = blockIdx.x * blockDim.x + threadIdx.x;
    if (n >= NN) return;
    float invd = 1.0f / fmaxf((float)g_deg[n], 1.0f);
#pragma unroll
    for (int h = 0; h < H_; h++) {
        float v = g_al_src[n * H_ + h] + g_al_dst[n * H_ + h] + g_al_esum[n * H_ + h] * invd;
        g_aself[n * H_ + h] = v > 0.f ? v : 0.2f * v;
    }
}

// ---------------- segment softmax + aggregation (1 block / node) ------------
__global__ void __launch_bounds__(256)
k_aggregate(const float* __restrict__ xw, const int* __restrict__ src,
            const float* __restrict__ bias, float* __restrict__ out, int do_elu) {
    int n = blockIdx.x;
    int beg = g_rowptr[n], end = g_rowptr[n + 1];
    __shared__ float sm[H_], ss[H_];
    int t = threadIdx.x, w = t >> 5, l = t & 31;

    // phase 1: per-head max (incl. self loop)
    if (w < H_) {
        float mx = g_aself[n * H_ + w];
        for (int i = beg + l; i < end; i += 32)
            mx = fmaxf(mx, g_alpha[g_esorted[i] * H_ + w]);
#pragma unroll
        for (int off = 16; off; off >>= 1)
            mx = fmaxf(mx, __shfl_xor_sync(0xffffffffu, mx, off));
        if (l == 0) sm[w] = mx;
    }
    __syncthreads();

    // phase 2: exp + sum; overwrite g_alpha with exp values
    if (w < H_) {
        float mm = sm[w];
        float acc = (l == 0) ? expf(g_aself[n * H_ + w] - mm) : 0.f;
        for (int i = beg + l; i < end; i += 32) {
            int e = g_esorted[i];
            float ex = expf(g_alpha[e * H_ + w] - mm);
            g_alpha[e * H_ + w] = ex;
            acc += ex;
        }
#pragma unroll
        for (int off = 16; off; off >>= 1) acc += __shfl_xor_sync(0xffffffffu, acc, off);
        if (l == 0) ss[w] = acc;
    }
    __syncthreads();

    // phase 3: weighted gather. thread t owns channel t of each head.
    float inv[H_];
#pragma unroll
    for (int h = 0; h < H_; h++) inv[h] = 1.0f / (ss[h] + 1e-16f);
    float acc[H_] = {0.f, 0.f, 0.f, 0.f};
    for (int i = beg; i < end; i++) {
        int e = g_esorted[i];
        int sn = src[e];
        const float* row = xw + (size_t)sn * HC;
#pragma unroll
        for (int h = 0; h < H_; h++) {
            float wg = g_alpha[e * H_ + h] * inv[h];
            acc[h] += wg * row[h * C_ + t];
        }
    }
    // self loop
    const float* srow = xw + (size_t)n * HC;
#pragma unroll
    for (int h = 0; h < H_; h++) {
        float wg = expf(g_aself[n * H_ + h] - sm[h]) * inv[h];
        acc[h] += wg * srow[h * C_ + t];
    }
    // bias + ELU + store
#pragma unroll
    for (int h = 0; h < H_; h++) {
        float v = acc[h] + bias[h * C_ + t];
        if (do_elu) v = v > 0.f ? v : expm1f(v);
        out[(size_t)n * HC + h * C_ + t] = v;
    }
}

// ---------------- launch -----------------------------------------------------
extern "C" void kernel_launch(void* const* d_in, const int* in_sizes, int n_in,
                              void* d_out, int out_size) {
    const float* x      = (const float*)d_in[0];
    const int*   ei     = (const int*)d_in[1];
    const float* ef     = (const float*)d_in[2];
    const float* W1     = (const float*)d_in[3];
    const float* asrc1  = (const float*)d_in[4];
    const float* adst1  = (const float*)d_in[5];
    const float* aedge1 = (const float*)d_in[6];
    const float* We1    = (const float*)d_in[7];
    const float* b1     = (const float*)d_in[8];
    const float* W2     = (const float*)d_in[9];
    const float* asrc2  = (const float*)d_in[10];
    const float* adst2  = (const float*)d_in[11];
    const float* aedge2 = (const float*)d_in[12];
    const float* We2    = (const float*)d_in[13];
    const float* b2     = (const float*)d_in[14];
    const float* Wf     = (const float*)d_in[15];
    const float* bf     = (const float*)d_in[16];
    const int* src = ei;
    const int* dst = ei + NE;
    float* out = (float*)d_out;

    void* p;
    cudaGetSymbolAddress(&p, g_xw);  float* xw   = (float*)p;
    cudaGetSymbolAddress(&p, g_h);   float* hbuf = (float*)p;

    // graph structure (CSR by dst) — shared by both layers
    k_zero_deg<<<(NN + 255) / 256, 256>>>();
    k_count<<<(NE + 255) / 256, 256>>>(dst);
    k_scan<<<1, 1024>>>();
    k_fill<<<(NE + 255) / 256, 256>>>(dst);

    dim3 gL(HC / 128, (NN + 127) / 128);

    // ---- layer 1 ----
    k_sgemm<false><<<gL, 256>>>(x, W1, nullptr, xw, NN, HC, DIN);
    k_al<<<NN, 128>>>(xw, asrc1, adst1);
    k_V<<<1, 256>>>(We1, aedge1);
    k_zero_esum<<<(NN * H_ + 255) / 256, 256>>>();
    k_edge_al<<<(NE + 255) / 256, 256>>>(ef, dst);
    k_alpha<<<(NE + 255) / 256, 256>>>(src, dst);
    k_aself<<<(NN + 255) / 256, 256>>>();
    k_aggregate<<<NN, 256>>>(xw, src, b1, hbuf, 1);

    // ---- layer 2 ----
    k_sgemm<false><<<gL, 256>>>(hbuf, W2, nullptr, xw, NN, HC, HC);
    k_al<<<NN, 128>>>(xw, asrc2, adst2);
    k_V<<<1, 256>>>(We2, aedge2);
    k_zero_esum<<<(NN * H_ + 255) / 256, 256>>>();
    k_edge_al<<<(NE + 255) / 256, 256>>>(ef, dst);
    k_alpha<<<(NE + 255) / 256, 256>>>(src, dst);
    k_aself<<<(NN + 255) / 256, 256>>>();
    k_aggregate<<<NN, 256>>>(xw, src, b2, hbuf, 1);

    // ---- final linear: out = h2 @ Wf + bf ----
    dim3 gF(DOUT / 128, (NN + 127) / 128);
    k_sgemm<true><<<gF, 256>>>(hbuf, Wf, bf, out, NN, DOUT, HC);
}

// round 4
// speedup vs baseline: 2.4449x; 2.4441x over previous
#include <cuda_runtime.h>
#include <cuda_bf16.h>
#include <math.h>
#include <stdint.h>

// Problem constants (fixed shapes per metadata)
constexpr int NN   = 10000;   // nodes
constexpr int NE   = 160000;  // edges
constexpr int DIN  = 128;     // input feature dim
constexpr int EDIM = 16;      // edge feature dim
constexpr int H_   = 4;       // heads
constexpr int C_   = 256;     // channels per head
constexpr int HC   = 1024;    // H*C
constexpr int DOUT = 25088;   // final output dim

// tensor-core final-GEMM constants
constexpr int MPAD  = 10112;      // 79 * 128 (M padded)
constexpr int KS    = 3 * HC;     // 3072 split-K (hi | lo | hi)
constexpr int KITER = KS / 32;    // 96 K-iterations of BK=32

// ---------------- scratch (static device globals: allocation-free) ----------
__device__ float g_xw[NN * HC];
__device__ float g_h[NN * HC];
__device__ float g_al_src[NN * H_];
__device__ float g_al_dst[NN * H_];
__device__ float g_al_e[NE * H_];
__device__ float g_al_esum[NN * H_];
__device__ float g_alpha[NE * H_];
__device__ float g_aself[NN * H_];
__device__ float g_V[EDIM * H_];
__device__ int   g_deg[NN];
__device__ int   g_rowptr[NN + 1];
__device__ int   g_cursor[NN];
__device__ int   g_esorted[NE];
__device__ __nv_bfloat16 g_Aext[(size_t)MPAD * KS];   // [10112, 3072] bf16
__device__ __nv_bfloat16 g_Bt[(size_t)DOUT * KS];     // [25088, 3072] bf16 (Wf^T split)

// ---------------- graph structure kernels ----------------------------------
__global__ void k_zero_deg() {
    int i = blockIdx.x * blockDim.x + threadIdx.x;
    if (i < NN) g_deg[i] = 0;
}

__global__ void k_zero_esum() {
    int i = blockIdx.x * blockDim.x + threadIdx.x;
    if (i < NN * H_) g_al_esum[i] = 0.f;
}

__global__ void k_count(const int* __restrict__ dst) {
    int e = blockIdx.x * blockDim.x + threadIdx.x;
    if (e < NE) atomicAdd(&g_deg[dst[e]], 1);
}

__global__ void k_scan() {
    __shared__ int sh[1024];
    __shared__ int carry;
    int t = threadIdx.x;
    if (t == 0) carry = 0;
    __syncthreads();
    for (int base = 0; base < NN; base += 1024) {
        int i = base + t;
        int v = (i < NN) ? g_deg[i] : 0;
        sh[t] = v;
        __syncthreads();
        for (int off = 1; off < 1024; off <<= 1) {
            int xv = (t >= off) ? sh[t - off] : 0;
            __syncthreads();
            if (t >= off) sh[t] += xv;
            __syncthreads();
        }
        int excl = sh[t] - v + carry;
        if (i < NN) { g_rowptr[i] = excl; g_cursor[i] = excl; }
        int tot = sh[1023];
        __syncthreads();
        if (t == 0) carry += tot;
        __syncthreads();
    }
    if (t == 0) g_rowptr[NN] = carry;
}

__global__ void k_fill(const int* __restrict__ dst) {
    int e = blockIdx.x * blockDim.x + threadIdx.x;
    if (e < NE) {
        int p = atomicAdd(&g_cursor[dst[e]], 1);
        g_esorted[p] = e;
    }
}

// ---------------- fp32 SGEMM (layer GEMMs) ----------------------------------
template <bool BIAS>
__global__ void __launch_bounds__(256)
k_sgemm(const float* __restrict__ A, const float* __restrict__ B,
        const float* __restrict__ bias, float* __restrict__ Cm,
        int M, int Nn, int K) {
    __shared__ float As[8][128];
    __shared__ float Bs[8][128];
    const int bm = blockIdx.y * 128, bn = blockIdx.x * 128;
    const int tid  = threadIdx.x;
    const int tx   = tid & 15, ty = tid >> 4;
    const int arow = tid >> 1, acol = (tid & 1) * 4;
    const int brow = tid >> 5, bcol = (tid & 31) * 4;

    float acc[8][8];
#pragma unroll
    for (int i = 0; i < 8; i++)
#pragma unroll
        for (int j = 0; j < 8; j++) acc[i][j] = 0.f;

    for (int k0 = 0; k0 < K; k0 += 8) {
        float4 av = make_float4(0.f, 0.f, 0.f, 0.f);
        if (bm + arow < M)
            av = *reinterpret_cast<const float4*>(A + (size_t)(bm + arow) * K + k0 + acol);
        As[acol + 0][arow] = av.x;
        As[acol + 1][arow] = av.y;
        As[acol + 2][arow] = av.z;
        As[acol + 3][arow] = av.w;
        float4 bv = *reinterpret_cast<const float4*>(B + (size_t)(k0 + brow) * Nn + bn + bcol);
        *reinterpret_cast<float4*>(&Bs[brow][bcol]) = bv;
        __syncthreads();
#pragma unroll
        for (int k = 0; k < 8; k++) {
            float a[8], b[8];
            float4 t0 = *reinterpret_cast<const float4*>(&As[k][ty * 8]);
            float4 t1 = *reinterpret_cast<const float4*>(&As[k][ty * 8 + 4]);
            float4 t2 = *reinterpret_cast<const float4*>(&Bs[k][tx * 8]);
            float4 t3 = *reinterpret_cast<const float4*>(&Bs[k][tx * 8 + 4]);
            a[0]=t0.x; a[1]=t0.y; a[2]=t0.z; a[3]=t0.w; a[4]=t1.x; a[5]=t1.y; a[6]=t1.z; a[7]=t1.w;
            b[0]=t2.x; b[1]=t2.y; b[2]=t2.z; b[3]=t2.w; b[4]=t3.x; b[5]=t3.y; b[6]=t3.z; b[7]=t3.w;
#pragma unroll
            for (int i = 0; i < 8; i++)
#pragma unroll
                for (int j = 0; j < 8; j++) acc[i][j] = fmaf(a[i], b[j], acc[i][j]);
        }
        __syncthreads();
    }

#pragma unroll
    for (int i = 0; i < 8; i++) {
        int m = bm + ty * 8 + i;
        if (m >= M) continue;
#pragma unroll
        for (int j = 0; j < 8; j += 4) {
            int n = bn + tx * 8 + j;
            float4 v;
            v.x = acc[i][j]; v.y = acc[i][j + 1]; v.z = acc[i][j + 2]; v.w = acc[i][j + 3];
            if (BIAS) { v.x += bias[n]; v.y += bias[n + 1]; v.z += bias[n + 2]; v.w += bias[n + 3]; }
            *reinterpret_cast<float4*>(Cm + (size_t)m * Nn + n) = v;
        }
    }
}

// ---------------- attention logit pieces ------------------------------------
__global__ void k_al(const float* __restrict__ xw,
                     const float* __restrict__ asrc, const float* __restrict__ adst) {
    int n = blockIdx.x;
    int w = threadIdx.x >> 5, l = threadIdx.x & 31;
    const float* row = xw + (size_t)n * HC + w * C_;
    const float* as  = asrc + w * C_;
    const float* ad  = adst + w * C_;
    float s = 0.f, d = 0.f;
    for (int c = l; c < C_; c += 32) {
        float v = row[c];
        s += v * as[c];
        d += v * ad[c];
    }
#pragma unroll
    for (int off = 16; off; off >>= 1) {
        s += __shfl_xor_sync(0xffffffffu, s, off);
        d += __shfl_xor_sync(0xffffffffu, d, off);
    }
    if (l == 0) { g_al_src[n * H_ + w] = s; g_al_dst[n * H_ + w] = d; }
}

__global__ void k_V(const float* __restrict__ We, const float* __restrict__ aedge) {
    int w = threadIdx.x >> 5, l = threadIdx.x & 31;
    for (int o = w; o < EDIM * H_; o += 8) {
        int d = o / H_, h = o % H_;
        float s = 0.f;
        for (int c = l; c < C_; c += 32)
            s += We[(size_t)d * HC + h * C_ + c] * aedge[h * C_ + c];
#pragma unroll
        for (int off = 16; off; off >>= 1) s += __shfl_xor_sync(0xffffffffu, s, off);
        if (l == 0) g_V[o] = s;
    }
}

__global__ void k_edge_al(const float* __restrict__ ef, const int* __restrict__ dst) {
    int e = blockIdx.x * blockDim.x + threadIdx.x;
    if (e >= NE) return;
    float ea[EDIM];
#pragma unroll
    for (int d = 0; d < EDIM; d++) ea[d] = ef[(size_t)e * EDIM + d];
    int dn = dst[e];
#pragma unroll
    for (int h = 0; h < H_; h++) {
        float s = 0.f;
#pragma unroll
        for (int d = 0; d < EDIM; d++) s += ea[d] * g_V[d * H_ + h];
        g_al_e[e * H_ + h] = s;
        atomicAdd(&g_al_esum[dn * H_ + h], s);
    }
}

__global__ void k_alpha(const int* __restrict__ src, const int* __restrict__ dst) {
    int e = blockIdx.x * blockDim.x + threadIdx.x;
    if (e >= NE) return;
    int sn = src[e], dn = dst[e];
#pragma unroll
    for (int h = 0; h < H_; h++) {
        float v = g_al_src[sn * H_ + h] + g_al_dst[dn * H_ + h] + g_al_e[e * H_ + h];
        g_alpha[e * H_ + h] = v > 0.f ? v : 0.2f * v;
    }
}

__global__ void k_aself() {
    int n = blockIdx.x * blockDim.x + threadIdx.x;
    if (n >= NN) return;
    float invd = 1.0f / fmaxf((float)g_deg[n], 1.0f);
#pragma unroll
    for (int h = 0; h < H_; h++) {
        float v = g_al_src[n * H_ + h] + g_al_dst[n * H_ + h] + g_al_esum[n * H_ + h] * invd;
        g_aself[n * H_ + h] = v > 0.f ? v : 0.2f * v;
    }
}

// ---------------- segment softmax + aggregation (1 block / node) ------------
__global__ void __launch_bounds__(256)
k_aggregate(const float* __restrict__ xw, const int* __restrict__ src,
            const float* __restrict__ bias, float* __restrict__ out, int do_elu) {
    int n = blockIdx.x;
    int beg = g_rowptr[n], end = g_rowptr[n + 1];
    __shared__ float sm[H_], ss[H_];
    int t = threadIdx.x, w = t >> 5, l = t & 31;

    if (w < H_) {
        float mx = g_aself[n * H_ + w];
        for (int i = beg + l; i < end; i += 32)
            mx = fmaxf(mx, g_alpha[g_esorted[i] * H_ + w]);
#pragma unroll
        for (int off = 16; off; off >>= 1)
            mx = fmaxf(mx, __shfl_xor_sync(0xffffffffu, mx, off));
        if (l == 0) sm[w] = mx;
    }
    __syncthreads();

    if (w < H_) {
        float mm = sm[w];
        float acc = (l == 0) ? expf(g_aself[n * H_ + w] - mm) : 0.f;
        for (int i = beg + l; i < end; i += 32) {
            int e = g_esorted[i];
            float ex = expf(g_alpha[e * H_ + w] - mm);
            g_alpha[e * H_ + w] = ex;
            acc += ex;
        }
#pragma unroll
        for (int off = 16; off; off >>= 1) acc += __shfl_xor_sync(0xffffffffu, acc, off);
        if (l == 0) ss[w] = acc;
    }
    __syncthreads();

    float inv[H_];
#pragma unroll
    for (int h = 0; h < H_; h++) inv[h] = 1.0f / (ss[h] + 1e-16f);
    float acc[H_] = {0.f, 0.f, 0.f, 0.f};
    for (int i = beg; i < end; i++) {
        int e = g_esorted[i];
        int sn = src[e];
        const float* row = xw + (size_t)sn * HC;
#pragma unroll
        for (int h = 0; h < H_; h++) {
            float wg = g_alpha[e * H_ + h] * inv[h];
            acc[h] += wg * row[h * C_ + t];
        }
    }
    const float* srow = xw + (size_t)n * HC;
#pragma unroll
    for (int h = 0; h < H_; h++) {
        float wg = expf(g_aself[n * H_ + h] - sm[h]) * inv[h];
        acc[h] += wg * srow[h * C_ + t];
    }
#pragma unroll
    for (int h = 0; h < H_; h++) {
        float v = acc[h] + bias[h * C_ + t];
        if (do_elu) v = v > 0.f ? v : expm1f(v);
        out[(size_t)n * HC + h * C_ + t] = v;
    }
}

// ---------------- split-bf16 conversions ------------------------------------
// A' = [hi | lo | hi] along K.  Rows >= NN zero-padded.
__global__ void k_convA(const float* __restrict__ src) {
    int i = blockIdx.x * blockDim.x + threadIdx.x;
    if (i >= MPAD * HC) return;
    int m = i >> 10, k = i & 1023;
    float a = (m < NN) ? src[(size_t)m * HC + k] : 0.f;
    __nv_bfloat16 hi = __float2bfloat16(a);
    __nv_bfloat16 lo = __float2bfloat16(a - __bfloat162float(hi));
    size_t base = (size_t)m * KS + k;
    g_Aext[base]        = hi;
    g_Aext[base + 1024] = lo;
    g_Aext[base + 2048] = hi;
}

// B' = transpose(Wf) with K-segments [hi | hi | lo].
__global__ void k_convB(const float* __restrict__ Wf) {
    __shared__ float t[32][33];
    int n = blockIdx.x * 32 + threadIdx.x;
    int k = blockIdx.y * 32 + threadIdx.y;
    t[threadIdx.y][threadIdx.x] = Wf[(size_t)k * DOUT + n];
    __syncthreads();
    int n2 = blockIdx.x * 32 + threadIdx.y;
    int k2 = blockIdx.y * 32 + threadIdx.x;
    float a = t[threadIdx.x][threadIdx.y];
    __nv_bfloat16 hi = __float2bfloat16(a);
    __nv_bfloat16 lo = __float2bfloat16(a - __bfloat162float(hi));
    size_t base = (size_t)n2 * KS + k2;
    g_Bt[base]        = hi;
    g_Bt[base + 1024] = hi;
    g_Bt[base + 2048] = lo;
}

// ---------------- HMMA bf16 GEMM (final linear) ------------------------------
// out[M, DOUT] = A'[M, 3072] @ B'[DOUT, 3072]^T + bias   (fp32 accum)
// 128x128 CTA tile, BK=32, 8 warps (warp tile 64x32), 4-stage cp.async pipeline.

__device__ __forceinline__ uint32_t s2u(const void* p) {
    uint32_t a;
    asm("{ .reg .u64 t; cvta.to.shared.u64 t, %1; cvt.u32.u64 %0, t; }" : "=r"(a) : "l"(p));
    return a;
}

__device__ __forceinline__ void cp16(uint32_t saddr, const void* gptr) {
    asm volatile("cp.async.cg.shared.global [%0], [%1], 16;" :: "r"(saddr), "l"(gptr));
}

#define LDSM4(r, addr) \
    asm volatile("ldmatrix.sync.aligned.m8n8.x4.shared.b16 {%0,%1,%2,%3}, [%4];" \
        : "=r"((r)[0]), "=r"((r)[1]), "=r"((r)[2]), "=r"((r)[3]) : "r"(addr))

#define MMA16816(c, a, b0, b1) \
    asm volatile("mma.sync.aligned.m16n8k16.row.col.f32.bf16.bf16.f32 " \
        "{%0,%1,%2,%3}, {%4,%5,%6,%7}, {%8,%9}, {%0,%1,%2,%3};" \
        : "+f"((c)[0]), "+f"((c)[1]), "+f"((c)[2]), "+f"((c)[3]) \
        : "r"((a)[0]), "r"((a)[1]), "r"((a)[2]), "r"((a)[3]), "r"(b0), "r"(b1))

constexpr int STAGE_BYTES = 16384;   // A 8KB + B 8KB per stage
constexpr int MMA_SMEM    = 4 * STAGE_BYTES;  // 64 KB

__global__ void __launch_bounds__(256, 2)
k_mma_gemm(const __nv_bfloat16* __restrict__ A, const __nv_bfloat16* __restrict__ B,
           const float* __restrict__ bias, float* __restrict__ out) {
    extern __shared__ char smem[];
    const uint32_t sb = s2u(smem);
    const int tid  = threadIdx.x;
    const int lane = tid & 31, wid = tid >> 5;
    const int wm = (wid & 1) * 64, wn = (wid >> 1) * 32;
    const int bm = blockIdx.x * 128, bn = blockIdx.y * 128;

    const __nv_bfloat16* ag0 = A + (size_t)bm * KS;
    const __nv_bfloat16* bg0 = B + (size_t)bn * KS;

    // swizzle: 16B segment s of row r lives at phys seg (s ^ ((r>>1)&3))
    auto load_stage = [&](int kt, int slot) {
        const int k0 = kt * 32;
        const uint32_t sa = sb + slot * STAGE_BYTES;
        const uint32_t sbm = sa + 8192;
#pragma unroll
        for (int i = 0; i < 2; i++) {
            int u = tid + i * 256;
            int row = u >> 2, seg = u & 3;
            uint32_t off = row * 64 + ((seg ^ ((row >> 1) & 3)) << 4);
            cp16(sa  + off, ag0 + (size_t)row * KS + k0 + seg * 8);
            cp16(sbm + off, bg0 + (size_t)row * KS + k0 + seg * 8);
        }
    };

    float acc[4][4][4];
#pragma unroll
    for (int i = 0; i < 4; i++)
#pragma unroll
        for (int j = 0; j < 4; j++)
#pragma unroll
            for (int r = 0; r < 4; r++) acc[i][j][r] = 0.f;

    load_stage(0, 0);
    asm volatile("cp.async.commit_group;" ::: "memory");
    load_stage(1, 1);
    asm volatile("cp.async.commit_group;" ::: "memory");
    load_stage(2, 2);
    asm volatile("cp.async.commit_group;" ::: "memory");

    for (int kt = 0; kt < KITER; kt++) {
        asm volatile("cp.async.wait_group 2;" ::: "memory");
        __syncthreads();
        if (kt + 3 < KITER) load_stage(kt + 3, (kt + 3) & 3);
        asm volatile("cp.async.commit_group;" ::: "memory");

        const uint32_t sa  = sb + (kt & 3) * STAGE_BYTES;
        const uint32_t sbm = sa + 8192;
#pragma unroll
        for (int ks2 = 0; ks2 < 2; ks2++) {
            uint32_t av[4][4], bv[2][4];
            const int segk = ks2 * 2 + (lane >> 4);
#pragma unroll
            for (int mf = 0; mf < 4; mf++) {
                int row = wm + mf * 16 + (lane & 15);
                LDSM4(av[mf], sa + row * 64 + ((segk ^ ((row >> 1) & 3)) << 4));
            }
#pragma unroll
            for (int p = 0; p < 2; p++) {
                int row = wn + p * 16 + (lane & 15);
                LDSM4(bv[p], sbm + row * 64 + ((segk ^ ((row >> 1) & 3)) << 4));
            }
#pragma unroll
            for (int mf = 0; mf < 4; mf++)
#pragma unroll
                for (int nf = 0; nf < 4; nf++)
                    MMA16816(acc[mf][nf], av[mf], bv[nf >> 1][nf & 1], bv[nf >> 1][(nf & 1) + 2]);
        }
    }

    // epilogue: accum frag (r0 = lane>>2 rows, +8; cols (lane&3)*2, +1)
    const int r0 = lane >> 2, c0 = (lane & 3) * 2;
#pragma unroll
    for (int mf = 0; mf < 4; mf++) {
#pragma unroll
        for (int half = 0; half < 2; half++) {
            int m = bm + wm + mf * 16 + r0 + half * 8;
            if (m >= NN) continue;
            float* orow = out + (size_t)m * DOUT;
#pragma unroll
            for (int nf = 0; nf < 4; nf++) {
                int n = bn + wn + nf * 8 + c0;
                float2 v;
                v.x = acc[mf][nf][half * 2 + 0] + __ldg(bias + n);
                v.y = acc[mf][nf][half * 2 + 1] + __ldg(bias + n + 1);
                *reinterpret_cast<float2*>(orow + n) = v;
            }
        }
    }
}

// ---------------- launch -----------------------------------------------------
extern "C" void kernel_launch(void* const* d_in, const int* in_sizes, int n_in,
                              void* d_out, int out_size) {
    const float* x      = (const float*)d_in[0];
    const int*   ei     = (const int*)d_in[1];
    const float* ef     = (const float*)d_in[2];
    const float* W1     = (const float*)d_in[3];
    const float* asrc1  = (const float*)d_in[4];
    const float* adst1  = (const float*)d_in[5];
    const float* aedge1 = (const float*)d_in[6];
    const float* We1    = (const float*)d_in[7];
    const float* b1     = (const float*)d_in[8];
    const float* W2     = (const float*)d_in[9];
    const float* asrc2  = (const float*)d_in[10];
    const float* adst2  = (const float*)d_in[11];
    const float* aedge2 = (const float*)d_in[12];
    const float* We2    = (const float*)d_in[13];
    const float* b2     = (const float*)d_in[14];
    const float* Wf     = (const float*)d_in[15];
    const float* bf     = (const float*)d_in[16];
    const int* src = ei;
    const int* dst = ei + NE;
    float* out = (float*)d_out;

    void* p;
    cudaGetSymbolAddress(&p, g_xw);   float* xw   = (float*)p;
    cudaGetSymbolAddress(&p, g_h);    float* hbuf = (float*)p;
    cudaGetSymbolAddress(&p, g_Aext); __nv_bfloat16* Aext = (__nv_bfloat16*)p;
    cudaGetSymbolAddress(&p, g_Bt);   __nv_bfloat16* Bt   = (__nv_bfloat16*)p;

    static bool attr_done = false;
    if (!attr_done) {
        cudaFuncSetAttribute(k_mma_gemm, cudaFuncAttributeMaxDynamicSharedMemorySize, MMA_SMEM);
        attr_done = true;
    }

    // Wf -> split-bf16 transposed (depends only on input weights)
    k_convB<<<dim3(DOUT / 32, HC / 32), dim3(32, 32)>>>(Wf);

    // graph structure (CSR by dst)
    k_zero_deg<<<(NN + 255) / 256, 256>>>();
    k_count<<<(NE + 255) / 256, 256>>>(dst);
    k_scan<<<1, 1024>>>();
    k_fill<<<(NE + 255) / 256, 256>>>(dst);

    dim3 gL(HC / 128, (NN + 127) / 128);

    // ---- layer 1 ----
    k_sgemm<false><<<gL, 256>>>(x, W1, nullptr, xw, NN, HC, DIN);
    k_al<<<NN, 128>>>(xw, asrc1, adst1);
    k_V<<<1, 256>>>(We1, aedge1);
    k_zero_esum<<<(NN * H_ + 255) / 256, 256>>>();
    k_edge_al<<<(NE + 255) / 256, 256>>>(ef, dst);
    k_alpha<<<(NE + 255) / 256, 256>>>(src, dst);
    k_aself<<<(NN + 255) / 256, 256>>>();
    k_aggregate<<<NN, 256>>>(xw, src, b1, hbuf, 1);

    // ---- layer 2 ----
    k_sgemm<false><<<gL, 256>>>(hbuf, W2, nullptr, xw, NN, HC, HC);
    k_al<<<NN, 128>>>(xw, asrc2, adst2);
    k_V<<<1, 256>>>(We2, aedge2);
    k_zero_esum<<<(NN * H_ + 255) / 256, 256>>>();
    k_edge_al<<<(NE + 255) / 256, 256>>>(ef, dst);
    k_alpha<<<(NE + 255) / 256, 256>>>(src, dst);
    k_aself<<<(NN + 255) / 256, 256>>>();
    k_aggregate<<<NN, 256>>>(xw, src, b2, hbuf, 1);

    // ---- final linear on tensor cores: out = h2 @ Wf + bf (split-bf16) ----
    k_convA<<<(MPAD * HC + 255) / 256, 256>>>(hbuf);
    dim3 gT(MPAD / 128, DOUT / 128);   // x = m-block fastest: A panel stays L2-resident
    k_mma_gemm<<<gT, 256, MMA_SMEM>>>(Aext, Bt, bf, out);
}

// round 5
// speedup vs baseline: 2.4512x; 1.0025x over previous
#include <cuda_runtime.h>
#include <cuda_bf16.h>
#include <math.h>
#include <stdint.h>

// Problem constants (fixed shapes per metadata)
constexpr int NN   = 10000;   // nodes
constexpr int NE   = 160000;  // edges
constexpr int DIN  = 128;     // input feature dim
constexpr int EDIM = 16;      // edge feature dim
constexpr int H_   = 4;       // heads
constexpr int C_   = 256;     // channels per head
constexpr int HC   = 1024;    // H*C
constexpr int DOUT = 25088;   // final output dim

constexpr int MPAD = 10112;   // 79 * 128 (M padded)
constexpr int KSF  = 3 * HC;  // 3072 split-K for K=1024 GEMMs

// ---------------- scratch (static device globals: allocation-free) ----------
__device__ float g_xw[NN * HC];
__device__ float g_h[NN * HC];
__device__ float g_al_src[NN * H_];
__device__ float g_al_dst[NN * H_];
__device__ float g_al_e[NE * H_];
__device__ float g_al_esum[NN * H_];
__device__ float g_alpha[NE * H_];
__device__ float g_aself[NN * H_];
__device__ float g_V[EDIM * H_];
__device__ int   g_deg[NN];
__device__ int   g_rowptr[NN + 1];
__device__ int   g_cursor[NN];
__device__ int   g_esorted[NE];
__device__ __nv_bfloat16 g_Asp[(size_t)MPAD * KSF];    // split A (reused per GEMM)
__device__ __nv_bfloat16 g_BtF[(size_t)DOUT * KSF];    // Wf^T split [25088,3072]
__device__ __nv_bfloat16 g_Bt2[(size_t)HC * KSF];      // W2^T split [1024,3072]
__device__ __nv_bfloat16 g_Bt1[(size_t)HC * 3 * DIN];  // W1^T split [1024,384]

// ---------------- graph structure kernels ----------------------------------
__global__ void k_zero_deg() {
    int i = blockIdx.x * blockDim.x + threadIdx.x;
    if (i < NN) g_deg[i] = 0;
}

__global__ void k_zero_esum() {
    int i = blockIdx.x * blockDim.x + threadIdx.x;
    if (i < NN * H_) g_al_esum[i] = 0.f;
}

__global__ void k_count(const int* __restrict__ dst) {
    int e = blockIdx.x * blockDim.x + threadIdx.x;
    if (e < NE) atomicAdd(&g_deg[dst[e]], 1);
}

__global__ void k_scan() {
    __shared__ int sh[1024];
    __shared__ int carry;
    int t = threadIdx.x;
    if (t == 0) carry = 0;
    __syncthreads();
    for (int base = 0; base < NN; base += 1024) {
        int i = base + t;
        int v = (i < NN) ? g_deg[i] : 0;
        sh[t] = v;
        __syncthreads();
        for (int off = 1; off < 1024; off <<= 1) {
            int xv = (t >= off) ? sh[t - off] : 0;
            __syncthreads();
            if (t >= off) sh[t] += xv;
            __syncthreads();
        }
        int excl = sh[t] - v + carry;
        if (i < NN) { g_rowptr[i] = excl; g_cursor[i] = excl; }
        int tot = sh[1023];
        __syncthreads();
        if (t == 0) carry += tot;
        __syncthreads();
    }
    if (t == 0) g_rowptr[NN] = carry;
}

__global__ void k_fill(const int* __restrict__ dst) {
    int e = blockIdx.x * blockDim.x + threadIdx.x;
    if (e < NE) {
        int p = atomicAdd(&g_cursor[dst[e]], 1);
        g_esorted[p] = e;
    }
}

// ---------------- attention logit pieces ------------------------------------
__global__ void k_al(const float* __restrict__ xw,
                     const float* __restrict__ asrc, const float* __restrict__ adst) {
    int n = blockIdx.x;
    int w = threadIdx.x >> 5, l = threadIdx.x & 31;
    const float* row = xw + (size_t)n * HC + w * C_;
    const float* as  = asrc + w * C_;
    const float* ad  = adst + w * C_;
    float s = 0.f, d = 0.f;
    for (int c = l; c < C_; c += 32) {
        float v = row[c];
        s += v * as[c];
        d += v * ad[c];
    }
#pragma unroll
    for (int off = 16; off; off >>= 1) {
        s += __shfl_xor_sync(0xffffffffu, s, off);
        d += __shfl_xor_sync(0xffffffffu, d, off);
    }
    if (l == 0) { g_al_src[n * H_ + w] = s; g_al_dst[n * H_ + w] = d; }
}

__global__ void k_V(const float* __restrict__ We, const float* __restrict__ aedge) {
    int w = threadIdx.x >> 5, l = threadIdx.x & 31;
    for (int o = w; o < EDIM * H_; o += 8) {
        int d = o / H_, h = o % H_;
        float s = 0.f;
        for (int c = l; c < C_; c += 32)
            s += We[(size_t)d * HC + h * C_ + c] * aedge[h * C_ + c];
#pragma unroll
        for (int off = 16; off; off >>= 1) s += __shfl_xor_sync(0xffffffffu, s, off);
        if (l == 0) g_V[o] = s;
    }
}

__global__ void k_edge_al(const float* __restrict__ ef, const int* __restrict__ dst) {
    int e = blockIdx.x * blockDim.x + threadIdx.x;
    if (e >= NE) return;
    float ea[EDIM];
#pragma unroll
    for (int d = 0; d < EDIM; d++) ea[d] = ef[(size_t)e * EDIM + d];
    int dn = dst[e];
#pragma unroll
    for (int h = 0; h < H_; h++) {
        float s = 0.f;
#pragma unroll
        for (int d = 0; d < EDIM; d++) s += ea[d] * g_V[d * H_ + h];
        g_al_e[e * H_ + h] = s;
        atomicAdd(&g_al_esum[dn * H_ + h], s);
    }
}

__global__ void k_alpha(const int* __restrict__ src, const int* __restrict__ dst) {
    int e = blockIdx.x * blockDim.x + threadIdx.x;
    if (e >= NE) return;
    int sn = src[e], dn = dst[e];
#pragma unroll
    for (int h = 0; h < H_; h++) {
        float v = g_al_src[sn * H_ + h] + g_al_dst[dn * H_ + h] + g_al_e[e * H_ + h];
        g_alpha[e * H_ + h] = v > 0.f ? v : 0.2f * v;
    }
}

__global__ void k_aself() {
    int n = blockIdx.x * blockDim.x + threadIdx.x;
    if (n >= NN) return;
    float invd = 1.0f / fmaxf((float)g_deg[n], 1.0f);
#pragma unroll
    for (int h = 0; h < H_; h++) {
        float v = g_al_src[n * H_ + h] + g_al_dst[n * H_ + h] + g_al_esum[n * H_ + h] * invd;
        g_aself[n * H_ + h] = v > 0.f ? v : 0.2f * v;
    }
}

// ---------------- segment softmax + aggregation (1 block / node) ------------
__global__ void __launch_bounds__(256)
k_aggregate(const float* __restrict__ xw, const int* __restrict__ src,
            const float* __restrict__ bias, float* __restrict__ out, int do_elu) {
    int n = blockIdx.x;
    int beg = g_rowptr[n], end = g_rowptr[n + 1];
    __shared__ float sm[H_], ss[H_];
    int t = threadIdx.x, w = t >> 5, l = t & 31;

    if (w < H_) {
        float mx = g_aself[n * H_ + w];
        for (int i = beg + l; i < end; i += 32)
            mx = fmaxf(mx, g_alpha[g_esorted[i] * H_ + w]);
#pragma unroll
        for (int off = 16; off; off >>= 1)
            mx = fmaxf(mx, __shfl_xor_sync(0xffffffffu, mx, off));
        if (l == 0) sm[w] = mx;
    }
    __syncthreads();

    if (w < H_) {
        float mm = sm[w];
        float acc = (l == 0) ? expf(g_aself[n * H_ + w] - mm) : 0.f;
        for (int i = beg + l; i < end; i += 32) {
            int e = g_esorted[i];
            float ex = expf(g_alpha[e * H_ + w] - mm);
            g_alpha[e * H_ + w] = ex;
            acc += ex;
        }
#pragma unroll
        for (int off = 16; off; off >>= 1) acc += __shfl_xor_sync(0xffffffffu, acc, off);
        if (l == 0) ss[w] = acc;
    }
    __syncthreads();

    float inv[H_];
#pragma unroll
    for (int h = 0; h < H_; h++) inv[h] = 1.0f / (ss[h] + 1e-16f);
    float acc[H_] = {0.f, 0.f, 0.f, 0.f};
    for (int i = beg; i < end; i++) {
        int e = g_esorted[i];
        int sn = src[e];
        const float* row = xw + (size_t)sn * HC;
#pragma unroll
        for (int h = 0; h < H_; h++) {
            float wg = g_alpha[e * H_ + h] * inv[h];
            acc[h] += wg * row[h * C_ + t];
        }
    }
    const float* srow = xw + (size_t)n * HC;
#pragma unroll
    for (int h = 0; h < H_; h++) {
        float wg = expf(g_aself[n * H_ + h] - sm[h]) * inv[h];
        acc[h] += wg * srow[h * C_ + t];
    }
#pragma unroll
    for (int h = 0; h < H_; h++) {
        float v = acc[h] + bias[h * C_ + t];
        if (do_elu) v = v > 0.f ? v : expm1f(v);
        out[(size_t)n * HC + h * C_ + t] = v;
    }
}

// ---------------- split-bf16 conversions ------------------------------------
// A' rows [hi | lo | hi] along K (len 3K).  Rows >= Mv zero-padded.
__global__ void k_convA(const float* __restrict__ src, __nv_bfloat16* __restrict__ dst,
                        int Mv, int K) {
    int i = blockIdx.x * blockDim.x + threadIdx.x;
    if (i >= MPAD * K) return;
    int m = i / K, k = i - m * K;
    float a = (m < Mv) ? src[(size_t)m * K + k] : 0.f;
    __nv_bfloat16 hi = __float2bfloat16(a);
    __nv_bfloat16 lo = __float2bfloat16(a - __bfloat162float(hi));
    size_t base = (size_t)m * (3 * K) + k;
    dst[base]         = hi;
    dst[base + K]     = lo;
    dst[base + 2 * K] = hi;
}

// B' = transpose(W[K,N]) with K-segments [hi | hi | lo], rows len 3K.
__global__ void k_convB(const float* __restrict__ W, __nv_bfloat16* __restrict__ dst,
                        int K, int Nn) {
    __shared__ float t[32][33];
    int n = blockIdx.x * 32 + threadIdx.x;
    int k = blockIdx.y * 32 + threadIdx.y;
    t[threadIdx.y][threadIdx.x] = W[(size_t)k * Nn + n];
    __syncthreads();
    int n2 = blockIdx.x * 32 + threadIdx.y;
    int k2 = blockIdx.y * 32 + threadIdx.x;
    float a = t[threadIdx.x][threadIdx.y];
    __nv_bfloat16 hi = __float2bfloat16(a);
    __nv_bfloat16 lo = __float2bfloat16(a - __bfloat162float(hi));
    size_t base = (size_t)n2 * (3 * K) + k2;
    dst[base]         = hi;
    dst[base + K]     = hi;
    dst[base + 2 * K] = lo;
}

// ---------------- HMMA bf16 GEMM -------------------------------------------
// out[m,n] (+bias[n]) = A'[m, Kext] . B'[n, Kext]    fp32 accumulate
// CTA tile 128x256, BK=32, 8 warps each 64x64, 4-stage cp.async pipeline.

__device__ __forceinline__ uint32_t s2u(const void* p) {
    uint32_t a;
    asm("{ .reg .u64 t; cvta.to.shared.u64 t, %1; cvt.u32.u64 %0, t; }" : "=r"(a) : "l"(p));
    return a;
}

__device__ __forceinline__ void cp16(uint32_t saddr, const void* gptr) {
    asm volatile("cp.async.cg.shared.global [%0], [%1], 16;" :: "r"(saddr), "l"(gptr));
}

#define LDSM4(r, addr) \
    asm volatile("ldmatrix.sync.aligned.m8n8.x4.shared.b16 {%0,%1,%2,%3}, [%4];" \
        : "=r"((r)[0]), "=r"((r)[1]), "=r"((r)[2]), "=r"((r)[3]) : "r"(addr))

#define MMA16816(c, a, b0, b1) \
    asm volatile("mma.sync.aligned.m16n8k16.row.col.f32.bf16.bf16.f32 " \
        "{%0,%1,%2,%3}, {%4,%5,%6,%7}, {%8,%9}, {%0,%1,%2,%3};" \
        : "+f"((c)[0]), "+f"((c)[1]), "+f"((c)[2]), "+f"((c)[3]) \
        : "r"((a)[0]), "r"((a)[1]), "r"((a)[2]), "r"((a)[3]), "r"(b0), "r"(b1))

constexpr int STAGE_BYTES = 24576;              // A 8KB + B 16KB
constexpr int MMA_SMEM    = 4 * STAGE_BYTES;    // 96 KB

template <bool BIAS>
__global__ void __launch_bounds__(256, 1)
k_mma_gemm(const __nv_bfloat16* __restrict__ A, const __nv_bfloat16* __restrict__ B,
           const float* __restrict__ bias, float* __restrict__ out,
           int Mv, int Kext, int ldo) {
    extern __shared__ char smem[];
    const uint32_t sb = s2u(smem);
    const int tid  = threadIdx.x;
    const int lane = tid & 31, wid = tid >> 5;
    const int wm = (wid & 1) * 64, wn = (wid >> 1) * 64;
    const int bm = blockIdx.x * 128, bn = blockIdx.y * 256;
    const int KITER = Kext >> 5;

    const __nv_bfloat16* ag0 = A + (size_t)bm * Kext;
    const __nv_bfloat16* bg0 = B + (size_t)bn * Kext;

    // swizzle: 16B segment s of row r -> phys seg (s ^ ((r>>1)&3))
    auto load_stage = [&](int kt, int slot) {
        const int k0 = kt * 32;
        const uint32_t sa  = sb + slot * STAGE_BYTES;
        const uint32_t sbm = sa + 8192;
#pragma unroll
        for (int i = 0; i < 2; i++) {     // A: 128 rows x 4 segs = 512
            int u = tid + i * 256;
            int row = u >> 2, seg = u & 3;
            uint32_t off = row * 64 + ((seg ^ ((row >> 1) & 3)) << 4);
            cp16(sa + off, ag0 + (size_t)row * Kext + k0 + seg * 8);
        }
#pragma unroll
        for (int i = 0; i < 4; i++) {     // B: 256 rows x 4 segs = 1024
            int u = tid + i * 256;
            int row = u >> 2, seg = u & 3;
            uint32_t off = row * 64 + ((seg ^ ((row >> 1) & 3)) << 4);
            cp16(sbm + off, bg0 + (size_t)row * Kext + k0 + seg * 8);
        }
    };

    float acc[4][8][4];
#pragma unroll
    for (int i = 0; i < 4; i++)
#pragma unroll
        for (int j = 0; j < 8; j++)
#pragma unroll
            for (int r = 0; r < 4; r++) acc[i][j][r] = 0.f;

    load_stage(0, 0);
    asm volatile("cp.async.commit_group;" ::: "memory");
    load_stage(1, 1);
    asm volatile("cp.async.commit_group;" ::: "memory");
    load_stage(2, 2);
    asm volatile("cp.async.commit_group;" ::: "memory");

    for (int kt = 0; kt < KITER; kt++) {
        asm volatile("cp.async.wait_group 2;" ::: "memory");
        __syncthreads();
        if (kt + 3 < KITER) load_stage(kt + 3, (kt + 3) & 3);
        asm volatile("cp.async.commit_group;" ::: "memory");

        const uint32_t sa  = sb + (kt & 3) * STAGE_BYTES;
        const uint32_t sbm = sa + 8192;
#pragma unroll
        for (int ks2 = 0; ks2 < 2; ks2++) {
            uint32_t av[4][4], bv[4][4];
            const int segk = ks2 * 2 + (lane >> 4);
#pragma unroll
            for (int mf = 0; mf < 4; mf++) {
                int row = wm + mf * 16 + (lane & 15);
                LDSM4(av[mf], sa + row * 64 + ((segk ^ ((row >> 1) & 3)) << 4));
            }
#pragma unroll
            for (int p = 0; p < 4; p++) {
                int row = wn + p * 16 + (lane & 15);
                LDSM4(bv[p], sbm + row * 64 + ((segk ^ ((row >> 1) & 3)) << 4));
            }
#pragma unroll
            for (int mf = 0; mf < 4; mf++)
#pragma unroll
                for (int p = 0; p < 4; p++) {
                    MMA16816(acc[mf][p * 2 + 0], av[mf], bv[p][0], bv[p][2]);
                    MMA16816(acc[mf][p * 2 + 1], av[mf], bv[p][1], bv[p][3]);
                }
        }
    }

    // epilogue
    const int r0 = lane >> 2, c0 = (lane & 3) * 2;
#pragma unroll
    for (int mf = 0; mf < 4; mf++) {
#pragma unroll
        for (int half = 0; half < 2; half++) {
            int m = bm + wm + mf * 16 + r0 + half * 8;
            if (m >= Mv) continue;
            float* orow = out + (size_t)m * ldo;
#pragma unroll
            for (int nf = 0; nf < 8; nf++) {
                int n = bn + wn + nf * 8 + c0;
                float2 v;
                v.x = acc[mf][nf][half * 2 + 0];
                v.y = acc[mf][nf][half * 2 + 1];
                if (BIAS) { v.x += __ldg(bias + n); v.y += __ldg(bias + n + 1); }
                *reinterpret_cast<float2*>(orow + n) = v;
            }
        }
    }
}

// ---------------- launch -----------------------------------------------------
extern "C" void kernel_launch(void* const* d_in, const int* in_sizes, int n_in,
                              void* d_out, int out_size) {
    const float* x      = (const float*)d_in[0];
    const int*   ei     = (const int*)d_in[1];
    const float* ef     = (const float*)d_in[2];
    const float* W1     = (const float*)d_in[3];
    const float* asrc1  = (const float*)d_in[4];
    const float* adst1  = (const float*)d_in[5];
    const float* aedge1 = (const float*)d_in[6];
    const float* We1    = (const float*)d_in[7];
    const float* b1     = (const float*)d_in[8];
    const float* W2     = (const float*)d_in[9];
    const float* asrc2  = (const float*)d_in[10];
    const float* adst2  = (const float*)d_in[11];
    const float* aedge2 = (const float*)d_in[12];
    const float* We2    = (const float*)d_in[13];
    const float* b2     = (const float*)d_in[14];
    const float* Wf     = (const float*)d_in[15];
    const float* bf     = (const float*)d_in[16];
    const int* src = ei;
    const int* dst = ei + NE;
    float* out = (float*)d_out;

    void* p;
    cudaGetSymbolAddress(&p, g_xw);  float* xw   = (float*)p;
    cudaGetSymbolAddress(&p, g_h);   float* hbuf = (float*)p;
    cudaGetSymbolAddress(&p, g_Asp); __nv_bfloat16* Asp = (__nv_bfloat16*)p;
    cudaGetSymbolAddress(&p, g_BtF); __nv_bfloat16* BtF = (__nv_bfloat16*)p;
    cudaGetSymbolAddress(&p, g_Bt2); __nv_bfloat16* Bt2 = (__nv_bfloat16*)p;
    cudaGetSymbolAddress(&p, g_Bt1); __nv_bfloat16* Bt1 = (__nv_bfloat16*)p;

    static bool attr_done = false;
    if (!attr_done) {
        cudaFuncSetAttribute(k_mma_gemm<true>,  cudaFuncAttributeMaxDynamicSharedMemorySize, MMA_SMEM);
        cudaFuncSetAttribute(k_mma_gemm<false>, cudaFuncAttributeMaxDynamicSharedMemorySize, MMA_SMEM);
        attr_done = true;
    }

    // weight conversions (independent of activations)
    k_convB<<<dim3(HC / 32, DIN / 32), dim3(32, 32)>>>(W1, Bt1, DIN, HC);
    k_convB<<<dim3(HC / 32, HC / 32), dim3(32, 32)>>>(W2, Bt2, HC, HC);
    k_convB<<<dim3(DOUT / 32, HC / 32), dim3(32, 32)>>>(Wf, BtF, HC, DOUT);

    // graph structure (CSR by dst)
    k_zero_deg<<<(NN + 255) / 256, 256>>>();
    k_count<<<(NE + 255) / 256, 256>>>(dst);
    k_scan<<<1, 1024>>>();
    k_fill<<<(NE + 255) / 256, 256>>>(dst);

    // ---- layer 1:  xw = x @ W1  (HMMA split-bf16) ----
    k_convA<<<(MPAD * DIN + 255) / 256, 256>>>(x, Asp, NN, DIN);
    k_mma_gemm<false><<<dim3(MPAD / 128, HC / 256), 256, MMA_SMEM>>>(
        Asp, Bt1, nullptr, xw, NN, 3 * DIN, HC);
    k_al<<<NN, 128>>>(xw, asrc1, adst1);
    k_V<<<1, 256>>>(We1, aedge1);
    k_zero_esum<<<(NN * H_ + 255) / 256, 256>>>();
    k_edge_al<<<(NE + 255) / 256, 256>>>(ef, dst);
    k_alpha<<<(NE + 255) / 256, 256>>>(src, dst);
    k_aself<<<(NN + 255) / 256, 256>>>();
    k_aggregate<<<NN, 256>>>(xw, src, b1, hbuf, 1);

    // ---- layer 2:  xw = h1 @ W2 ----
    k_convA<<<(MPAD * HC + 255) / 256, 256>>>(hbuf, Asp, NN, HC);
    k_mma_gemm<false><<<dim3(MPAD / 128, HC / 256), 256, MMA_SMEM>>>(
        Asp, Bt2, nullptr, xw, NN, KSF, HC);
    k_al<<<NN, 128>>>(xw, asrc2, adst2);
    k_V<<<1, 256>>>(We2, aedge2);
    k_zero_esum<<<(NN * H_ + 255) / 256, 256>>>();
    k_edge_al<<<(NE + 255) / 256, 256>>>(ef, dst);
    k_alpha<<<(NE + 255) / 256, 256>>>(src, dst);
    k_aself<<<(NN + 255) / 256, 256>>>();
    k_aggregate<<<NN, 256>>>(xw, src, b2, hbuf, 1);

    // ---- final linear: out = h2 @ Wf + bf ----
    k_convA<<<(MPAD * HC + 255) / 256, 256>>>(hbuf, Asp, NN, HC);
    k_mma_gemm<true><<<dim3(MPAD / 128, DOUT / 256), 256, MMA_SMEM>>>(
        Asp, BtF, bf, out, NN, KSF, DOUT);
}

// round 6
// speedup vs baseline: 2.6201x; 1.0689x over previous
#include <cuda_runtime.h>
#include <cuda_bf16.h>
#include <math.h>
#include <stdint.h>

// Problem constants (fixed shapes per metadata)
constexpr int NN   = 10000;   // nodes
constexpr int NE   = 160000;  // edges
constexpr int DIN  = 128;     // input feature dim
constexpr int EDIM = 16;      // edge feature dim
constexpr int H_   = 4;       // heads
constexpr int C_   = 256;     // channels per head
constexpr int HC   = 1024;    // H*C
constexpr int DOUT = 25088;   // final output dim

constexpr int MPAD = 10112;   // 79 * 128 (M padded)
constexpr int KSF  = 3 * HC;  // 3072 split-K for K=1024 GEMMs

// ---------------- scratch (static device globals: allocation-free) ----------
__device__ float g_xw[NN * HC];
__device__ float g_h[NN * HC];
__device__ float g_al_src[NN * H_];
__device__ float g_al_dst[NN * H_];
__device__ float g_al_e[NE * H_];
__device__ float g_al_esum[NN * H_];
__device__ float g_alpha[NE * H_];
__device__ float g_aself[NN * H_];
__device__ float g_V[EDIM * H_];
__device__ int   g_deg[NN];
__device__ int   g_rowptr[NN + 1];
__device__ int   g_cursor[NN];
__device__ int   g_esorted[NE];
__device__ __nv_bfloat16 g_Asp[(size_t)MPAD * KSF];    // split A (reused per GEMM)
__device__ __nv_bfloat16 g_BtF[(size_t)DOUT * KSF];    // Wf^T split [25088,3072]
__device__ __nv_bfloat16 g_Bt2[(size_t)HC * KSF];      // W2^T split [1024,3072]
__device__ __nv_bfloat16 g_Bt1[(size_t)HC * 3 * DIN];  // W1^T split [1024,384]

// ---------------- graph structure kernels ----------------------------------
__global__ void k_zero_deg() {
    int i = blockIdx.x * blockDim.x + threadIdx.x;
    if (i < NN) g_deg[i] = 0;
}

__global__ void k_zero_esum() {
    int i = blockIdx.x * blockDim.x + threadIdx.x;
    if (i < NN * H_) g_al_esum[i] = 0.f;
}

__global__ void k_count(const int* __restrict__ dst) {
    int e = blockIdx.x * blockDim.x + threadIdx.x;
    if (e < NE) atomicAdd(&g_deg[dst[e]], 1);
}

__global__ void k_scan() {
    __shared__ int sh[1024];
    __shared__ int carry;
    int t = threadIdx.x;
    if (t == 0) carry = 0;
    __syncthreads();
    for (int base = 0; base < NN; base += 1024) {
        int i = base + t;
        int v = (i < NN) ? g_deg[i] : 0;
        sh[t] = v;
        __syncthreads();
        for (int off = 1; off < 1024; off <<= 1) {
            int xv = (t >= off) ? sh[t - off] : 0;
            __syncthreads();
            if (t >= off) sh[t] += xv;
            __syncthreads();
        }
        int excl = sh[t] - v + carry;
        if (i < NN) { g_rowptr[i] = excl; g_cursor[i] = excl; }
        int tot = sh[1023];
        __syncthreads();
        if (t == 0) carry += tot;
        __syncthreads();
    }
    if (t == 0) g_rowptr[NN] = carry;
}

__global__ void k_fill(const int* __restrict__ dst) {
    int e = blockIdx.x * blockDim.x + threadIdx.x;
    if (e < NE) {
        int p = atomicAdd(&g_cursor[dst[e]], 1);
        g_esorted[p] = e;
    }
}

// ---------------- attention logit pieces ------------------------------------
__global__ void k_al(const float* __restrict__ xw,
                     const float* __restrict__ asrc, const float* __restrict__ adst) {
    int n = blockIdx.x;
    int w = threadIdx.x >> 5, l = threadIdx.x & 31;
    const float* row = xw + (size_t)n * HC + w * C_;
    const float* as  = asrc + w * C_;
    const float* ad  = adst + w * C_;
    float s = 0.f, d = 0.f;
    for (int c = l; c < C_; c += 32) {
        float v = row[c];
        s += v * as[c];
        d += v * ad[c];
    }
#pragma unroll
    for (int off = 16; off; off >>= 1) {
        s += __shfl_xor_sync(0xffffffffu, s, off);
        d += __shfl_xor_sync(0xffffffffu, d, off);
    }
    if (l == 0) { g_al_src[n * H_ + w] = s; g_al_dst[n * H_ + w] = d; }
}

__global__ void k_V(const float* __restrict__ We, const float* __restrict__ aedge) {
    int w = threadIdx.x >> 5, l = threadIdx.x & 31;
    for (int o = w; o < EDIM * H_; o += 8) {
        int d = o / H_, h = o % H_;
        float s = 0.f;
        for (int c = l; c < C_; c += 32)
            s += We[(size_t)d * HC + h * C_ + c] * aedge[h * C_ + c];
#pragma unroll
        for (int off = 16; off; off >>= 1) s += __shfl_xor_sync(0xffffffffu, s, off);
        if (l == 0) g_V[o] = s;
    }
}

__global__ void k_edge_al(const float* __restrict__ ef, const int* __restrict__ dst) {
    int e = blockIdx.x * blockDim.x + threadIdx.x;
    if (e >= NE) return;
    float ea[EDIM];
#pragma unroll
    for (int d = 0; d < EDIM; d++) ea[d] = ef[(size_t)e * EDIM + d];
    int dn = dst[e];
#pragma unroll
    for (int h = 0; h < H_; h++) {
        float s = 0.f;
#pragma unroll
        for (int d = 0; d < EDIM; d++) s += ea[d] * g_V[d * H_ + h];
        g_al_e[e * H_ + h] = s;
        atomicAdd(&g_al_esum[dn * H_ + h], s);
    }
}

__global__ void k_alpha(const int* __restrict__ src, const int* __restrict__ dst) {
    int e = blockIdx.x * blockDim.x + threadIdx.x;
    if (e >= NE) return;
    int sn = src[e], dn = dst[e];
#pragma unroll
    for (int h = 0; h < H_; h++) {
        float v = g_al_src[sn * H_ + h] + g_al_dst[dn * H_ + h] + g_al_e[e * H_ + h];
        g_alpha[e * H_ + h] = v > 0.f ? v : 0.2f * v;
    }
}

__global__ void k_aself() {
    int n = blockIdx.x * blockDim.x + threadIdx.x;
    if (n >= NN) return;
    float invd = 1.0f / fmaxf((float)g_deg[n], 1.0f);
#pragma unroll
    for (int h = 0; h < H_; h++) {
        float v = g_al_src[n * H_ + h] + g_al_dst[n * H_ + h] + g_al_esum[n * H_ + h] * invd;
        g_aself[n * H_ + h] = v > 0.f ? v : 0.2f * v;
    }
}

// ---------------- segment softmax + aggregation (1 block / node) ------------
__global__ void __launch_bounds__(256)
k_aggregate(const float* __restrict__ xw, const int* __restrict__ src,
            const float* __restrict__ bias, float* __restrict__ out, int do_elu) {
    int n = blockIdx.x;
    int beg = g_rowptr[n], end = g_rowptr[n + 1];
    __shared__ float sm[H_], ss[H_];
    int t = threadIdx.x, w = t >> 5, l = t & 31;

    if (w < H_) {
        float mx = g_aself[n * H_ + w];
        for (int i = beg + l; i < end; i += 32)
            mx = fmaxf(mx, g_alpha[g_esorted[i] * H_ + w]);
#pragma unroll
        for (int off = 16; off; off >>= 1)
            mx = fmaxf(mx, __shfl_xor_sync(0xffffffffu, mx, off));
        if (l == 0) sm[w] = mx;
    }
    __syncthreads();

    if (w < H_) {
        float mm = sm[w];
        float acc = (l == 0) ? expf(g_aself[n * H_ + w] - mm) : 0.f;
        for (int i = beg + l; i < end; i += 32) {
            int e = g_esorted[i];
            float ex = expf(g_alpha[e * H_ + w] - mm);
            g_alpha[e * H_ + w] = ex;
            acc += ex;
        }
#pragma unroll
        for (int off = 16; off; off >>= 1) acc += __shfl_xor_sync(0xffffffffu, acc, off);
        if (l == 0) ss[w] = acc;
    }
    __syncthreads();

    float inv[H_];
#pragma unroll
    for (int h = 0; h < H_; h++) inv[h] = 1.0f / (ss[h] + 1e-16f);
    float acc[H_] = {0.f, 0.f, 0.f, 0.f};
    for (int i = beg; i < end; i++) {
        int e = g_esorted[i];
        int sn = src[e];
        const float* row = xw + (size_t)sn * HC;
#pragma unroll
        for (int h = 0; h < H_; h++) {
            float wg = g_alpha[e * H_ + h] * inv[h];
            acc[h] += wg * row[h * C_ + t];
        }
    }
    const float* srow = xw + (size_t)n * HC;
#pragma unroll
    for (int h = 0; h < H_; h++) {
        float wg = expf(g_aself[n * H_ + h] - sm[h]) * inv[h];
        acc[h] += wg * srow[h * C_ + t];
    }
#pragma unroll
    for (int h = 0; h < H_; h++) {
        float v = acc[h] + bias[h * C_ + t];
        if (do_elu) v = v > 0.f ? v : expm1f(v);
        out[(size_t)n * HC + h * C_ + t] = v;
    }
}

// ---------------- split-bf16 conversions ------------------------------------
// A' rows [hi | lo | hi] along K (len 3K).  Rows >= Mv zero-padded.
__global__ void k_convA(const float* __restrict__ src, __nv_bfloat16* __restrict__ dst,
                        int Mv, int K) {
    int i = blockIdx.x * blockDim.x + threadIdx.x;
    if (i >= MPAD * K) return;
    int m = i / K, k = i - m * K;
    float a = (m < Mv) ? src[(size_t)m * K + k] : 0.f;
    __nv_bfloat16 hi = __float2bfloat16(a);
    __nv_bfloat16 lo = __float2bfloat16(a - __bfloat162float(hi));
    size_t base = (size_t)m * (3 * K) + k;
    dst[base]         = hi;
    dst[base + K]     = lo;
    dst[base + 2 * K] = hi;
}

// B' = transpose(W[K,N]) with K-segments [hi | hi | lo], rows len 3K.
__global__ void k_convB(const float* __restrict__ W, __nv_bfloat16* __restrict__ dst,
                        int K, int Nn) {
    __shared__ float t[32][33];
    int n = blockIdx.x * 32 + threadIdx.x;
    int k = blockIdx.y * 32 + threadIdx.y;
    t[threadIdx.y][threadIdx.x] = W[(size_t)k * Nn + n];
    __syncthreads();
    int n2 = blockIdx.x * 32 + threadIdx.y;
    int k2 = blockIdx.y * 32 + threadIdx.x;
    float a = t[threadIdx.x][threadIdx.y];
    __nv_bfloat16 hi = __float2bfloat16(a);
    __nv_bfloat16 lo = __float2bfloat16(a - __bfloat162float(hi));
    size_t base = (size_t)n2 * (3 * K) + k2;
    dst[base]         = hi;
    dst[base + K]     = hi;
    dst[base + 2 * K] = lo;
}

// ---------------- HMMA bf16 GEMM -------------------------------------------
// out[m,n] (+bias[n]) = A'[m, Kext] . B'[n, Kext]    fp32 accumulate
// CTA tile 128x256, 512 threads (16 warps, warp tile 32x64), BK=32,
// 4-stage cp.async pipeline.  1 CTA/SM but full 16-warp residency.

__device__ __forceinline__ uint32_t s2u(const void* p) {
    uint32_t a;
    asm("{ .reg .u64 t; cvta.to.shared.u64 t, %1; cvt.u32.u64 %0, t; }" : "=r"(a) : "l"(p));
    return a;
}

__device__ __forceinline__ void cp16(uint32_t saddr, const void* gptr) {
    asm volatile("cp.async.cg.shared.global [%0], [%1], 16;" :: "r"(saddr), "l"(gptr));
}

#define LDSM4(r, addr) \
    asm volatile("ldmatrix.sync.aligned.m8n8.x4.shared.b16 {%0,%1,%2,%3}, [%4];" \
        : "=r"((r)[0]), "=r"((r)[1]), "=r"((r)[2]), "=r"((r)[3]) : "r"(addr))

#define MMA16816(c, a, b0, b1) \
    asm volatile("mma.sync.aligned.m16n8k16.row.col.f32.bf16.bf16.f32 " \
        "{%0,%1,%2,%3}, {%4,%5,%6,%7}, {%8,%9}, {%0,%1,%2,%3};" \
        : "+f"((c)[0]), "+f"((c)[1]), "+f"((c)[2]), "+f"((c)[3]) \
        : "r"((a)[0]), "r"((a)[1]), "r"((a)[2]), "r"((a)[3]), "r"(b0), "r"(b1))

constexpr int STAGE_BYTES = 24576;              // A 8KB + B 16KB
constexpr int MMA_SMEM    = 4 * STAGE_BYTES;    // 96 KB

template <bool BIAS>
__global__ void __launch_bounds__(512, 1)
k_mma_gemm(const __nv_bfloat16* __restrict__ A, const __nv_bfloat16* __restrict__ B,
           const float* __restrict__ bias, float* __restrict__ out,
           int Mv, int Kext, int ldo) {
    extern __shared__ char smem[];
    const uint32_t sb = s2u(smem);
    const int tid  = threadIdx.x;
    const int lane = tid & 31, wid = tid >> 5;
    const int wm = (wid & 3) * 32, wn = (wid >> 2) * 64;
    const int bm = blockIdx.x * 128, bn = blockIdx.y * 256;
    const int KITER = Kext >> 5;

    const __nv_bfloat16* ag0 = A + (size_t)bm * Kext;
    const __nv_bfloat16* bg0 = B + (size_t)bn * Kext;

    // swizzle: 16B segment s of row r -> phys seg (s ^ ((r>>1)&3))
    auto load_stage = [&](int kt, int slot) {
        const int k0 = kt * 32;
        const uint32_t sa  = sb + slot * STAGE_BYTES;
        const uint32_t sbm = sa + 8192;
        {                                  // A: 128 rows x 4 segs = 512
            int row = tid >> 2, seg = tid & 3;
            uint32_t off = row * 64 + ((seg ^ ((row >> 1) & 3)) << 4);
            cp16(sa + off, ag0 + (size_t)row * Kext + k0 + seg * 8);
        }
#pragma unroll
        for (int i = 0; i < 2; i++) {      // B: 256 rows x 4 segs = 1024
            int u = tid + i * 512;
            int row = u >> 2, seg = u & 3;
            uint32_t off = row * 64 + ((seg ^ ((row >> 1) & 3)) << 4);
            cp16(sbm + off, bg0 + (size_t)row * Kext + k0 + seg * 8);
        }
    };

    float acc[2][8][4];
#pragma unroll
    for (int i = 0; i < 2; i++)
#pragma unroll
        for (int j = 0; j < 8; j++)
#pragma unroll
            for (int r = 0; r < 4; r++) acc[i][j][r] = 0.f;

    load_stage(0, 0);
    asm volatile("cp.async.commit_group;" ::: "memory");
    load_stage(1, 1);
    asm volatile("cp.async.commit_group;" ::: "memory");
    load_stage(2, 2);
    asm volatile("cp.async.commit_group;" ::: "memory");

    for (int kt = 0; kt < KITER; kt++) {
        asm volatile("cp.async.wait_group 2;" ::: "memory");
        __syncthreads();
        if (kt + 3 < KITER) load_stage(kt + 3, (kt + 3) & 3);
        asm volatile("cp.async.commit_group;" ::: "memory");

        const uint32_t sa  = sb + (kt & 3) * STAGE_BYTES;
        const uint32_t sbm = sa + 8192;
#pragma unroll
        for (int ks2 = 0; ks2 < 2; ks2++) {
            uint32_t av[2][4], bv[4][4];
            const int segk = ks2 * 2 + (lane >> 4);
#pragma unroll
            for (int mf = 0; mf < 2; mf++) {
                int row = wm + mf * 16 + (lane & 15);
                LDSM4(av[mf], sa + row * 64 + ((segk ^ ((row >> 1) & 3)) << 4));
            }
#pragma unroll
            for (int p = 0; p < 4; p++) {
                int row = wn + p * 16 + (lane & 15);
                LDSM4(bv[p], sbm + row * 64 + ((segk ^ ((row >> 1) & 3)) << 4));
            }
#pragma unroll
            for (int mf = 0; mf < 2; mf++)
#pragma unroll
                for (int p = 0; p < 4; p++) {
                    MMA16816(acc[mf][p * 2 + 0], av[mf], bv[p][0], bv[p][2]);
                    MMA16816(acc[mf][p * 2 + 1], av[mf], bv[p][1], bv[p][3]);
                }
        }
    }

    // epilogue
    const int r0 = lane >> 2, c0 = (lane & 3) * 2;
#pragma unroll
    for (int mf = 0; mf < 2; mf++) {
#pragma unroll
        for (int half = 0; half < 2; half++) {
            int m = bm + wm + mf * 16 + r0 + half * 8;
            if (m >= Mv) continue;
            float* orow = out + (size_t)m * ldo;
#pragma unroll
            for (int nf = 0; nf < 8; nf++) {
                int n = bn + wn + nf * 8 + c0;
                float2 v;
                v.x = acc[mf][nf][half * 2 + 0];
                v.y = acc[mf][nf][half * 2 + 1];
                if (BIAS) { v.x += __ldg(bias + n); v.y += __ldg(bias + n + 1); }
                *reinterpret_cast<float2*>(orow + n) = v;
            }
        }
    }
}

// ---------------- launch -----------------------------------------------------
extern "C" void kernel_launch(void* const* d_in, const int* in_sizes, int n_in,
                              void* d_out, int out_size) {
    const float* x      = (const float*)d_in[0];
    const int*   ei     = (const int*)d_in[1];
    const float* ef     = (const float*)d_in[2];
    const float* W1     = (const float*)d_in[3];
    const float* asrc1  = (const float*)d_in[4];
    const float* adst1  = (const float*)d_in[5];
    const float* aedge1 = (const float*)d_in[6];
    const float* We1    = (const float*)d_in[7];
    const float* b1     = (const float*)d_in[8];
    const float* W2     = (const float*)d_in[9];
    const float* asrc2  = (const float*)d_in[10];
    const float* adst2  = (const float*)d_in[11];
    const float* aedge2 = (const float*)d_in[12];
    const float* We2    = (const float*)d_in[13];
    const float* b2     = (const float*)d_in[14];
    const float* Wf     = (const float*)d_in[15];
    const float* bf     = (const float*)d_in[16];
    const int* src = ei;
    const int* dst = ei + NE;
    float* out = (float*)d_out;

    void* p;
    cudaGetSymbolAddress(&p, g_xw);  float* xw   = (float*)p;
    cudaGetSymbolAddress(&p, g_h);   float* hbuf = (float*)p;
    cudaGetSymbolAddress(&p, g_Asp); __nv_bfloat16* Asp = (__nv_bfloat16*)p;
    cudaGetSymbolAddress(&p, g_BtF); __nv_bfloat16* BtF = (__nv_bfloat16*)p;
    cudaGetSymbolAddress(&p, g_Bt2); __nv_bfloat16* Bt2 = (__nv_bfloat16*)p;
    cudaGetSymbolAddress(&p, g_Bt1); __nv_bfloat16* Bt1 = (__nv_bfloat16*)p;

    static bool attr_done = false;
    if (!attr_done) {
        cudaFuncSetAttribute(k_mma_gemm<true>,  cudaFuncAttributeMaxDynamicSharedMemorySize, MMA_SMEM);
        cudaFuncSetAttribute(k_mma_gemm<false>, cudaFuncAttributeMaxDynamicSharedMemorySize, MMA_SMEM);
        attr_done = true;
    }

    // weight conversions (independent of activations)
    k_convB<<<dim3(HC / 32, DIN / 32), dim3(32, 32)>>>(W1, Bt1, DIN, HC);
    k_convB<<<dim3(HC / 32, HC / 32), dim3(32, 32)>>>(W2, Bt2, HC, HC);
    k_convB<<<dim3(DOUT / 32, HC / 32), dim3(32, 32)>>>(Wf, BtF, HC, DOUT);

    // graph structure (CSR by dst)
    k_zero_deg<<<(NN + 255) / 256, 256>>>();
    k_count<<<(NE + 255) / 256, 256>>>(dst);
    k_scan<<<1, 1024>>>();
    k_fill<<<(NE + 255) / 256, 256>>>(dst);

    // ---- layer 1:  xw = x @ W1  (HMMA split-bf16) ----
    k_convA<<<(MPAD * DIN + 255) / 256, 256>>>(x, Asp, NN, DIN);
    k_mma_gemm<false><<<dim3(MPAD / 128, HC / 256), 512, MMA_SMEM>>>(
        Asp, Bt1, nullptr, xw, NN, 3 * DIN, HC);
    k_al<<<NN, 128>>>(xw, asrc1, adst1);
    k_V<<<1, 256>>>(We1, aedge1);
    k_zero_esum<<<(NN * H_ + 255) / 256, 256>>>();
    k_edge_al<<<(NE + 255) / 256, 256>>>(ef, dst);
    k_alpha<<<(NE + 255) / 256, 256>>>(src, dst);
    k_aself<<<(NN + 255) / 256, 256>>>();
    k_aggregate<<<NN, 256>>>(xw, src, b1, hbuf, 1);

    // ---- layer 2:  xw = h1 @ W2 ----
    k_convA<<<(MPAD * HC + 255) / 256, 256>>>(hbuf, Asp, NN, HC);
    k_mma_gemm<false><<<dim3(MPAD / 128, HC / 256), 512, MMA_SMEM>>>(
        Asp, Bt2, nullptr, xw, NN, KSF, HC);
    k_al<<<NN, 128>>>(xw, asrc2, adst2);
    k_V<<<1, 256>>>(We2, aedge2);
    k_zero_esum<<<(NN * H_ + 255) / 256, 256>>>();
    k_edge_al<<<(NE + 255) / 256, 256>>>(ef, dst);
    k_alpha<<<(NE + 255) / 256, 256>>>(src, dst);
    k_aself<<<(NN + 255) / 256, 256>>>();
    k_aggregate<<<NN, 256>>>(xw, src, b2, hbuf, 1);

    // ---- final linear: out = h2 @ Wf + bf ----
    k_convA<<<(MPAD * HC + 255) / 256, 256>>>(hbuf, Asp, NN, HC);
    k_mma_gemm<true><<<dim3(MPAD / 128, DOUT / 256), 512, MMA_SMEM>>>(
        Asp, BtF, bf, out, NN, KSF, DOUT);
}

// round 7
// speedup vs baseline: 3.8833x; 1.4821x over previous
#include <cuda_runtime.h>
#include <cuda_bf16.h>
#include <math.h>
#include <stdint.h>

// Problem constants (fixed shapes per metadata)
constexpr int NN   = 10000;   // nodes
constexpr int NE   = 160000;  // edges
constexpr int DIN  = 128;     // input feature dim
constexpr int EDIM = 16;      // edge feature dim
constexpr int H_   = 4;       // heads
constexpr int C_   = 256;     // channels per head
constexpr int HC   = 1024;    // H*C
constexpr int DOUT = 25088;   // final output dim

constexpr int MPAD = 10112;   // 79 * 128 (M padded)

// ---------------- scratch (static device globals: allocation-free) ----------
__device__ float g_xw[NN * HC];
__device__ float g_h[NN * HC];
__device__ float g_al_src[NN * H_];
__device__ float g_al_dst[NN * H_];
__device__ float g_al_e[NE * H_];
__device__ float g_al_esum[NN * H_];
__device__ float g_alpha[NE * H_];
__device__ float g_aself[NN * H_];
__device__ float g_V[EDIM * H_];
__device__ int   g_deg[NN];
__device__ int   g_rowptr[NN + 1];
__device__ int   g_cursor[NN];
__device__ int   g_esorted[NE];
__device__ float g_Asp[(size_t)MPAD * HC];     // A rounded to tf32, M-padded
__device__ float g_BtF[(size_t)DOUT * HC];     // Wf^T tf32 [25088,1024]
__device__ float g_Bt2[(size_t)HC * HC];       // W2^T tf32 [1024,1024]
__device__ float g_Bt1[(size_t)HC * DIN];      // W1^T tf32 [1024,128]

// ---------------- graph structure kernels ----------------------------------
__global__ void k_zero_deg() {
    int i = blockIdx.x * blockDim.x + threadIdx.x;
    if (i < NN) g_deg[i] = 0;
}

__global__ void k_zero_esum() {
    int i = blockIdx.x * blockDim.x + threadIdx.x;
    if (i < NN * H_) g_al_esum[i] = 0.f;
}

__global__ void k_count(const int* __restrict__ dst) {
    int e = blockIdx.x * blockDim.x + threadIdx.x;
    if (e < NE) atomicAdd(&g_deg[dst[e]], 1);
}

__global__ void k_scan() {
    __shared__ int sh[1024];
    __shared__ int carry;
    int t = threadIdx.x;
    if (t == 0) carry = 0;
    __syncthreads();
    for (int base = 0; base < NN; base += 1024) {
        int i = base + t;
        int v = (i < NN) ? g_deg[i] : 0;
        sh[t] = v;
        __syncthreads();
        for (int off = 1; off < 1024; off <<= 1) {
            int xv = (t >= off) ? sh[t - off] : 0;
            __syncthreads();
            if (t >= off) sh[t] += xv;
            __syncthreads();
        }
        int excl = sh[t] - v + carry;
        if (i < NN) { g_rowptr[i] = excl; g_cursor[i] = excl; }
        int tot = sh[1023];
        __syncthreads();
        if (t == 0) carry += tot;
        __syncthreads();
    }
    if (t == 0) g_rowptr[NN] = carry;
}

__global__ void k_fill(const int* __restrict__ dst) {
    int e = blockIdx.x * blockDim.x + threadIdx.x;
    if (e < NE) {
        int p = atomicAdd(&g_cursor[dst[e]], 1);
        g_esorted[p] = e;
    }
}

// ---------------- attention logit pieces ------------------------------------
__global__ void k_al(const float* __restrict__ xw,
                     const float* __restrict__ asrc, const float* __restrict__ adst) {
    int n = blockIdx.x;
    int w = threadIdx.x >> 5, l = threadIdx.x & 31;
    const float* row = xw + (size_t)n * HC + w * C_;
    const float* as  = asrc + w * C_;
    const float* ad  = adst + w * C_;
    float s = 0.f, d = 0.f;
    for (int c = l; c < C_; c += 32) {
        float v = row[c];
        s += v * as[c];
        d += v * ad[c];
    }
#pragma unroll
    for (int off = 16; off; off >>= 1) {
        s += __shfl_xor_sync(0xffffffffu, s, off);
        d += __shfl_xor_sync(0xffffffffu, d, off);
    }
    if (l == 0) { g_al_src[n * H_ + w] = s; g_al_dst[n * H_ + w] = d; }
}

__global__ void k_V(const float* __restrict__ We, const float* __restrict__ aedge) {
    int w = threadIdx.x >> 5, l = threadIdx.x & 31;
    for (int o = w; o < EDIM * H_; o += 8) {
        int d = o / H_, h = o % H_;
        float s = 0.f;
        for (int c = l; c < C_; c += 32)
            s += We[(size_t)d * HC + h * C_ + c] * aedge[h * C_ + c];
#pragma unroll
        for (int off = 16; off; off >>= 1) s += __shfl_xor_sync(0xffffffffu, s, off);
        if (l == 0) g_V[o] = s;
    }
}

__global__ void k_edge_al(const float* __restrict__ ef, const int* __restrict__ dst) {
    int e = blockIdx.x * blockDim.x + threadIdx.x;
    if (e >= NE) return;
    float ea[EDIM];
#pragma unroll
    for (int d = 0; d < EDIM; d++) ea[d] = ef[(size_t)e * EDIM + d];
    int dn = dst[e];
#pragma unroll
    for (int h = 0; h < H_; h++) {
        float s = 0.f;
#pragma unroll
        for (int d = 0; d < EDIM; d++) s += ea[d] * g_V[d * H_ + h];
        g_al_e[e * H_ + h] = s;
        atomicAdd(&g_al_esum[dn * H_ + h], s);
    }
}

__global__ void k_alpha(const int* __restrict__ src, const int* __restrict__ dst) {
    int e = blockIdx.x * blockDim.x + threadIdx.x;
    if (e >= NE) return;
    int sn = src[e], dn = dst[e];
#pragma unroll
    for (int h = 0; h < H_; h++) {
        float v = g_al_src[sn * H_ + h] + g_al_dst[dn * H_ + h] + g_al_e[e * H_ + h];
        g_alpha[e * H_ + h] = v > 0.f ? v : 0.2f * v;
    }
}

__global__ void k_aself() {
    int n = blockIdx.x * blockDim.x + threadIdx.x;
    if (n >= NN) return;
    float invd = 1.0f / fmaxf((float)g_deg[n], 1.0f);
#pragma unroll
    for (int h = 0; h < H_; h++) {
        float v = g_al_src[n * H_ + h] + g_al_dst[n * H_ + h] + g_al_esum[n * H_ + h] * invd;
        g_aself[n * H_ + h] = v > 0.f ? v : 0.2f * v;
    }
}

// ---------------- segment softmax + aggregation (1 block / node) ------------
__global__ void __launch_bounds__(256)
k_aggregate(const float* __restrict__ xw, const int* __restrict__ src,
            const float* __restrict__ bias, float* __restrict__ out, int do_elu) {
    int n = blockIdx.x;
    int beg = g_rowptr[n], end = g_rowptr[n + 1];
    __shared__ float sm[H_], ss[H_];
    int t = threadIdx.x, w = t >> 5, l = t & 31;

    if (w < H_) {
        float mx = g_aself[n * H_ + w];
        for (int i = beg + l; i < end; i += 32)
            mx = fmaxf(mx, g_alpha[g_esorted[i] * H_ + w]);
#pragma unroll
        for (int off = 16; off; off >>= 1)
            mx = fmaxf(mx, __shfl_xor_sync(0xffffffffu, mx, off));
        if (l == 0) sm[w] = mx;
    }
    __syncthreads();

    if (w < H_) {
        float mm = sm[w];
        float acc = (l == 0) ? expf(g_aself[n * H_ + w] - mm) : 0.f;
        for (int i = beg + l; i < end; i += 32) {
            int e = g_esorted[i];
            float ex = expf(g_alpha[e * H_ + w] - mm);
            g_alpha[e * H_ + w] = ex;
            acc += ex;
        }
#pragma unroll
        for (int off = 16; off; off >>= 1) acc += __shfl_xor_sync(0xffffffffu, acc, off);
        if (l == 0) ss[w] = acc;
    }
    __syncthreads();

    float inv[H_];
#pragma unroll
    for (int h = 0; h < H_; h++) inv[h] = 1.0f / (ss[h] + 1e-16f);
    float acc[H_] = {0.f, 0.f, 0.f, 0.f};
    for (int i = beg; i < end; i++) {
        int e = g_esorted[i];
        int sn = src[e];
        const float* row = xw + (size_t)sn * HC;
#pragma unroll
        for (int h = 0; h < H_; h++) {
            float wg = g_alpha[e * H_ + h] * inv[h];
            acc[h] += wg * row[h * C_ + t];
        }
    }
    const float* srow = xw + (size_t)n * HC;
#pragma unroll
    for (int h = 0; h < H_; h++) {
        float wg = expf(g_aself[n * H_ + h] - sm[h]) * inv[h];
        acc[h] += wg * srow[h * C_ + t];
    }
#pragma unroll
    for (int h = 0; h < H_; h++) {
        float v = acc[h] + bias[h * C_ + t];
        if (do_elu) v = v > 0.f ? v : expm1f(v);
        out[(size_t)n * HC + h * C_ + t] = v;
    }
}

// ---------------- tf32 conversions ------------------------------------------
__device__ __forceinline__ float f2tf32(float f) {
    uint32_t r;
    asm("cvt.rna.tf32.f32 %0, %1;" : "=r"(r) : "f"(f));
    return __uint_as_float(r);
}

// A rounded to tf32; rows >= Mv zero-padded.
__global__ void k_convA(const float* __restrict__ src, float* __restrict__ dst,
                        int Mv, int K) {
    int i = blockIdx.x * blockDim.x + threadIdx.x;
    if (i >= MPAD * K) return;
    int m = i / K, k = i - m * K;
    float a = (m < Mv) ? src[(size_t)m * K + k] : 0.f;
    dst[(size_t)m * K + k] = f2tf32(a);
}

// B' = transpose(W[K,N]) rounded to tf32, stored [N,K].
__global__ void k_convB(const float* __restrict__ W, float* __restrict__ dst,
                        int K, int Nn) {
    __shared__ float t[32][33];
    int n = blockIdx.x * 32 + threadIdx.x;
    int k = blockIdx.y * 32 + threadIdx.y;
    t[threadIdx.y][threadIdx.x] = W[(size_t)k * Nn + n];
    __syncthreads();
    int n2 = blockIdx.x * 32 + threadIdx.y;
    int k2 = blockIdx.y * 32 + threadIdx.x;
    dst[(size_t)n2 * K + k2] = f2tf32(t[threadIdx.x][threadIdx.y]);
}

// ---------------- TF32 tensor-core GEMM --------------------------------------
// out[m,n] (+bias[n]) = A[m,K] . B[n,K]   (A,B pre-rounded tf32; fp32 accum)
// CTA tile 128x256, 512 threads (16 warps, warp tile 32x64), BK=32 fp32,
// 4-stage cp.async pipeline (192 KB smem).

__device__ __forceinline__ uint32_t s2u(const void* p) {
    uint32_t a;
    asm("{ .reg .u64 t; cvta.to.shared.u64 t, %1; cvt.u32.u64 %0, t; }" : "=r"(a) : "l"(p));
    return a;
}

__device__ __forceinline__ void cp16(uint32_t saddr, const void* gptr) {
    asm volatile("cp.async.cg.shared.global [%0], [%1], 16;" :: "r"(saddr), "l"(gptr));
}

#define LDSM4(r, addr) \
    asm volatile("ldmatrix.sync.aligned.m8n8.x4.shared.b16 {%0,%1,%2,%3}, [%4];" \
        : "=r"((r)[0]), "=r"((r)[1]), "=r"((r)[2]), "=r"((r)[3]) : "r"(addr))

#define MMATF32(c, a, b0, b1) \
    asm volatile("mma.sync.aligned.m16n8k8.row.col.f32.tf32.tf32.f32 " \
        "{%0,%1,%2,%3}, {%4,%5,%6,%7}, {%8,%9}, {%0,%1,%2,%3};" \
        : "+f"((c)[0]), "+f"((c)[1]), "+f"((c)[2]), "+f"((c)[3]) \
        : "r"((a)[0]), "r"((a)[1]), "r"((a)[2]), "r"((a)[3]), "r"(b0), "r"(b1))

constexpr int STAGE_BYTES = 49152;              // A 16KB + B 32KB (fp32, BK=32)
constexpr int MMA_SMEM    = 4 * STAGE_BYTES;    // 192 KB

template <bool BIAS>
__global__ void __launch_bounds__(512, 1)
k_mma_gemm(const float* __restrict__ A, const float* __restrict__ B,
           const float* __restrict__ bias, float* __restrict__ out,
           int Mv, int K, int ldo) {
    extern __shared__ char smem[];
    const uint32_t sb = s2u(smem);
    const int tid  = threadIdx.x;
    const int lane = tid & 31, wid = tid >> 5;
    const int wm = (wid & 3) * 32, wn = (wid >> 2) * 64;
    const int bm = blockIdx.x * 128, bn = blockIdx.y * 256;
    const int KITER = K >> 5;

    const float* ag0 = A + (size_t)bm * K;
    const float* bg0 = B + (size_t)bn * K;

    // rows of 128B (32 fp32), 8 x 16B segments; phys seg = seg ^ (row & 7)
    auto load_stage = [&](int kt, int slot) {
        const int k0 = kt * 32;
        const uint32_t sa  = sb + slot * STAGE_BYTES;
        const uint32_t sbm = sa + 16384;
#pragma unroll
        for (int i = 0; i < 2; i++) {      // A: 128 rows x 8 segs = 1024
            int u = tid + i * 512;
            int row = u >> 3, seg = u & 7;
            uint32_t off = row * 128 + ((seg ^ (row & 7)) << 4);
            cp16(sa + off, ag0 + (size_t)row * K + k0 + seg * 4);
        }
#pragma unroll
        for (int i = 0; i < 4; i++) {      // B: 256 rows x 8 segs = 2048
            int u = tid + i * 512;
            int row = u >> 3, seg = u & 7;
            uint32_t off = row * 128 + ((seg ^ (row & 7)) << 4);
            cp16(sbm + off, bg0 + (size_t)row * K + k0 + seg * 4);
        }
    };

    float acc[2][8][4];
#pragma unroll
    for (int i = 0; i < 2; i++)
#pragma unroll
        for (int j = 0; j < 8; j++)
#pragma unroll
            for (int r = 0; r < 4; r++) acc[i][j][r] = 0.f;

    load_stage(0, 0);
    asm volatile("cp.async.commit_group;" ::: "memory");
    load_stage(1, 1);
    asm volatile("cp.async.commit_group;" ::: "memory");
    load_stage(2, 2);
    asm volatile("cp.async.commit_group;" ::: "memory");

    for (int kt = 0; kt < KITER; kt++) {
        asm volatile("cp.async.wait_group 2;" ::: "memory");
        __syncthreads();
        if (kt + 3 < KITER) load_stage(kt + 3, (kt + 3) & 3);
        asm volatile("cp.async.commit_group;" ::: "memory");

        const uint32_t sa  = sb + (kt & 3) * STAGE_BYTES;
        const uint32_t sbm = sa + 16384;
#pragma unroll
        for (int kf = 0; kf < 4; kf++) {
            // seg index for this k8 step: lanes 0-15 -> first 16B, 16-31 -> second
            const int segb = kf * 2 + (lane >> 4);
            uint32_t av[2][4], bv[4][4];
#pragma unroll
            for (int mf = 0; mf < 2; mf++) {
                int row = wm + mf * 16 + (lane & 15);
                LDSM4(av[mf], sa + row * 128 + ((segb ^ (row & 7)) << 4));
            }
#pragma unroll
            for (int p = 0; p < 4; p++) {
                int row = wn + p * 16 + (lane & 15);
                LDSM4(bv[p], sbm + row * 128 + ((segb ^ (row & 7)) << 4));
            }
            // bv[p]: r0/r2 = n-octet (p*16..+7) b0/b1 ; r1/r3 = (+8..15)
#pragma unroll
            for (int mf = 0; mf < 2; mf++)
#pragma unroll
                for (int p = 0; p < 4; p++) {
                    MMATF32(acc[mf][p * 2 + 0], av[mf], bv[p][0], bv[p][2]);
                    MMATF32(acc[mf][p * 2 + 1], av[mf], bv[p][1], bv[p][3]);
                }
        }
    }

    // epilogue
    const int r0 = lane >> 2, c0 = (lane & 3) * 2;
#pragma unroll
    for (int mf = 0; mf < 2; mf++) {
#pragma unroll
        for (int half = 0; half < 2; half++) {
            int m = bm + wm + mf * 16 + r0 + half * 8;
            if (m >= Mv) continue;
            float* orow = out + (size_t)m * ldo;
#pragma unroll
            for (int nf = 0; nf < 8; nf++) {
                int n = bn + wn + nf * 8 + c0;
                float2 v;
                v.x = acc[mf][nf][half * 2 + 0];
                v.y = acc[mf][nf][half * 2 + 1];
                if (BIAS) { v.x += __ldg(bias + n); v.y += __ldg(bias + n + 1); }
                *reinterpret_cast<float2*>(orow + n) = v;
            }
        }
    }
}

// ---------------- launch -----------------------------------------------------
extern "C" void kernel_launch(void* const* d_in, const int* in_sizes, int n_in,
                              void* d_out, int out_size) {
    const float* x      = (const float*)d_in[0];
    const int*   ei     = (const int*)d_in[1];
    const float* ef     = (const float*)d_in[2];
    const float* W1     = (const float*)d_in[3];
    const float* asrc1  = (const float*)d_in[4];
    const float* adst1  = (const float*)d_in[5];
    const float* aedge1 = (const float*)d_in[6];
    const float* We1    = (const float*)d_in[7];
    const float* b1     = (const float*)d_in[8];
    const float* W2     = (const float*)d_in[9];
    const float* asrc2  = (const float*)d_in[10];
    const float* adst2  = (const float*)d_in[11];
    const float* aedge2 = (const float*)d_in[12];
    const float* We2    = (const float*)d_in[13];
    const float* b2     = (const float*)d_in[14];
    const float* Wf     = (const float*)d_in[15];
    const float* bf     = (const float*)d_in[16];
    const int* src = ei;
    const int* dst = ei + NE;
    float* out = (float*)d_out;

    void* p;
    cudaGetSymbolAddress(&p, g_xw);  float* xw   = (float*)p;
    cudaGetSymbolAddress(&p, g_h);   float* hbuf = (float*)p;
    cudaGetSymbolAddress(&p, g_Asp); float* Asp = (float*)p;
    cudaGetSymbolAddress(&p, g_BtF); float* BtF = (float*)p;
    cudaGetSymbolAddress(&p, g_Bt2); float* Bt2 = (float*)p;
    cudaGetSymbolAddress(&p, g_Bt1); float* Bt1 = (float*)p;

    static bool attr_done = false;
    if (!attr_done) {
        cudaFuncSetAttribute(k_mma_gemm<true>,  cudaFuncAttributeMaxDynamicSharedMemorySize, MMA_SMEM);
        cudaFuncSetAttribute(k_mma_gemm<false>, cudaFuncAttributeMaxDynamicSharedMemorySize, MMA_SMEM);
        attr_done = true;
    }

    // weight conversions (independent of activations)
    k_convB<<<dim3(HC / 32, DIN / 32), dim3(32, 32)>>>(W1, Bt1, DIN, HC);
    k_convB<<<dim3(HC / 32, HC / 32), dim3(32, 32)>>>(W2, Bt2, HC, HC);
    k_convB<<<dim3(DOUT / 32, HC / 32), dim3(32, 32)>>>(Wf, BtF, HC, DOUT);

    // graph structure (CSR by dst)
    k_zero_deg<<<(NN + 255) / 256, 256>>>();
    k_count<<<(NE + 255) / 256, 256>>>(dst);
    k_scan<<<1, 1024>>>();
    k_fill<<<(NE + 255) / 256, 256>>>(dst);

    // ---- layer 1:  xw = x @ W1  (tf32 MMA) ----
    k_convA<<<(MPAD * DIN + 255) / 256, 256>>>(x, Asp, NN, DIN);
    k_mma_gemm<false><<<dim3(MPAD / 128, HC / 256), 512, MMA_SMEM>>>(
        Asp, Bt1, nullptr, xw, NN, DIN, HC);
    k_al<<<NN, 128>>>(xw, asrc1, adst1);
    k_V<<<1, 256>>>(We1, aedge1);
    k_zero_esum<<<(NN * H_ + 255) / 256, 256>>>();
    k_edge_al<<<(NE + 255) / 256, 256>>>(ef, dst);
    k_alpha<<<(NE + 255) / 256, 256>>>(src, dst);
    k_aself<<<(NN + 255) / 256, 256>>>();
    k_aggregate<<<NN, 256>>>(xw, src, b1, hbuf, 1);

    // ---- layer 2:  xw = h1 @ W2 ----
    k_convA<<<(MPAD * HC + 255) / 256, 256>>>(hbuf, Asp, NN, HC);
    k_mma_gemm<false><<<dim3(MPAD / 128, HC / 256), 512, MMA_SMEM>>>(
        Asp, Bt2, nullptr, xw, NN, HC, HC);
    k_al<<<NN, 128>>>(xw, asrc2, adst2);
    k_V<<<1, 256>>>(We2, aedge2);
    k_zero_esum<<<(NN * H_ + 255) / 256, 256>>>();
    k_edge_al<<<(NE + 255) / 256, 256>>>(ef, dst);
    k_alpha<<<(NE + 255) / 256, 256>>>(src, dst);
    k_aself<<<(NN + 255) / 256, 256>>>();
    k_aggregate<<<NN, 256>>>(xw, src, b2, hbuf, 1);

    // ---- final linear: out = h2 @ Wf + bf ----
    k_convA<<<(MPAD * HC + 255) / 256, 256>>>(hbuf, Asp, NN, HC);
    k_mma_gemm<true><<<dim3(MPAD / 128, DOUT / 256), 512, MMA_SMEM>>>(
        Asp, BtF, bf, out, NN, HC, DOUT);
}

// round 8
// speedup vs baseline: 6.1350x; 1.5798x over previous
#include <cuda_runtime.h>
#include <cuda_fp16.h>
#include <math.h>
#include <stdint.h>

// Problem constants (fixed shapes per metadata)
constexpr int NN   = 10000;   // nodes
constexpr int NE   = 160000;  // edges
constexpr int DIN  = 128;     // input feature dim
constexpr int EDIM = 16;      // edge feature dim
constexpr int H_   = 4;       // heads
constexpr int C_   = 256;     // channels per head
constexpr int HC   = 1024;    // H*C
constexpr int DOUT = 25088;   // final output dim

constexpr int MPAD = 10112;   // 79 * 128 (M padded)

// ---------------- scratch (static device globals: allocation-free) ----------
__device__ float g_xw[NN * HC];
__device__ float g_h[NN * HC];
__device__ float g_al_src[NN * H_];
__device__ float g_al_dst[NN * H_];
__device__ float g_al_e[NE * H_];
__device__ float g_al_esum[NN * H_];
__device__ float g_alpha[NE * H_];
__device__ float g_aself[NN * H_];
__device__ float g_V[EDIM * H_];
__device__ int   g_deg[NN];
__device__ int   g_rowptr[NN + 1];
__device__ int   g_cursor[NN];
__device__ int   g_esorted[NE];
__device__ __half g_Asp[(size_t)MPAD * HC];     // A rounded to fp16, M-padded
__device__ __half g_BtF[(size_t)DOUT * HC];     // Wf^T fp16 [25088,1024]
__device__ __half g_Bt2[(size_t)HC * HC];       // W2^T fp16 [1024,1024]
__device__ __half g_Bt1[(size_t)HC * DIN];      // W1^T fp16 [1024,128]

// ---------------- graph structure kernels ----------------------------------
__global__ void k_zero_deg() {
    int i = blockIdx.x * blockDim.x + threadIdx.x;
    if (i < NN) g_deg[i] = 0;
}

__global__ void k_zero_esum() {
    int i = blockIdx.x * blockDim.x + threadIdx.x;
    if (i < NN * H_) g_al_esum[i] = 0.f;
}

__global__ void k_count(const int* __restrict__ dst) {
    int e = blockIdx.x * blockDim.x + threadIdx.x;
    if (e < NE) atomicAdd(&g_deg[dst[e]], 1);
}

__global__ void k_scan() {
    __shared__ int sh[1024];
    __shared__ int carry;
    int t = threadIdx.x;
    if (t == 0) carry = 0;
    __syncthreads();
    for (int base = 0; base < NN; base += 1024) {
        int i = base + t;
        int v = (i < NN) ? g_deg[i] : 0;
        sh[t] = v;
        __syncthreads();
        for (int off = 1; off < 1024; off <<= 1) {
            int xv = (t >= off) ? sh[t - off] : 0;
            __syncthreads();
            if (t >= off) sh[t] += xv;
            __syncthreads();
        }
        int excl = sh[t] - v + carry;
        if (i < NN) { g_rowptr[i] = excl; g_cursor[i] = excl; }
        int tot = sh[1023];
        __syncthreads();
        if (t == 0) carry += tot;
        __syncthreads();
    }
    if (t == 0) g_rowptr[NN] = carry;
}

__global__ void k_fill(const int* __restrict__ dst) {
    int e = blockIdx.x * blockDim.x + threadIdx.x;
    if (e < NE) {
        int p = atomicAdd(&g_cursor[dst[e]], 1);
        g_esorted[p] = e;
    }
}

// ---------------- attention logit pieces ------------------------------------
__global__ void k_al(const float* __restrict__ xw,
                     const float* __restrict__ asrc, const float* __restrict__ adst) {
    int n = blockIdx.x;
    int w = threadIdx.x >> 5, l = threadIdx.x & 31;
    const float* row = xw + (size_t)n * HC + w * C_;
    const float* as  = asrc + w * C_;
    const float* ad  = adst + w * C_;
    float s = 0.f, d = 0.f;
    for (int c = l; c < C_; c += 32) {
        float v = row[c];
        s += v * as[c];
        d += v * ad[c];
    }
#pragma unroll
    for (int off = 16; off; off >>= 1) {
        s += __shfl_xor_sync(0xffffffffu, s, off);
        d += __shfl_xor_sync(0xffffffffu, d, off);
    }
    if (l == 0) { g_al_src[n * H_ + w] = s; g_al_dst[n * H_ + w] = d; }
}

__global__ void k_V(const float* __restrict__ We, const float* __restrict__ aedge) {
    int w = threadIdx.x >> 5, l = threadIdx.x & 31;
    for (int o = w; o < EDIM * H_; o += 8) {
        int d = o / H_, h = o % H_;
        float s = 0.f;
        for (int c = l; c < C_; c += 32)
            s += We[(size_t)d * HC + h * C_ + c] * aedge[h * C_ + c];
#pragma unroll
        for (int off = 16; off; off >>= 1) s += __shfl_xor_sync(0xffffffffu, s, off);
        if (l == 0) g_V[o] = s;
    }
}

__global__ void k_edge_al(const float* __restrict__ ef, const int* __restrict__ dst) {
    int e = blockIdx.x * blockDim.x + threadIdx.x;
    if (e >= NE) return;
    float ea[EDIM];
#pragma unroll
    for (int d = 0; d < EDIM; d++) ea[d] = ef[(size_t)e * EDIM + d];
    int dn = dst[e];
#pragma unroll
    for (int h = 0; h < H_; h++) {
        float s = 0.f;
#pragma unroll
        for (int d = 0; d < EDIM; d++) s += ea[d] * g_V[d * H_ + h];
        g_al_e[e * H_ + h] = s;
        atomicAdd(&g_al_esum[dn * H_ + h], s);
    }
}

__global__ void k_alpha(const int* __restrict__ src, const int* __restrict__ dst) {
    int e = blockIdx.x * blockDim.x + threadIdx.x;
    if (e >= NE) return;
    int sn = src[e], dn = dst[e];
#pragma unroll
    for (int h = 0; h < H_; h++) {
        float v = g_al_src[sn * H_ + h] + g_al_dst[dn * H_ + h] + g_al_e[e * H_ + h];
        g_alpha[e * H_ + h] = v > 0.f ? v : 0.2f * v;
    }
}

__global__ void k_aself() {
    int n = blockIdx.x * blockDim.x + threadIdx.x;
    if (n >= NN) return;
    float invd = 1.0f / fmaxf((float)g_deg[n], 1.0f);
#pragma unroll
    for (int h = 0; h < H_; h++) {
        float v = g_al_src[n * H_ + h] + g_al_dst[n * H_ + h] + g_al_esum[n * H_ + h] * invd;
        g_aself[n * H_ + h] = v > 0.f ? v : 0.2f * v;
    }
}

// ---------------- segment softmax + aggregation (1 block / node) ------------
__global__ void __launch_bounds__(256)
k_aggregate(const float* __restrict__ xw, const int* __restrict__ src,
            const float* __restrict__ bias, float* __restrict__ out, int do_elu) {
    int n = blockIdx.x;
    int beg = g_rowptr[n], end = g_rowptr[n + 1];
    __shared__ float sm[H_], ss[H_];
    int t = threadIdx.x, w = t >> 5, l = t & 31;

    if (w < H_) {
        float mx = g_aself[n * H_ + w];
        for (int i = beg + l; i < end; i += 32)
            mx = fmaxf(mx, g_alpha[g_esorted[i] * H_ + w]);
#pragma unroll
        for (int off = 16; off; off >>= 1)
            mx = fmaxf(mx, __shfl_xor_sync(0xffffffffu, mx, off));
        if (l == 0) sm[w] = mx;
    }
    __syncthreads();

    if (w < H_) {
        float mm = sm[w];
        float acc = (l == 0) ? expf(g_aself[n * H_ + w] - mm) : 0.f;
        for (int i = beg + l; i < end; i += 32) {
            int e = g_esorted[i];
            float ex = expf(g_alpha[e * H_ + w] - mm);
            g_alpha[e * H_ + w] = ex;
            acc += ex;
        }
#pragma unroll
        for (int off = 16; off; off >>= 1) acc += __shfl_xor_sync(0xffffffffu, acc, off);
        if (l == 0) ss[w] = acc;
    }
    __syncthreads();

    float inv[H_];
#pragma unroll
    for (int h = 0; h < H_; h++) inv[h] = 1.0f / (ss[h] + 1e-16f);
    float acc[H_] = {0.f, 0.f, 0.f, 0.f};
    for (int i = beg; i < end; i++) {
        int e = g_esorted[i];
        int sn = src[e];
        const float* row = xw + (size_t)sn * HC;
#pragma unroll
        for (int h = 0; h < H_; h++) {
            float wg = g_alpha[e * H_ + h] * inv[h];
            acc[h] += wg * row[h * C_ + t];
        }
    }
    const float* srow = xw + (size_t)n * HC;
#pragma unroll
    for (int h = 0; h < H_; h++) {
        float wg = expf(g_aself[n * H_ + h] - sm[h]) * inv[h];
        acc[h] += wg * srow[h * C_ + t];
    }
#pragma unroll
    for (int h = 0; h < H_; h++) {
        float v = acc[h] + bias[h * C_ + t];
        if (do_elu) v = v > 0.f ? v : expm1f(v);
        out[(size_t)n * HC + h * C_ + t] = v;
    }
}

// ---------------- fp16 conversions ------------------------------------------
// A rounded to fp16; rows >= Mv zero-padded.
__global__ void k_convA(const float* __restrict__ src, __half* __restrict__ dst,
                        int Mv, int K) {
    int i = blockIdx.x * blockDim.x + threadIdx.x;
    if (i >= MPAD * K) return;
    int m = i / K, k = i - m * K;
    float a = (m < Mv) ? src[(size_t)m * K + k] : 0.f;
    dst[(size_t)m * K + k] = __float2half(a);
}

// B' = transpose(W[K,N]) rounded to fp16, stored [N,K].
__global__ void k_convB(const float* __restrict__ W, __half* __restrict__ dst,
                        int K, int Nn) {
    __shared__ float t[32][33];
    int n = blockIdx.x * 32 + threadIdx.x;
    int k = blockIdx.y * 32 + threadIdx.y;
    t[threadIdx.y][threadIdx.x] = W[(size_t)k * Nn + n];
    __syncthreads();
    int n2 = blockIdx.x * 32 + threadIdx.y;
    int k2 = blockIdx.y * 32 + threadIdx.x;
    dst[(size_t)n2 * K + k2] = __float2half(t[threadIdx.x][threadIdx.y]);
}

// ---------------- fp16 HMMA GEMM --------------------------------------------
// out[m,n] (+bias[n]) = A[m,K] . B[n,K]   (fp16 operands, fp32 accumulate)
// CTA tile 128x256, 512 threads (16 warps, warp tile 32x64), BK=32,
// 4-stage cp.async pipeline (96 KB smem).

__device__ __forceinline__ uint32_t s2u(const void* p) {
    uint32_t a;
    asm("{ .reg .u64 t; cvta.to.shared.u64 t, %1; cvt.u32.u64 %0, t; }" : "=r"(a) : "l"(p));
    return a;
}

__device__ __forceinline__ void cp16(uint32_t saddr, const void* gptr) {
    asm volatile("cp.async.cg.shared.global [%0], [%1], 16;" :: "r"(saddr), "l"(gptr));
}

#define LDSM4(r, addr) \
    asm volatile("ldmatrix.sync.aligned.m8n8.x4.shared.b16 {%0,%1,%2,%3}, [%4];" \
        : "=r"((r)[0]), "=r"((r)[1]), "=r"((r)[2]), "=r"((r)[3]) : "r"(addr))

#define MMA16816(c, a, b0, b1) \
    asm volatile("mma.sync.aligned.m16n8k16.row.col.f32.f16.f16.f32 " \
        "{%0,%1,%2,%3}, {%4,%5,%6,%7}, {%8,%9}, {%0,%1,%2,%3};" \
        : "+f"((c)[0]), "+f"((c)[1]), "+f"((c)[2]), "+f"((c)[3]) \
        : "r"((a)[0]), "r"((a)[1]), "r"((a)[2]), "r"((a)[3]), "r"(b0), "r"(b1))

constexpr int STAGE_BYTES = 24576;              // A 8KB + B 16KB
constexpr int MMA_SMEM    = 4 * STAGE_BYTES;    // 96 KB

template <bool BIAS>
__global__ void __launch_bounds__(512, 1)
k_mma_gemm(const __half* __restrict__ A, const __half* __restrict__ B,
           const float* __restrict__ bias, float* __restrict__ out,
           int Mv, int K, int ldo) {
    extern __shared__ char smem[];
    const uint32_t sb = s2u(smem);
    const int tid  = threadIdx.x;
    const int lane = tid & 31, wid = tid >> 5;
    const int wm = (wid & 3) * 32, wn = (wid >> 2) * 64;
    const int bm = blockIdx.x * 128, bn = blockIdx.y * 256;
    const int KITER = K >> 5;

    const __half* ag0 = A + (size_t)bm * K;
    const __half* bg0 = B + (size_t)bn * K;

    // swizzle: 16B segment s of row r -> phys seg (s ^ ((r>>1)&3))
    auto load_stage = [&](int kt, int slot) {
        const int k0 = kt * 32;
        const uint32_t sa  = sb + slot * STAGE_BYTES;
        const uint32_t sbm = sa + 8192;
        {                                  // A: 128 rows x 4 segs = 512
            int row = tid >> 2, seg = tid & 3;
            uint32_t off = row * 64 + ((seg ^ ((row >> 1) & 3)) << 4);
            cp16(sa + off, ag0 + (size_t)row * K + k0 + seg * 8);
        }
#pragma unroll
        for (int i = 0; i < 2; i++) {      // B: 256 rows x 4 segs = 1024
            int u = tid + i * 512;
            int row = u >> 2, seg = u & 3;
            uint32_t off = row * 64 + ((seg ^ ((row >> 1) & 3)) << 4);
            cp16(sbm + off, bg0 + (size_t)row * K + k0 + seg * 8);
        }
    };

    float acc[2][8][4];
#pragma unroll
    for (int i = 0; i < 2; i++)
#pragma unroll
        for (int j = 0; j < 8; j++)
#pragma unroll
            for (int r = 0; r < 4; r++) acc[i][j][r] = 0.f;

    load_stage(0, 0);
    asm volatile("cp.async.commit_group;" ::: "memory");
    load_stage(1, 1);
    asm volatile("cp.async.commit_group;" ::: "memory");
    load_stage(2, 2);
    asm volatile("cp.async.commit_group;" ::: "memory");

    for (int kt = 0; kt < KITER; kt++) {
        asm volatile("cp.async.wait_group 2;" ::: "memory");
        __syncthreads();
        if (kt + 3 < KITER) load_stage(kt + 3, (kt + 3) & 3);
        asm volatile("cp.async.commit_group;" ::: "memory");

        const uint32_t sa  = sb + (kt & 3) * STAGE_BYTES;
        const uint32_t sbm = sa + 8192;
#pragma unroll
        for (int ks2 = 0; ks2 < 2; ks2++) {
            uint32_t av[2][4], bv[4][4];
            const int segk = ks2 * 2 + (lane >> 4);
#pragma unroll
            for (int mf = 0; mf < 2; mf++) {
                int row = wm + mf * 16 + (lane & 15);
                LDSM4(av[mf], sa + row * 64 + ((segk ^ ((row >> 1) & 3)) << 4));
            }
#pragma unroll
            for (int p = 0; p < 4; p++) {
                int row = wn + p * 16 + (lane & 15);
                LDSM4(bv[p], sbm + row * 64 + ((segk ^ ((row >> 1) & 3)) << 4));
            }
#pragma unroll
            for (int mf = 0; mf < 2; mf++)
#pragma unroll
                for (int p = 0; p < 4; p++) {
                    MMA16816(acc[mf][p * 2 + 0], av[mf], bv[p][0], bv[p][2]);
                    MMA16816(acc[mf][p * 2 + 1], av[mf], bv[p][1], bv[p][3]);
                }
        }
    }

    // epilogue
    const int r0 = lane >> 2, c0 = (lane & 3) * 2;
#pragma unroll
    for (int mf = 0; mf < 2; mf++) {
#pragma unroll
        for (int half = 0; half < 2; half++) {
            int m = bm + wm + mf * 16 + r0 + half * 8;
            if (m >= Mv) continue;
            float* orow = out + (size_t)m * ldo;
#pragma unroll
            for (int nf = 0; nf < 8; nf++) {
                int n = bn + wn + nf * 8 + c0;
                float2 v;
                v.x = acc[mf][nf][half * 2 + 0];
                v.y = acc[mf][nf][half * 2 + 1];
                if (BIAS) { v.x += __ldg(bias + n); v.y += __ldg(bias + n + 1); }
                *reinterpret_cast<float2*>(orow + n) = v;
            }
        }
    }
}

// ---------------- launch -----------------------------------------------------
extern "C" void kernel_launch(void* const* d_in, const int* in_sizes, int n_in,
                              void* d_out, int out_size) {
    const float* x      = (const float*)d_in[0];
    const int*   ei     = (const int*)d_in[1];
    const float* ef     = (const float*)d_in[2];
    const float* W1     = (const float*)d_in[3];
    const float* asrc1  = (const float*)d_in[4];
    const float* adst1  = (const float*)d_in[5];
    const float* aedge1 = (const float*)d_in[6];
    const float* We1    = (const float*)d_in[7];
    const float* b1     = (const float*)d_in[8];
    const float* W2     = (const float*)d_in[9];
    const float* asrc2  = (const float*)d_in[10];
    const float* adst2  = (const float*)d_in[11];
    const float* aedge2 = (const float*)d_in[12];
    const float* We2    = (const float*)d_in[13];
    const float* b2     = (const float*)d_in[14];
    const float* Wf     = (const float*)d_in[15];
    const float* bf     = (const float*)d_in[16];
    const int* src = ei;
    const int* dst = ei + NE;
    float* out = (float*)d_out;

    void* p;
    cudaGetSymbolAddress(&p, g_xw);  float* xw   = (float*)p;
    cudaGetSymbolAddress(&p, g_h);   float* hbuf = (float*)p;
    cudaGetSymbolAddress(&p, g_Asp); __half* Asp = (__half*)p;
    cudaGetSymbolAddress(&p, g_BtF); __half* BtF = (__half*)p;
    cudaGetSymbolAddress(&p, g_Bt2); __half* Bt2 = (__half*)p;
    cudaGetSymbolAddress(&p, g_Bt1); __half* Bt1 = (__half*)p;

    static bool attr_done = false;
    if (!attr_done) {
        cudaFuncSetAttribute(k_mma_gemm<true>,  cudaFuncAttributeMaxDynamicSharedMemorySize, MMA_SMEM);
        cudaFuncSetAttribute(k_mma_gemm<false>, cudaFuncAttributeMaxDynamicSharedMemorySize, MMA_SMEM);
        attr_done = true;
    }

    // weight conversions (independent of activations)
    k_convB<<<dim3(HC / 32, DIN / 32), dim3(32, 32)>>>(W1, Bt1, DIN, HC);
    k_convB<<<dim3(HC / 32, HC / 32), dim3(32, 32)>>>(W2, Bt2, HC, HC);
    k_convB<<<dim3(DOUT / 32, HC / 32), dim3(32, 32)>>>(Wf, BtF, HC, DOUT);

    // graph structure (CSR by dst)
    k_zero_deg<<<(NN + 255) / 256, 256>>>();
    k_count<<<(NE + 255) / 256, 256>>>(dst);
    k_scan<<<1, 1024>>>();
    k_fill<<<(NE + 255) / 256, 256>>>(dst);

    // ---- layer 1:  xw = x @ W1  (fp16 HMMA) ----
    k_convA<<<(MPAD * DIN + 255) / 256, 256>>>(x, Asp, NN, DIN);
    k_mma_gemm<false><<<dim3(MPAD / 128, HC / 256), 512, MMA_SMEM>>>(
        Asp, Bt1, nullptr, xw, NN, DIN, HC);
    k_al<<<NN, 128>>>(xw, asrc1, adst1);
    k_V<<<1, 256>>>(We1, aedge1);
    k_zero_esum<<<(NN * H_ + 255) / 256, 256>>>();
    k_edge_al<<<(NE + 255) / 256, 256>>>(ef, dst);
    k_alpha<<<(NE + 255) / 256, 256>>>(src, dst);
    k_aself<<<(NN + 255) / 256, 256>>>();
    k_aggregate<<<NN, 256>>>(xw, src, b1, hbuf, 1);

    // ---- layer 2:  xw = h1 @ W2 ----
    k_convA<<<(MPAD * HC + 255) / 256, 256>>>(hbuf, Asp, NN, HC);
    k_mma_gemm<false><<<dim3(MPAD / 128, HC / 256), 512, MMA_SMEM>>>(
        Asp, Bt2, nullptr, xw, NN, HC, HC);
    k_al<<<NN, 128>>>(xw, asrc2, adst2);
    k_V<<<1, 256>>>(We2, aedge2);
    k_zero_esum<<<(NN * H_ + 255) / 256, 256>>>();
    k_edge_al<<<(NE + 255) / 256, 256>>>(ef, dst);
    k_alpha<<<(NE + 255) / 256, 256>>>(src, dst);
    k_aself<<<(NN + 255) / 256, 256>>>();
    k_aggregate<<<NN, 256>>>(xw, src, b2, hbuf, 1);

    // ---- final linear: out = h2 @ Wf + bf ----
    k_convA<<<(MPAD * HC + 255) / 256, 256>>>(hbuf, Asp, NN, HC);
    k_mma_gemm<true><<<dim3(MPAD / 128, DOUT / 256), 512, MMA_SMEM>>>(
        Asp, BtF, bf, out, NN, HC, DOUT);
}

// round 9
// speedup vs baseline: 6.4958x; 1.0588x over previous
#include <cuda_runtime.h>
#include <cuda_fp16.h>
#include <math.h>
#include <stdint.h>

// Problem constants (fixed shapes per metadata)
constexpr int NN   = 10000;   // nodes
constexpr int NE   = 160000;  // edges
constexpr int DIN  = 128;     // input feature dim
constexpr int EDIM = 16;      // edge feature dim
constexpr int H_   = 4;       // heads
constexpr int C_   = 256;     // channels per head
constexpr int HC   = 1024;    // H*C
constexpr int DOUT = 25088;   // final output dim

constexpr int MPAD = 10112;   // 79 * 128 (M padded)

// ---------------- scratch (static device globals: allocation-free) ----------
__device__ float  g_xw[NN * HC];          // layer GEMM output fp32 (for k_al)
__device__ __half g_xw2[NN * HC];         // fp16 copy (gather source)
__device__ float  g_al_src[NN * H_];
__device__ float  g_al_dst[NN * H_];
__device__ float  g_al_esum[NN * H_];
__device__ float  g_alpha_s[(size_t)H_ * NE];  // SoA [H][NE], CSR-sorted
__device__ float  g_aself[NN * H_];
__device__ float  g_V[EDIM * H_];
__device__ int    g_deg[NN];
__device__ int    g_rowptr[NN + 1];
__device__ int    g_cursor[NN];
__device__ int    g_esorted[NE];
__device__ int    g_src_s[NE];            // src node per sorted position
__device__ __half g_Asp[(size_t)MPAD * HC];     // GEMM A operand (fp16)
__device__ __half g_BtF[(size_t)DOUT * HC];     // Wf^T fp16 [25088,1024]
__device__ __half g_Bt2[(size_t)HC * HC];       // W2^T fp16 [1024,1024]
__device__ __half g_Bt1[(size_t)HC * DIN];      // W1^T fp16 [1024,128]

// ---------------- graph structure kernels ----------------------------------
__global__ void k_zero_deg() {
    int i = blockIdx.x * blockDim.x + threadIdx.x;
    if (i < NN) g_deg[i] = 0;
}

__global__ void k_zero_esum() {
    int i = blockIdx.x * blockDim.x + threadIdx.x;
    if (i < NN * H_) g_al_esum[i] = 0.f;
}

__global__ void k_count(const int* __restrict__ dst) {
    int e = blockIdx.x * blockDim.x + threadIdx.x;
    if (e < NE) atomicAdd(&g_deg[dst[e]], 1);
}

__global__ void k_scan() {
    __shared__ int sh[1024];
    __shared__ int carry;
    int t = threadIdx.x;
    if (t == 0) carry = 0;
    __syncthreads();
    for (int base = 0; base < NN; base += 1024) {
        int i = base + t;
        int v = (i < NN) ? g_deg[i] : 0;
        sh[t] = v;
        __syncthreads();
        for (int off = 1; off < 1024; off <<= 1) {
            int xv = (t >= off) ? sh[t - off] : 0;
            __syncthreads();
            if (t >= off) sh[t] += xv;
            __syncthreads();
        }
        int excl = sh[t] - v + carry;
        if (i < NN) { g_rowptr[i] = excl; g_cursor[i] = excl; }
        int tot = sh[1023];
        __syncthreads();
        if (t == 0) carry += tot;
        __syncthreads();
    }
    if (t == 0) g_rowptr[NN] = carry;
}

__global__ void k_fill(const int* __restrict__ dst) {
    int e = blockIdx.x * blockDim.x + threadIdx.x;
    if (e < NE) {
        int p = atomicAdd(&g_cursor[dst[e]], 1);
        g_esorted[p] = e;
    }
}

// ---------------- attention logit pieces ------------------------------------
__global__ void k_al(const float* __restrict__ xw,
                     const float* __restrict__ asrc, const float* __restrict__ adst) {
    int n = blockIdx.x;
    int w = threadIdx.x >> 5, l = threadIdx.x & 31;
    const float* row = xw + (size_t)n * HC + w * C_;
    const float* as  = asrc + w * C_;
    const float* ad  = adst + w * C_;
    float s = 0.f, d = 0.f;
    for (int c = l; c < C_; c += 32) {
        float v = row[c];
        s += v * as[c];
        d += v * ad[c];
    }
#pragma unroll
    for (int off = 16; off; off >>= 1) {
        s += __shfl_xor_sync(0xffffffffu, s, off);
        d += __shfl_xor_sync(0xffffffffu, d, off);
    }
    if (l == 0) { g_al_src[n * H_ + w] = s; g_al_dst[n * H_ + w] = d; }
}

__global__ void k_V(const float* __restrict__ We, const float* __restrict__ aedge) {
    int w = threadIdx.x >> 5, l = threadIdx.x & 31;
    for (int o = w; o < EDIM * H_; o += 8) {
        int d = o / H_, h = o % H_;
        float s = 0.f;
        for (int c = l; c < C_; c += 32)
            s += We[(size_t)d * HC + h * C_ + c] * aedge[h * C_ + c];
#pragma unroll
        for (int off = 16; off; off >>= 1) s += __shfl_xor_sync(0xffffffffu, s, off);
        if (l == 0) g_V[o] = s;
    }
}

// One pass over CSR-sorted positions: edge attn logits + esum atomics +
// leaky-relu alpha in sorted SoA order + pre-gathered src ids.
__global__ void k_edgelogits(const float* __restrict__ ef, const int* __restrict__ src,
                             const int* __restrict__ dst) {
    int i = blockIdx.x * blockDim.x + threadIdx.x;
    if (i >= NE) return;
    int e  = g_esorted[i];
    int sn = src[e], dn = dst[e];
    g_src_s[i] = sn;
    float ea[EDIM];
    const float4* efp = reinterpret_cast<const float4*>(ef + (size_t)e * EDIM);
#pragma unroll
    for (int q = 0; q < EDIM / 4; q++) {
        float4 v = efp[q];
        ea[q * 4 + 0] = v.x; ea[q * 4 + 1] = v.y; ea[q * 4 + 2] = v.z; ea[q * 4 + 3] = v.w;
    }
#pragma unroll
    for (int h = 0; h < H_; h++) {
        float s = 0.f;
#pragma unroll
        for (int d = 0; d < EDIM; d++) s += ea[d] * g_V[d * H_ + h];
        atomicAdd(&g_al_esum[dn * H_ + h], s);
        float v = g_al_src[sn * H_ + h] + g_al_dst[dn * H_ + h] + s;
        g_alpha_s[(size_t)h * NE + i] = v > 0.f ? v : 0.2f * v;
    }
}

__global__ void k_aself() {
    int n = blockIdx.x * blockDim.x + threadIdx.x;
    if (n >= NN) return;
    float invd = 1.0f / fmaxf((float)g_deg[n], 1.0f);
#pragma unroll
    for (int h = 0; h < H_; h++) {
        float v = g_al_src[n * H_ + h] + g_al_dst[n * H_ + h] + g_al_esum[n * H_ + h] * invd;
        g_aself[n * H_ + h] = v > 0.f ? v : 0.2f * v;
    }
}

// ---------------- segment softmax + aggregation (1 block / node) ------------
// Gathers fp16 rows from xw2, writes bias+ELU result as fp16 into GEMM A buf.
__global__ void __launch_bounds__(256)
k_aggregate(const __half* __restrict__ xw2, const float* __restrict__ bias,
            __half* __restrict__ outH) {
    int n = blockIdx.x;
    int beg = g_rowptr[n], end = g_rowptr[n + 1];
    __shared__ float sm[H_], ss[H_];
    int t = threadIdx.x, w = t >> 5, l = t & 31;

    // phase 1: per-head max (incl. self loop); coalesced SoA reads
    if (w < H_) {
        const float* as = g_alpha_s + (size_t)w * NE;
        float mx = g_aself[n * H_ + w];
        for (int i = beg + l; i < end; i += 32) mx = fmaxf(mx, as[i]);
#pragma unroll
        for (int off = 16; off; off >>= 1)
            mx = fmaxf(mx, __shfl_xor_sync(0xffffffffu, mx, off));
        if (l == 0) sm[w] = mx;
    }
    __syncthreads();

    // phase 2: exp + sum; overwrite alpha_s with exp values
    if (w < H_) {
        float mm = sm[w];
        float* as = g_alpha_s + (size_t)w * NE;
        float acc = (l == 0) ? expf(g_aself[n * H_ + w] - mm) : 0.f;
        for (int i = beg + l; i < end; i += 32) {
            float ex = expf(as[i] - mm);
            as[i] = ex;
            acc += ex;
        }
#pragma unroll
        for (int off = 16; off; off >>= 1) acc += __shfl_xor_sync(0xffffffffu, acc, off);
        if (l == 0) ss[w] = acc;
    }
    __syncthreads();

    // phase 3: weighted gather. thread t owns channels 4t..4t+3 (head h = t>>6).
    const int h = t >> 6;
    const float inv = 1.0f / (ss[h] + 1e-16f);
    const float* ash = g_alpha_s + (size_t)h * NE;
    float a0 = 0.f, a1 = 0.f, a2 = 0.f, a3 = 0.f;
    for (int i = beg; i < end; i++) {
        int sn = g_src_s[i];
        float wg = ash[i];
        uint2 rv = *reinterpret_cast<const uint2*>(xw2 + (size_t)sn * HC + 4 * t);
        __half2 p0 = *reinterpret_cast<__half2*>(&rv.x);
        __half2 p1 = *reinterpret_cast<__half2*>(&rv.y);
        a0 += wg * __low2float(p0); a1 += wg * __high2float(p0);
        a2 += wg * __low2float(p1); a3 += wg * __high2float(p1);
    }
    {   // self loop
        float wg = expf(g_aself[n * H_ + h] - sm[h]);
        uint2 rv = *reinterpret_cast<const uint2*>(xw2 + (size_t)n * HC + 4 * t);
        __half2 p0 = *reinterpret_cast<__half2*>(&rv.x);
        __half2 p1 = *reinterpret_cast<__half2*>(&rv.y);
        a0 += wg * __low2float(p0); a1 += wg * __high2float(p0);
        a2 += wg * __low2float(p1); a3 += wg * __high2float(p1);
    }
    float4 b4 = *reinterpret_cast<const float4*>(bias + 4 * t);
    float v0 = a0 * inv + b4.x, v1 = a1 * inv + b4.y;
    float v2 = a2 * inv + b4.z, v3 = a3 * inv + b4.w;
    v0 = v0 > 0.f ? v0 : expm1f(v0);
    v1 = v1 > 0.f ? v1 : expm1f(v1);
    v2 = v2 > 0.f ? v2 : expm1f(v2);
    v3 = v3 > 0.f ? v3 : expm1f(v3);
    uint2 ov;
    *reinterpret_cast<__half2*>(&ov.x) = __floats2half2_rn(v0, v1);
    *reinterpret_cast<__half2*>(&ov.y) = __floats2half2_rn(v2, v3);
    *reinterpret_cast<uint2*>(outH + (size_t)n * HC + 4 * t) = ov;
}

// ---------------- fp16 conversions ------------------------------------------
// A rounded to fp16; rows >= Mv zero-padded (layer-1 input x only).
__global__ void k_convA(const float* __restrict__ src, __half* __restrict__ dst,
                        int Mv, int K) {
    int i = blockIdx.x * blockDim.x + threadIdx.x;
    if (i >= MPAD * K) return;
    int m = i / K, k = i - m * K;
    float a = (m < Mv) ? src[(size_t)m * K + k] : 0.f;
    dst[(size_t)m * K + k] = __float2half(a);
}

// B' = transpose(W[K,N]) rounded to fp16, stored [N,K].
__global__ void k_convB(const float* __restrict__ W, __half* __restrict__ dst,
                        int K, int Nn) {
    __shared__ float t[32][33];
    int n = blockIdx.x * 32 + threadIdx.x;
    int k = blockIdx.y * 32 + threadIdx.y;
    t[threadIdx.y][threadIdx.x] = W[(size_t)k * Nn + n];
    __syncthreads();
    int n2 = blockIdx.x * 32 + threadIdx.y;
    int k2 = blockIdx.y * 32 + threadIdx.x;
    dst[(size_t)n2 * K + k2] = __float2half(t[threadIdx.x][threadIdx.y]);
}

// ---------------- fp16 HMMA GEMM --------------------------------------------
// out[m,n] (+bias[n]) = A[m,K] . B[n,K]   (fp16 operands, fp32 accumulate)
// CTA tile 128x256, 512 threads (16 warps, warp tile 32x64), BK=32,
// 4-stage cp.async pipeline (96 KB smem).  Optional fp16 shadow output.

__device__ __forceinline__ uint32_t s2u(const void* p) {
    uint32_t a;
    asm("{ .reg .u64 t; cvta.to.shared.u64 t, %1; cvt.u32.u64 %0, t; }" : "=r"(a) : "l"(p));
    return a;
}

__device__ __forceinline__ void cp16(uint32_t saddr, const void* gptr) {
    asm volatile("cp.async.cg.shared.global [%0], [%1], 16;" :: "r"(saddr), "l"(gptr));
}

#define LDSM4(r, addr) \
    asm volatile("ldmatrix.sync.aligned.m8n8.x4.shared.b16 {%0,%1,%2,%3}, [%4];" \
        : "=r"((r)[0]), "=r"((r)[1]), "=r"((r)[2]), "=r"((r)[3]) : "r"(addr))

#define MMA16816(c, a, b0, b1) \
    asm volatile("mma.sync.aligned.m16n8k16.row.col.f32.f16.f16.f32 " \
        "{%0,%1,%2,%3}, {%4,%5,%6,%7}, {%8,%9}, {%0,%1,%2,%3};" \
        : "+f"((c)[0]), "+f"((c)[1]), "+f"((c)[2]), "+f"((c)[3]) \
        : "r"((a)[0]), "r"((a)[1]), "r"((a)[2]), "r"((a)[3]), "r"(b0), "r"(b1))

constexpr int STAGE_BYTES = 24576;              // A 8KB + B 16KB
constexpr int MMA_SMEM    = 4 * STAGE_BYTES;    // 96 KB

template <bool BIAS, bool WHALF>
__global__ void __launch_bounds__(512, 1)
k_mma_gemm(const __half* __restrict__ A, const __half* __restrict__ B,
           const float* __restrict__ bias, float* __restrict__ out,
           __half* __restrict__ out2, int Mv, int K, int ldo) {
    extern __shared__ char smem[];
    const uint32_t sb = s2u(smem);
    const int tid  = threadIdx.x;
    const int lane = tid & 31, wid = tid >> 5;
    const int wm = (wid & 3) * 32, wn = (wid >> 2) * 64;
    const int bm = blockIdx.x * 128, bn = blockIdx.y * 256;
    const int KITER = K >> 5;

    const __half* ag0 = A + (size_t)bm * K;
    const __half* bg0 = B + (size_t)bn * K;

    // swizzle: 16B segment s of row r -> phys seg (s ^ ((r>>1)&3))
    auto load_stage = [&](int kt, int slot) {
        const int k0 = kt * 32;
        const uint32_t sa  = sb + slot * STAGE_BYTES;
        const uint32_t sbm = sa + 8192;
        {                                  // A: 128 rows x 4 segs = 512
            int row = tid >> 2, seg = tid & 3;
            uint32_t off = row * 64 + ((seg ^ ((row >> 1) & 3)) << 4);
            cp16(sa + off, ag0 + (size_t)row * K + k0 + seg * 8);
        }
#pragma unroll
        for (int i = 0; i < 2; i++) {      // B: 256 rows x 4 segs = 1024
            int u = tid + i * 512;
            int row = u >> 2, seg = u & 3;
            uint32_t off = row * 64 + ((seg ^ ((row >> 1) & 3)) << 4);
            cp16(sbm + off, bg0 + (size_t)row * K + k0 + seg * 8);
        }
    };

    float acc[2][8][4];
#pragma unroll
    for (int i = 0; i < 2; i++)
#pragma unroll
        for (int j = 0; j < 8; j++)
#pragma unroll
            for (int r = 0; r < 4; r++) acc[i][j][r] = 0.f;

    load_stage(0, 0);
    asm volatile("cp.async.commit_group;" ::: "memory");
    load_stage(1, 1);
    asm volatile("cp.async.commit_group;" ::: "memory");
    load_stage(2, 2);
    asm volatile("cp.async.commit_group;" ::: "memory");

    for (int kt = 0; kt < KITER; kt++) {
        asm volatile("cp.async.wait_group 2;" ::: "memory");
        __syncthreads();
        if (kt + 3 < KITER) load_stage(kt + 3, (kt + 3) & 3);
        asm volatile("cp.async.commit_group;" ::: "memory");

        const uint32_t sa  = sb + (kt & 3) * STAGE_BYTES;
        const uint32_t sbm = sa + 8192;
#pragma unroll
        for (int ks2 = 0; ks2 < 2; ks2++) {
            uint32_t av[2][4], bv[4][4];
            const int segk = ks2 * 2 + (lane >> 4);
#pragma unroll
            for (int mf = 0; mf < 2; mf++) {
                int row = wm + mf * 16 + (lane & 15);
                LDSM4(av[mf], sa + row * 64 + ((segk ^ ((row >> 1) & 3)) << 4));
            }
#pragma unroll
            for (int p = 0; p < 4; p++) {
                int row = wn + p * 16 + (lane & 15);
                LDSM4(bv[p], sbm + row * 64 + ((segk ^ ((row >> 1) & 3)) << 4));
            }
#pragma unroll
            for (int mf = 0; mf < 2; mf++)
#pragma unroll
                for (int p = 0; p < 4; p++) {
                    MMA16816(acc[mf][p * 2 + 0], av[mf], bv[p][0], bv[p][2]);
                    MMA16816(acc[mf][p * 2 + 1], av[mf], bv[p][1], bv[p][3]);
                }
        }
    }

    // epilogue
    const int r0 = lane >> 2, c0 = (lane & 3) * 2;
#pragma unroll
    for (int mf = 0; mf < 2; mf++) {
#pragma unroll
        for (int half = 0; half < 2; half++) {
            int m = bm + wm + mf * 16 + r0 + half * 8;
            if (m >= Mv) continue;
            float* orow = out + (size_t)m * ldo;
            __half* o2row = WHALF ? out2 + (size_t)m * ldo : nullptr;
#pragma unroll
            for (int nf = 0; nf < 8; nf++) {
                int n = bn + wn + nf * 8 + c0;
                float2 v;
                v.x = acc[mf][nf][half * 2 + 0];
                v.y = acc[mf][nf][half * 2 + 1];
                if (BIAS) { v.x += __ldg(bias + n); v.y += __ldg(bias + n + 1); }
                *reinterpret_cast<float2*>(orow + n) = v;
                if (WHALF)
                    *reinterpret_cast<__half2*>(o2row + n) = __floats2half2_rn(v.x, v.y);
            }
        }
    }
}

// ---------------- launch -----------------------------------------------------
extern "C" void kernel_launch(void* const* d_in, const int* in_sizes, int n_in,
                              void* d_out, int out_size) {
    const float* x      = (const float*)d_in[0];
    const int*   ei     = (const int*)d_in[1];
    const float* ef     = (const float*)d_in[2];
    const float* W1     = (const float*)d_in[3];
    const float* asrc1  = (const float*)d_in[4];
    const float* adst1  = (const float*)d_in[5];
    const float* aedge1 = (const float*)d_in[6];
    const float* We1    = (const float*)d_in[7];
    const float* b1     = (const float*)d_in[8];
    const float* W2     = (const float*)d_in[9];
    const float* asrc2  = (const float*)d_in[10];
    const float* adst2  = (const float*)d_in[11];
    const float* aedge2 = (const float*)d_in[12];
    const float* We2    = (const float*)d_in[13];
    const float* b2     = (const float*)d_in[14];
    const float* Wf     = (const float*)d_in[15];
    const float* bf     = (const float*)d_in[16];
    const int* src = ei;
    const int* dst = ei + NE;
    float* out = (float*)d_out;

    void* p;
    cudaGetSymbolAddress(&p, g_xw);  float*  xw  = (float*)p;
    cudaGetSymbolAddress(&p, g_xw2); __half* xw2 = (__half*)p;
    cudaGetSymbolAddress(&p, g_Asp); __half* Asp = (__half*)p;
    cudaGetSymbolAddress(&p, g_BtF); __half* BtF = (__half*)p;
    cudaGetSymbolAddress(&p, g_Bt2); __half* Bt2 = (__half*)p;
    cudaGetSymbolAddress(&p, g_Bt1); __half* Bt1 = (__half*)p;

    static bool attr_done = false;
    if (!attr_done) {
        cudaFuncSetAttribute((const void*)k_mma_gemm<true,  false>,
                             cudaFuncAttributeMaxDynamicSharedMemorySize, MMA_SMEM);
        cudaFuncSetAttribute((const void*)k_mma_gemm<false, true>,
                             cudaFuncAttributeMaxDynamicSharedMemorySize, MMA_SMEM);
        attr_done = true;
    }

    // weight conversions (independent of activations)
    k_convB<<<dim3(HC / 32, DIN / 32), dim3(32, 32)>>>(W1, Bt1, DIN, HC);
    k_convB<<<dim3(HC / 32, HC / 32), dim3(32, 32)>>>(W2, Bt2, HC, HC);
    k_convB<<<dim3(DOUT / 32, HC / 32), dim3(32, 32)>>>(Wf, BtF, HC, DOUT);

    // graph structure (CSR by dst)
    k_zero_deg<<<(NN + 255) / 256, 256>>>();
    k_count<<<(NE + 255) / 256, 256>>>(dst);
    k_scan<<<1, 1024>>>();
    k_fill<<<(NE + 255) / 256, 256>>>(dst);

    // ---- layer 1:  xw = x @ W1  (fp16 HMMA, fp32+fp16 outputs) ----
    k_convA<<<(MPAD * DIN + 255) / 256, 256>>>(x, Asp, NN, DIN);
    k_mma_gemm<false, true><<<dim3(MPAD / 128, HC / 256), 512, MMA_SMEM>>>(
        Asp, Bt1, nullptr, xw, xw2, NN, DIN, HC);
    k_al<<<NN, 128>>>(xw, asrc1, adst1);
    k_V<<<1, 256>>>(We1, aedge1);
    k_zero_esum<<<(NN * H_ + 255) / 256, 256>>>();
    k_edgelogits<<<(NE + 255) / 256, 256>>>(ef, src, dst);
    k_aself<<<(NN + 255) / 256, 256>>>();
    k_aggregate<<<NN, 256>>>(xw2, b1, Asp);   // writes fp16 A for layer 2

    // ---- layer 2:  xw = h1 @ W2 ----
    k_mma_gemm<false, true><<<dim3(MPAD / 128, HC / 256), 512, MMA_SMEM>>>(
        Asp, Bt2, nullptr, xw, xw2, NN, HC, HC);
    k_al<<<NN, 128>>>(xw, asrc2, adst2);
    k_V<<<1, 256>>>(We2, aedge2);
    k_zero_esum<<<(NN * H_ + 255) / 256, 256>>>();
    k_edgelogits<<<(NE + 255) / 256, 256>>>(ef, src, dst);
    k_aself<<<(NN + 255) / 256, 256>>>();
    k_aggregate<<<NN, 256>>>(xw2, b2, Asp);   // writes fp16 A for final GEMM

    // ---- final linear: out = h2 @ Wf + bf ----
    k_mma_gemm<true, false><<<dim3(MPAD / 128, DOUT / 256), 512, MMA_SMEM>>>(
        Asp, BtF, bf, out, nullptr, NN, HC, DOUT);
}

// round 10
// speedup vs baseline: 6.6705x; 1.0269x over previous
#include <cuda_runtime.h>
#include <cuda_fp16.h>
#include <math.h>
#include <stdint.h>

// Problem constants (fixed shapes per metadata)
constexpr int NN   = 10000;   // nodes
constexpr int NE   = 160000;  // edges
constexpr int DIN  = 128;     // input feature dim
constexpr int EDIM = 16;      // edge feature dim
constexpr int H_   = 4;       // heads
constexpr int C_   = 256;     // channels per head
constexpr int HC   = 1024;    // H*C
constexpr int DOUT = 25088;   // final output dim

constexpr int MPAD = 10112;   // 79 * 128 (M padded)

// ---------------- scratch (static device globals: allocation-free) ----------
__device__ float  g_xw[NN * HC];          // layer GEMM output fp32 (for k_al)
__device__ __half g_xw2[NN * HC];         // fp16 copy (gather source)
__device__ float  g_al_src[NN * H_];
__device__ float  g_al_dst[NN * H_];
__device__ float  g_alpha_s[(size_t)H_ * NE];  // leaky logits, SoA CSR-sorted
__device__ float  g_s_s[(size_t)H_ * NE];      // raw edge logits, SoA CSR-sorted
__device__ float  g_V[EDIM * H_];
__device__ int    g_deg[NN];
__device__ int    g_rowptr[NN + 1];
__device__ int    g_cursor[NN];
__device__ int    g_esorted[NE];
__device__ int    g_src_s[NE];            // src node per sorted position
__device__ __half g_Asp[(size_t)MPAD * HC];     // GEMM A operand (fp16)
__device__ __half g_BtF[(size_t)DOUT * HC];     // Wf^T fp16 [25088,1024]
__device__ __half g_Bt2[(size_t)HC * HC];       // W2^T fp16 [1024,1024]
__device__ __half g_Bt1[(size_t)HC * DIN];      // W1^T fp16 [1024,128]

// ---------------- graph structure kernels ----------------------------------
__global__ void k_zero_deg() {
    int i = blockIdx.x * blockDim.x + threadIdx.x;
    if (i < NN) g_deg[i] = 0;
}

__global__ void k_count(const int* __restrict__ dst) {
    int e = blockIdx.x * blockDim.x + threadIdx.x;
    if (e < NE) atomicAdd(&g_deg[dst[e]], 1);
}

__global__ void k_scan() {
    __shared__ int sh[1024];
    __shared__ int carry;
    int t = threadIdx.x;
    if (t == 0) carry = 0;
    __syncthreads();
    for (int base = 0; base < NN; base += 1024) {
        int i = base + t;
        int v = (i < NN) ? g_deg[i] : 0;
        sh[t] = v;
        __syncthreads();
        for (int off = 1; off < 1024; off <<= 1) {
            int xv = (t >= off) ? sh[t - off] : 0;
            __syncthreads();
            if (t >= off) sh[t] += xv;
            __syncthreads();
        }
        int excl = sh[t] - v + carry;
        if (i < NN) { g_rowptr[i] = excl; g_cursor[i] = excl; }
        int tot = sh[1023];
        __syncthreads();
        if (t == 0) carry += tot;
        __syncthreads();
    }
    if (t == 0) g_rowptr[NN] = carry;
}

__global__ void k_fill(const int* __restrict__ dst) {
    int e = blockIdx.x * blockDim.x + threadIdx.x;
    if (e < NE) {
        int p = atomicAdd(&g_cursor[dst[e]], 1);
        g_esorted[p] = e;
    }
}

// ---------------- attention logit pieces ------------------------------------
__global__ void k_al(const float* __restrict__ xw,
                     const float* __restrict__ asrc, const float* __restrict__ adst) {
    int n = blockIdx.x;
    int w = threadIdx.x >> 5, l = threadIdx.x & 31;
    const float* row = xw + (size_t)n * HC + w * C_;
    const float* as  = asrc + w * C_;
    const float* ad  = adst + w * C_;
    float s = 0.f, d = 0.f;
    for (int c = l; c < C_; c += 32) {
        float v = row[c];
        s += v * as[c];
        d += v * ad[c];
    }
#pragma unroll
    for (int off = 16; off; off >>= 1) {
        s += __shfl_xor_sync(0xffffffffu, s, off);
        d += __shfl_xor_sync(0xffffffffu, d, off);
    }
    if (l == 0) { g_al_src[n * H_ + w] = s; g_al_dst[n * H_ + w] = d; }
}

__global__ void k_V(const float* __restrict__ We, const float* __restrict__ aedge) {
    int w = threadIdx.x >> 5, l = threadIdx.x & 31;
    for (int o = w; o < EDIM * H_; o += 8) {
        int d = o / H_, h = o % H_;
        float s = 0.f;
        for (int c = l; c < C_; c += 32)
            s += We[(size_t)d * HC + h * C_ + c] * aedge[h * C_ + c];
#pragma unroll
        for (int off = 16; off; off >>= 1) s += __shfl_xor_sync(0xffffffffu, s, off);
        if (l == 0) g_V[o] = s;
    }
}

// One pass over CSR-sorted positions: edge attn logits (raw + leaky) in sorted
// SoA order + pre-gathered src ids.  No atomics.
__global__ void k_edgelogits(const float* __restrict__ ef, const int* __restrict__ src,
                             const int* __restrict__ dst) {
    int i = blockIdx.x * blockDim.x + threadIdx.x;
    if (i >= NE) return;
    int e  = g_esorted[i];
    int sn = src[e], dn = dst[e];
    g_src_s[i] = sn;
    float ea[EDIM];
    const float4* efp = reinterpret_cast<const float4*>(ef + (size_t)e * EDIM);
#pragma unroll
    for (int q = 0; q < EDIM / 4; q++) {
        float4 v = efp[q];
        ea[q * 4 + 0] = v.x; ea[q * 4 + 1] = v.y; ea[q * 4 + 2] = v.z; ea[q * 4 + 3] = v.w;
    }
#pragma unroll
    for (int h = 0; h < H_; h++) {
        float s = 0.f;
#pragma unroll
        for (int d = 0; d < EDIM; d++) s += ea[d] * g_V[d * H_ + h];
        g_s_s[(size_t)h * NE + i] = s;
        float v = g_al_src[sn * H_ + h] + g_al_dst[dn * H_ + h] + s;
        g_alpha_s[(size_t)h * NE + i] = v > 0.f ? v : 0.2f * v;
    }
}

// ---------------- segment softmax + aggregation (1 block / node) ------------
// Computes self-loop logit (mean edge attr) via CSR reduction, softmax, and
// weighted fp16 gather; writes bias+ELU result as fp16 into GEMM A buffer.
__global__ void __launch_bounds__(256)
k_aggregate(const __half* __restrict__ xw2, const float* __restrict__ bias,
            __half* __restrict__ outH) {
    int n = blockIdx.x;
    int beg = g_rowptr[n], end = g_rowptr[n + 1];
    __shared__ float sm[H_], ss[H_], sself[H_];
    int t = threadIdx.x, w = t >> 5, l = t & 31;

    // phase 0: esum via CSR reduction -> self-loop leaky logit
    if (w < H_) {
        const float* ssrc = g_s_s + (size_t)w * NE;
        float es = 0.f;
        for (int i = beg + l; i < end; i += 32) es += ssrc[i];
#pragma unroll
        for (int off = 16; off; off >>= 1) es += __shfl_xor_sync(0xffffffffu, es, off);
        if (l == 0) {
            float invd = 1.0f / fmaxf((float)(end - beg), 1.0f);
            float v = g_al_src[n * H_ + w] + g_al_dst[n * H_ + w] + es * invd;
            sself[w] = v > 0.f ? v : 0.2f * v;
        }
    }
    __syncthreads();

    // phase 1: per-head max (incl. self loop); coalesced SoA reads
    if (w < H_) {
        const float* as = g_alpha_s + (size_t)w * NE;
        float mx = sself[w];
        for (int i = beg + l; i < end; i += 32) mx = fmaxf(mx, as[i]);
#pragma unroll
        for (int off = 16; off; off >>= 1)
            mx = fmaxf(mx, __shfl_xor_sync(0xffffffffu, mx, off));
        if (l == 0) sm[w] = mx;
    }
    __syncthreads();

    // phase 2: exp + sum; overwrite alpha_s with exp values
    if (w < H_) {
        float mm = sm[w];
        float* as = g_alpha_s + (size_t)w * NE;
        float acc = (l == 0) ? expf(sself[w] - mm) : 0.f;
        for (int i = beg + l; i < end; i += 32) {
            float ex = expf(as[i] - mm);
            as[i] = ex;
            acc += ex;
        }
#pragma unroll
        for (int off = 16; off; off >>= 1) acc += __shfl_xor_sync(0xffffffffu, acc, off);
        if (l == 0) ss[w] = acc;
    }
    __syncthreads();

    // phase 3: weighted gather. thread t owns channels 4t..4t+3 (head h = t>>6).
    const int h = t >> 6;
    const float inv = 1.0f / (ss[h] + 1e-16f);
    const float* ash = g_alpha_s + (size_t)h * NE;
    float a0 = 0.f, a1 = 0.f, a2 = 0.f, a3 = 0.f;
    for (int i = beg; i < end; i++) {
        int sn = g_src_s[i];
        float wg = ash[i];
        uint2 rv = *reinterpret_cast<const uint2*>(xw2 + (size_t)sn * HC + 4 * t);
        __half2 p0 = *reinterpret_cast<__half2*>(&rv.x);
        __half2 p1 = *reinterpret_cast<__half2*>(&rv.y);
        a0 += wg * __low2float(p0); a1 += wg * __high2float(p0);
        a2 += wg * __low2float(p1); a3 += wg * __high2float(p1);
    }
    {   // self loop
        float wg = expf(sself[h] - sm[h]);
        uint2 rv = *reinterpret_cast<const uint2*>(xw2 + (size_t)n * HC + 4 * t);
        __half2 p0 = *reinterpret_cast<__half2*>(&rv.x);
        __half2 p1 = *reinterpret_cast<__half2*>(&rv.y);
        a0 += wg * __low2float(p0); a1 += wg * __high2float(p0);
        a2 += wg * __low2float(p1); a3 += wg * __high2float(p1);
    }
    float4 b4 = *reinterpret_cast<const float4*>(bias + 4 * t);
    float v0 = a0 * inv + b4.x, v1 = a1 * inv + b4.y;
    float v2 = a2 * inv + b4.z, v3 = a3 * inv + b4.w;
    v0 = v0 > 0.f ? v0 : expm1f(v0);
    v1 = v1 > 0.f ? v1 : expm1f(v1);
    v2 = v2 > 0.f ? v2 : expm1f(v2);
    v3 = v3 > 0.f ? v3 : expm1f(v3);
    uint2 ov;
    *reinterpret_cast<__half2*>(&ov.x) = __floats2half2_rn(v0, v1);
    *reinterpret_cast<__half2*>(&ov.y) = __floats2half2_rn(v2, v3);
    *reinterpret_cast<uint2*>(outH + (size_t)n * HC + 4 * t) = ov;
}

// ---------------- fp16 conversions ------------------------------------------
// A rounded to fp16; rows >= Mv zero-padded (layer-1 input x only).
__global__ void k_convA(const float* __restrict__ src, __half* __restrict__ dst,
                        int Mv, int K) {
    int i = blockIdx.x * blockDim.x + threadIdx.x;
    if (i >= MPAD * K) return;
    int m = i / K, k = i - m * K;
    float a = (m < Mv) ? src[(size_t)m * K + k] : 0.f;
    dst[(size_t)m * K + k] = __float2half(a);
}

// B' = transpose(W[K,N]) rounded to fp16, stored [N,K].
__global__ void k_convB(const float* __restrict__ W, __half* __restrict__ dst,
                        int K, int Nn) {
    __shared__ float t[32][33];
    int n = blockIdx.x * 32 + threadIdx.x;
    int k = blockIdx.y * 32 + threadIdx.y;
    t[threadIdx.y][threadIdx.x] = W[(size_t)k * Nn + n];
    __syncthreads();
    int n2 = blockIdx.x * 32 + threadIdx.y;
    int k2 = blockIdx.y * 32 + threadIdx.x;
    dst[(size_t)n2 * K + k2] = __float2half(t[threadIdx.x][threadIdx.y]);
}

// ---------------- fp16 HMMA GEMM --------------------------------------------
// out[m,n] (+bias[n]) = A[m,K] . B[n,K]   (fp16 operands, fp32 accumulate)
// CTA tile 128x128, 256 threads (8 warps, warp tile 64x32), BK=32,
// 4-stage cp.async pipeline (64 KB smem), 2 CTAs/SM.

__device__ __forceinline__ uint32_t s2u(const void* p) {
    uint32_t a;
    asm("{ .reg .u64 t; cvta.to.shared.u64 t, %1; cvt.u32.u64 %0, t; }" : "=r"(a) : "l"(p));
    return a;
}

__device__ __forceinline__ void cp16(uint32_t saddr, const void* gptr) {
    asm volatile("cp.async.cg.shared.global [%0], [%1], 16;" :: "r"(saddr), "l"(gptr));
}

#define LDSM4(r, addr) \
    asm volatile("ldmatrix.sync.aligned.m8n8.x4.shared.b16 {%0,%1,%2,%3}, [%4];" \
        : "=r"((r)[0]), "=r"((r)[1]), "=r"((r)[2]), "=r"((r)[3]) : "r"(addr))

#define MMA16816(c, a, b0, b1) \
    asm volatile("mma.sync.aligned.m16n8k16.row.col.f32.f16.f16.f32 " \
        "{%0,%1,%2,%3}, {%4,%5,%6,%7}, {%8,%9}, {%0,%1,%2,%3};" \
        : "+f"((c)[0]), "+f"((c)[1]), "+f"((c)[2]), "+f"((c)[3]) \
        : "r"((a)[0]), "r"((a)[1]), "r"((a)[2]), "r"((a)[3]), "r"(b0), "r"(b1))

constexpr int STAGE_BYTES = 16384;              // A 8KB + B 8KB
constexpr int MMA_SMEM    = 4 * STAGE_BYTES;    // 64 KB

template <bool BIAS, bool WHALF>
__global__ void __launch_bounds__(256, 2)
k_mma_gemm(const __half* __restrict__ A, const __half* __restrict__ B,
           const float* __restrict__ bias, float* __restrict__ out,
           __half* __restrict__ out2, int Mv, int K, int ldo) {
    extern __shared__ char smem[];
    const uint32_t sb = s2u(smem);
    const int tid  = threadIdx.x;
    const int lane = tid & 31, wid = tid >> 5;
    const int wm = (wid & 1) * 64, wn = (wid >> 1) * 32;
    const int bm = blockIdx.x * 128, bn = blockIdx.y * 128;
    const int KITER = K >> 5;

    const __half* ag0 = A + (size_t)bm * K;
    const __half* bg0 = B + (size_t)bn * K;

    // swizzle: 16B segment s of row r -> phys seg (s ^ ((r>>1)&3))
    auto load_stage = [&](int kt, int slot) {
        const int k0 = kt * 32;
        const uint32_t sa  = sb + slot * STAGE_BYTES;
        const uint32_t sbm = sa + 8192;
#pragma unroll
        for (int i = 0; i < 2; i++) {      // A: 128 rows x 4 segs = 512
            int u = tid + i * 256;
            int row = u >> 2, seg = u & 3;
            uint32_t off = row * 64 + ((seg ^ ((row >> 1) & 3)) << 4);
            cp16(sa  + off, ag0 + (size_t)row * K + k0 + seg * 8);
            cp16(sbm + off, bg0 + (size_t)row * K + k0 + seg * 8);
        }
    };

    float acc[4][4][4];
#pragma unroll
    for (int i = 0; i < 4; i++)
#pragma unroll
        for (int j = 0; j < 4; j++)
#pragma unroll
            for (int r = 0; r < 4; r++) acc[i][j][r] = 0.f;

    load_stage(0, 0);
    asm volatile("cp.async.commit_group;" ::: "memory");
    load_stage(1, 1);
    asm volatile("cp.async.commit_group;" ::: "memory");
    load_stage(2, 2);
    asm volatile("cp.async.commit_group;" ::: "memory");

    for (int kt = 0; kt < KITER; kt++) {
        asm volatile("cp.async.wait_group 2;" ::: "memory");
        __syncthreads();
        if (kt + 3 < KITER) load_stage(kt + 3, (kt + 3) & 3);
        asm volatile("cp.async.commit_group;" ::: "memory");

        const uint32_t sa  = sb + (kt & 3) * STAGE_BYTES;
        const uint32_t sbm = sa + 8192;
#pragma unroll
        for (int ks2 = 0; ks2 < 2; ks2++) {
            uint32_t av[4][4], bv[2][4];
            const int segk = ks2 * 2 + (lane >> 4);
#pragma unroll
            for (int mf = 0; mf < 4; mf++) {
                int row = wm + mf * 16 + (lane & 15);
                LDSM4(av[mf], sa + row * 64 + ((segk ^ ((row >> 1) & 3)) << 4));
            }
#pragma unroll
            for (int p = 0; p < 2; p++) {
                int row = wn + p * 16 + (lane & 15);
                LDSM4(bv[p], sbm + row * 64 + ((segk ^ ((row >> 1) & 3)) << 4));
            }
#pragma unroll
            for (int mf = 0; mf < 4; mf++)
#pragma unroll
                for (int nf = 0; nf < 4; nf++)
                    MMA16816(acc[mf][nf], av[mf], bv[nf >> 1][nf & 1], bv[nf >> 1][(nf & 1) + 2]);
        }
    }

    // epilogue
    const int r0 = lane >> 2, c0 = (lane & 3) * 2;
#pragma unroll
    for (int mf = 0; mf < 4; mf++) {
#pragma unroll
        for (int half = 0; half < 2; half++) {
            int m = bm + wm + mf * 16 + r0 + half * 8;
            if (m >= Mv) continue;
            float* orow = out + (size_t)m * ldo;
            __half* o2row = WHALF ? out2 + (size_t)m * ldo : nullptr;
#pragma unroll
            for (int nf = 0; nf < 4; nf++) {
                int n = bn + wn + nf * 8 + c0;
                float2 v;
                v.x = acc[mf][nf][half * 2 + 0];
                v.y = acc[mf][nf][half * 2 + 1];
                if (BIAS) { v.x += __ldg(bias + n); v.y += __ldg(bias + n + 1); }
                *reinterpret_cast<float2*>(orow + n) = v;
                if (WHALF)
                    *reinterpret_cast<__half2*>(o2row + n) = __floats2half2_rn(v.x, v.y);
            }
        }
    }
}

// ---------------- launch -----------------------------------------------------
extern "C" void kernel_launch(void* const* d_in, const int* in_sizes, int n_in,
                              void* d_out, int out_size) {
    const float* x      = (const float*)d_in[0];
    const int*   ei     = (const int*)d_in[1];
    const float* ef     = (const float*)d_in[2];
    const float* W1     = (const float*)d_in[3];
    const float* asrc1  = (const float*)d_in[4];
    const float* adst1  = (const float*)d_in[5];
    const float* aedge1 = (const float*)d_in[6];
    const float* We1    = (const float*)d_in[7];
    const float* b1     = (const float*)d_in[8];
    const float* W2     = (const float*)d_in[9];
    const float* asrc2  = (const float*)d_in[10];
    const float* adst2  = (const float*)d_in[11];
    const float* aedge2 = (const float*)d_in[12];
    const float* We2    = (const float*)d_in[13];
    const float* b2     = (const float*)d_in[14];
    const float* Wf     = (const float*)d_in[15];
    const float* bf     = (const float*)d_in[16];
    const int* src = ei;
    const int* dst = ei + NE;
    float* out = (float*)d_out;

    void* p;
    cudaGetSymbolAddress(&p, g_xw);  float*  xw  = (float*)p;
    cudaGetSymbolAddress(&p, g_xw2); __half* xw2 = (__half*)p;
    cudaGetSymbolAddress(&p, g_Asp); __half* Asp = (__half*)p;
    cudaGetSymbolAddress(&p, g_BtF); __half* BtF = (__half*)p;
    cudaGetSymbolAddress(&p, g_Bt2); __half* Bt2 = (__half*)p;
    cudaGetSymbolAddress(&p, g_Bt1); __half* Bt1 = (__half*)p;

    static bool attr_done = false;
    if (!attr_done) {
        cudaFuncSetAttribute((const void*)k_mma_gemm<true,  false>,
                             cudaFuncAttributeMaxDynamicSharedMemorySize, MMA_SMEM);
        cudaFuncSetAttribute((const void*)k_mma_gemm<false, true>,
                             cudaFuncAttributeMaxDynamicSharedMemorySize, MMA_SMEM);
        attr_done = true;
    }

    // weight conversions (independent of activations)
    k_convB<<<dim3(HC / 32, DIN / 32), dim3(32, 32)>>>(W1, Bt1, DIN, HC);
    k_convB<<<dim3(HC / 32, HC / 32), dim3(32, 32)>>>(W2, Bt2, HC, HC);
    k_convB<<<dim3(DOUT / 32, HC / 32), dim3(32, 32)>>>(Wf, BtF, HC, DOUT);

    // graph structure (CSR by dst)
    k_zero_deg<<<(NN + 255) / 256, 256>>>();
    k_count<<<(NE + 255) / 256, 256>>>(dst);
    k_scan<<<1, 1024>>>();
    k_fill<<<(NE + 255) / 256, 256>>>(dst);

    // ---- layer 1:  xw = x @ W1  (fp16 HMMA, fp32+fp16 outputs) ----
    k_convA<<<(MPAD * DIN + 255) / 256, 256>>>(x, Asp, NN, DIN);
    k_mma_gemm<false, true><<<dim3(MPAD / 128, HC / 128), 256, MMA_SMEM>>>(
        Asp, Bt1, nullptr, xw, xw2, NN, DIN, HC);
    k_al<<<NN, 128>>>(xw, asrc1, adst1);
    k_V<<<1, 256>>>(We1, aedge1);
    k_edgelogits<<<(NE + 255) / 256, 256>>>(ef, src, dst);
    k_aggregate<<<NN, 256>>>(xw2, b1, Asp);   // writes fp16 A for layer 2

    // ---- layer 2:  xw = h1 @ W2 ----
    k_mma_gemm<false, true><<<dim3(MPAD / 128, HC / 128), 256, MMA_SMEM>>>(
        Asp, Bt2, nullptr, xw, xw2, NN, HC, HC);
    k_al<<<NN, 128>>>(xw, asrc2, adst2);
    k_V<<<1, 256>>>(We2, aedge2);
    k_edgelogits<<<(NE + 255) / 256, 256>>>(ef, src, dst);
    k_aggregate<<<NN, 256>>>(xw2, b2, Asp);   // writes fp16 A for final GEMM

    // ---- final linear: out = h2 @ Wf + bf ----
    k_mma_gemm<true, false><<<dim3(MPAD / 128, DOUT / 128), 256, MMA_SMEM>>>(
        Asp, BtF, bf, out, nullptr, NN, HC, DOUT);
}

// round 11
// speedup vs baseline: 6.7238x; 1.0080x over previous
#include <cuda_runtime.h>
#include <cuda_fp16.h>
#include <math.h>
#include <stdint.h>

// Problem constants (fixed shapes per metadata)
constexpr int NN   = 10000;   // nodes
constexpr int NE   = 160000;  // edges
constexpr int DIN  = 128;     // input feature dim
constexpr int EDIM = 16;      // edge feature dim
constexpr int H_   = 4;       // heads
constexpr int C_   = 256;     // channels per head
constexpr int HC   = 1024;    // H*C
constexpr int DOUT = 25088;   // final output dim

constexpr int MPAD = 10112;   // 79 * 128 (M padded)

// ---------------- scratch (static device globals: allocation-free) ----------
__device__ float  g_xw[NN * HC];          // layer GEMM output fp32 (for k_al)
__device__ __half g_xw2[NN * HC];         // fp16 copy (gather source)
__device__ float  g_al_src[NN * H_];
__device__ float  g_al_dst[NN * H_];
__device__ float  g_alpha_s[(size_t)H_ * NE];  // leaky logits, SoA CSR-sorted
__device__ float  g_s_s[(size_t)H_ * NE];      // raw edge logits, SoA CSR-sorted
__device__ float  g_V[EDIM * H_];
__device__ int    g_deg[NN];
__device__ int    g_rowptr[NN + 1];
__device__ int    g_cursor[NN];
__device__ int    g_esorted[NE];
__device__ int    g_src_s[NE];            // src node per sorted position
__device__ __half g_Asp[(size_t)MPAD * HC];     // GEMM A operand (fp16)
__device__ __half g_BtF[(size_t)DOUT * HC];     // Wf^T fp16 [25088,1024]
__device__ __half g_Bt2[(size_t)HC * HC];       // W2^T fp16 [1024,1024]
__device__ __half g_Bt1[(size_t)HC * DIN];      // W1^T fp16 [1024,128]

// ---------------- graph structure kernels ----------------------------------
__global__ void k_zero_deg() {
    int i = blockIdx.x * blockDim.x + threadIdx.x;
    if (i < NN) g_deg[i] = 0;
}

__global__ void k_count(const int* __restrict__ dst) {
    int e = blockIdx.x * blockDim.x + threadIdx.x;
    if (e < NE) atomicAdd(&g_deg[dst[e]], 1);
}

__global__ void k_scan() {
    __shared__ int sh[1024];
    __shared__ int carry;
    int t = threadIdx.x;
    if (t == 0) carry = 0;
    __syncthreads();
    for (int base = 0; base < NN; base += 1024) {
        int i = base + t;
        int v = (i < NN) ? g_deg[i] : 0;
        sh[t] = v;
        __syncthreads();
        for (int off = 1; off < 1024; off <<= 1) {
            int xv = (t >= off) ? sh[t - off] : 0;
            __syncthreads();
            if (t >= off) sh[t] += xv;
            __syncthreads();
        }
        int excl = sh[t] - v + carry;
        if (i < NN) { g_rowptr[i] = excl; g_cursor[i] = excl; }
        int tot = sh[1023];
        __syncthreads();
        if (t == 0) carry += tot;
        __syncthreads();
    }
    if (t == 0) g_rowptr[NN] = carry;
}

__global__ void k_fill(const int* __restrict__ dst) {
    int e = blockIdx.x * blockDim.x + threadIdx.x;
    if (e < NE) {
        int p = atomicAdd(&g_cursor[dst[e]], 1);
        g_esorted[p] = e;
    }
}

// ---------------- attention logit pieces ------------------------------------
__global__ void k_al(const float* __restrict__ xw,
                     const float* __restrict__ asrc, const float* __restrict__ adst) {
    int n = blockIdx.x;
    int w = threadIdx.x >> 5, l = threadIdx.x & 31;
    const float* row = xw + (size_t)n * HC + w * C_;
    const float* as  = asrc + w * C_;
    const float* ad  = adst + w * C_;
    float s = 0.f, d = 0.f;
    for (int c = l; c < C_; c += 32) {
        float v = row[c];
        s += v * as[c];
        d += v * ad[c];
    }
#pragma unroll
    for (int off = 16; off; off >>= 1) {
        s += __shfl_xor_sync(0xffffffffu, s, off);
        d += __shfl_xor_sync(0xffffffffu, d, off);
    }
    if (l == 0) { g_al_src[n * H_ + w] = s; g_al_dst[n * H_ + w] = d; }
}

__global__ void k_V(const float* __restrict__ We, const float* __restrict__ aedge) {
    int w = threadIdx.x >> 5, l = threadIdx.x & 31;
    for (int o = w; o < EDIM * H_; o += 8) {
        int d = o / H_, h = o % H_;
        float s = 0.f;
        for (int c = l; c < C_; c += 32)
            s += We[(size_t)d * HC + h * C_ + c] * aedge[h * C_ + c];
#pragma unroll
        for (int off = 16; off; off >>= 1) s += __shfl_xor_sync(0xffffffffu, s, off);
        if (l == 0) g_V[o] = s;
    }
}

// One pass over CSR-sorted positions: edge attn logits (raw + leaky) in sorted
// SoA order + pre-gathered src ids.  No atomics.
__global__ void k_edgelogits(const float* __restrict__ ef, const int* __restrict__ src,
                             const int* __restrict__ dst) {
    int i = blockIdx.x * blockDim.x + threadIdx.x;
    if (i >= NE) return;
    int e  = g_esorted[i];
    int sn = src[e], dn = dst[e];
    g_src_s[i] = sn;
    float ea[EDIM];
    const float4* efp = reinterpret_cast<const float4*>(ef + (size_t)e * EDIM);
#pragma unroll
    for (int q = 0; q < EDIM / 4; q++) {
        float4 v = efp[q];
        ea[q * 4 + 0] = v.x; ea[q * 4 + 1] = v.y; ea[q * 4 + 2] = v.z; ea[q * 4 + 3] = v.w;
    }
#pragma unroll
    for (int h = 0; h < H_; h++) {
        float s = 0.f;
#pragma unroll
        for (int d = 0; d < EDIM; d++) s += ea[d] * g_V[d * H_ + h];
        g_s_s[(size_t)h * NE + i] = s;
        float v = g_al_src[sn * H_ + h] + g_al_dst[dn * H_ + h] + s;
        g_alpha_s[(size_t)h * NE + i] = v > 0.f ? v : 0.2f * v;
    }
}

// ---------------- segment softmax + aggregation (1 block / node) ------------
// Computes self-loop logit (mean edge attr) via CSR reduction, softmax, and
// weighted fp16 gather; writes bias+ELU result as fp16 into GEMM A buffer.
__global__ void __launch_bounds__(256)
k_aggregate(const __half* __restrict__ xw2, const float* __restrict__ bias,
            __half* __restrict__ outH) {
    int n = blockIdx.x;
    int beg = g_rowptr[n], end = g_rowptr[n + 1];
    __shared__ float sm[H_], ss[H_], sself[H_];
    int t = threadIdx.x, w = t >> 5, l = t & 31;

    // phase 0: esum via CSR reduction -> self-loop leaky logit
    if (w < H_) {
        const float* ssrc = g_s_s + (size_t)w * NE;
        float es = 0.f;
        for (int i = beg + l; i < end; i += 32) es += ssrc[i];
#pragma unroll
        for (int off = 16; off; off >>= 1) es += __shfl_xor_sync(0xffffffffu, es, off);
        if (l == 0) {
            float invd = 1.0f / fmaxf((float)(end - beg), 1.0f);
            float v = g_al_src[n * H_ + w] + g_al_dst[n * H_ + w] + es * invd;
            sself[w] = v > 0.f ? v : 0.2f * v;
        }
    }
    __syncthreads();

    // phase 1: per-head max (incl. self loop); coalesced SoA reads
    if (w < H_) {
        const float* as = g_alpha_s + (size_t)w * NE;
        float mx = sself[w];
        for (int i = beg + l; i < end; i += 32) mx = fmaxf(mx, as[i]);
#pragma unroll
        for (int off = 16; off; off >>= 1)
            mx = fmaxf(mx, __shfl_xor_sync(0xffffffffu, mx, off));
        if (l == 0) sm[w] = mx;
    }
    __syncthreads();

    // phase 2: exp + sum; overwrite alpha_s with exp values
    if (w < H_) {
        float mm = sm[w];
        float* as = g_alpha_s + (size_t)w * NE;
        float acc = (l == 0) ? expf(sself[w] - mm) : 0.f;
        for (int i = beg + l; i < end; i += 32) {
            float ex = expf(as[i] - mm);
            as[i] = ex;
            acc += ex;
        }
#pragma unroll
        for (int off = 16; off; off >>= 1) acc += __shfl_xor_sync(0xffffffffu, acc, off);
        if (l == 0) ss[w] = acc;
    }
    __syncthreads();

    // phase 3: weighted gather. thread t owns channels 4t..4t+3 (head h = t>>6).
    const int h = t >> 6;
    const float inv = 1.0f / (ss[h] + 1e-16f);
    const float* ash = g_alpha_s + (size_t)h * NE;
    float a0 = 0.f, a1 = 0.f, a2 = 0.f, a3 = 0.f;
    for (int i = beg; i < end; i++) {
        int sn = g_src_s[i];
        float wg = ash[i];
        uint2 rv = *reinterpret_cast<const uint2*>(xw2 + (size_t)sn * HC + 4 * t);
        __half2 p0 = *reinterpret_cast<__half2*>(&rv.x);
        __half2 p1 = *reinterpret_cast<__half2*>(&rv.y);
        a0 += wg * __low2float(p0); a1 += wg * __high2float(p0);
        a2 += wg * __low2float(p1); a3 += wg * __high2float(p1);
    }
    {   // self loop
        float wg = expf(sself[h] - sm[h]);
        uint2 rv = *reinterpret_cast<const uint2*>(xw2 + (size_t)n * HC + 4 * t);
        __half2 p0 = *reinterpret_cast<__half2*>(&rv.x);
        __half2 p1 = *reinterpret_cast<__half2*>(&rv.y);
        a0 += wg * __low2float(p0); a1 += wg * __high2float(p0);
        a2 += wg * __low2float(p1); a3 += wg * __high2float(p1);
    }
    float4 b4 = *reinterpret_cast<const float4*>(bias + 4 * t);
    float v0 = a0 * inv + b4.x, v1 = a1 * inv + b4.y;
    float v2 = a2 * inv + b4.z, v3 = a3 * inv + b4.w;
    v0 = v0 > 0.f ? v0 : expm1f(v0);
    v1 = v1 > 0.f ? v1 : expm1f(v1);
    v2 = v2 > 0.f ? v2 : expm1f(v2);
    v3 = v3 > 0.f ? v3 : expm1f(v3);
    uint2 ov;
    *reinterpret_cast<__half2*>(&ov.x) = __floats2half2_rn(v0, v1);
    *reinterpret_cast<__half2*>(&ov.y) = __floats2half2_rn(v2, v3);
    *reinterpret_cast<uint2*>(outH + (size_t)n * HC + 4 * t) = ov;
}

// ---------------- fp16 conversions ------------------------------------------
// A rounded to fp16; rows >= Mv zero-padded (layer-1 input x only).
__global__ void k_convA(const float* __restrict__ src, __half* __restrict__ dst,
                        int Mv, int K) {
    int i = blockIdx.x * blockDim.x + threadIdx.x;
    if (i >= MPAD * K) return;
    int m = i / K, k = i - m * K;
    float a = (m < Mv) ? src[(size_t)m * K + k] : 0.f;
    dst[(size_t)m * K + k] = __float2half(a);
}

// B' = transpose(W[K,N]) rounded to fp16, stored [N,K].
__global__ void k_convB(const float* __restrict__ W, __half* __restrict__ dst,
                        int K, int Nn) {
    __shared__ float t[32][33];
    int n = blockIdx.x * 32 + threadIdx.x;
    int k = blockIdx.y * 32 + threadIdx.y;
    t[threadIdx.y][threadIdx.x] = W[(size_t)k * Nn + n];
    __syncthreads();
    int n2 = blockIdx.x * 32 + threadIdx.y;
    int k2 = blockIdx.y * 32 + threadIdx.x;
    dst[(size_t)n2 * K + k2] = __float2half(t[threadIdx.x][threadIdx.y]);
}

// ---------------- fp16 HMMA GEMM --------------------------------------------
// out[m,n] (+bias[n]) = A[m,K] . B[n,K]   (fp16 operands, fp32 accumulate)
// CTA tile 128x128, 128 threads (4 warps, warp tile 64x64), BK=32,
// 4-stage cp.async pipeline (64 KB smem), 2 CTAs/SM.
// 64x64 warp tiles halve smem fragment traffic vs 64x32 (A x2, B x2 reuse).

__device__ __forceinline__ uint32_t s2u(const void* p) {
    uint32_t a;
    asm("{ .reg .u64 t; cvta.to.shared.u64 t, %1; cvt.u32.u64 %0, t; }" : "=r"(a) : "l"(p));
    return a;
}

__device__ __forceinline__ void cp16(uint32_t saddr, const void* gptr) {
    asm volatile("cp.async.cg.shared.global [%0], [%1], 16;" :: "r"(saddr), "l"(gptr));
}

#define LDSM4(r, addr) \
    asm volatile("ldmatrix.sync.aligned.m8n8.x4.shared.b16 {%0,%1,%2,%3}, [%4];" \
        : "=r"((r)[0]), "=r"((r)[1]), "=r"((r)[2]), "=r"((r)[3]) : "r"(addr))

#define MMA16816(c, a, b0, b1) \
    asm volatile("mma.sync.aligned.m16n8k16.row.col.f32.f16.f16.f32 " \
        "{%0,%1,%2,%3}, {%4,%5,%6,%7}, {%8,%9}, {%0,%1,%2,%3};" \
        : "+f"((c)[0]), "+f"((c)[1]), "+f"((c)[2]), "+f"((c)[3]) \
        : "r"((a)[0]), "r"((a)[1]), "r"((a)[2]), "r"((a)[3]), "r"(b0), "r"(b1))

constexpr int STAGE_BYTES = 16384;              // A 8KB + B 8KB
constexpr int MMA_SMEM    = 4 * STAGE_BYTES;    // 64 KB

template <bool BIAS, bool WHALF>
__global__ void __launch_bounds__(128, 2)
k_mma_gemm(const __half* __restrict__ A, const __half* __restrict__ B,
           const float* __restrict__ bias, float* __restrict__ out,
           __half* __restrict__ out2, int Mv, int K, int ldo) {
    extern __shared__ char smem[];
    const uint32_t sb = s2u(smem);
    const int tid  = threadIdx.x;
    const int lane = tid & 31, wid = tid >> 5;
    const int wm = (wid & 1) * 64, wn = (wid >> 1) * 64;
    const int bm = blockIdx.x * 128, bn = blockIdx.y * 128;
    const int KITER = K >> 5;

    const __half* ag0 = A + (size_t)bm * K;
    const __half* bg0 = B + (size_t)bn * K;

    // swizzle: 16B segment s of row r -> phys seg (s ^ ((r>>1)&3))
    auto load_stage = [&](int kt, int slot) {
        const int k0 = kt * 32;
        const uint32_t sa  = sb + slot * STAGE_BYTES;
        const uint32_t sbm = sa + 8192;
#pragma unroll
        for (int i = 0; i < 4; i++) {      // A,B: each 128 rows x 4 segs = 512
            int u = tid + i * 128;
            int row = u >> 2, seg = u & 3;
            uint32_t off = row * 64 + ((seg ^ ((row >> 1) & 3)) << 4);
            cp16(sa  + off, ag0 + (size_t)row * K + k0 + seg * 8);
            cp16(sbm + off, bg0 + (size_t)row * K + k0 + seg * 8);
        }
    };

    float acc[4][8][4];
#pragma unroll
    for (int i = 0; i < 4; i++)
#pragma unroll
        for (int j = 0; j < 8; j++)
#pragma unroll
            for (int r = 0; r < 4; r++) acc[i][j][r] = 0.f;

    load_stage(0, 0);
    asm volatile("cp.async.commit_group;" ::: "memory");
    load_stage(1, 1);
    asm volatile("cp.async.commit_group;" ::: "memory");
    load_stage(2, 2);
    asm volatile("cp.async.commit_group;" ::: "memory");

    for (int kt = 0; kt < KITER; kt++) {
        asm volatile("cp.async.wait_group 2;" ::: "memory");
        __syncthreads();
        if (kt + 3 < KITER) load_stage(kt + 3, (kt + 3) & 3);
        asm volatile("cp.async.commit_group;" ::: "memory");

        const uint32_t sa  = sb + (kt & 3) * STAGE_BYTES;
        const uint32_t sbm = sa + 8192;
#pragma unroll
        for (int ks2 = 0; ks2 < 2; ks2++) {
            uint32_t av[4][4], bv[4][4];
            const int segk = ks2 * 2 + (lane >> 4);
#pragma unroll
            for (int mf = 0; mf < 4; mf++) {
                int row = wm + mf * 16 + (lane & 15);
                LDSM4(av[mf], sa + row * 64 + ((segk ^ ((row >> 1) & 3)) << 4));
            }
#pragma unroll
            for (int p = 0; p < 4; p++) {
                int row = wn + p * 16 + (lane & 15);
                LDSM4(bv[p], sbm + row * 64 + ((segk ^ ((row >> 1) & 3)) << 4));
            }
#pragma unroll
            for (int mf = 0; mf < 4; mf++)
#pragma unroll
                for (int p = 0; p < 4; p++) {
                    MMA16816(acc[mf][p * 2 + 0], av[mf], bv[p][0], bv[p][2]);
                    MMA16816(acc[mf][p * 2 + 1], av[mf], bv[p][1], bv[p][3]);
                }
        }
    }

    // epilogue
    const int r0 = lane >> 2, c0 = (lane & 3) * 2;
#pragma unroll
    for (int mf = 0; mf < 4; mf++) {
#pragma unroll
        for (int half = 0; half < 2; half++) {
            int m = bm + wm + mf * 16 + r0 + half * 8;
            if (m >= Mv) continue;
            float* orow = out + (size_t)m * ldo;
            __half* o2row = WHALF ? out2 + (size_t)m * ldo : nullptr;
#pragma unroll
            for (int nf = 0; nf < 8; nf++) {
                int n = bn + wn + nf * 8 + c0;
                float2 v;
                v.x = acc[mf][nf][half * 2 + 0];
                v.y = acc[mf][nf][half * 2 + 1];
                if (BIAS) { v.x += __ldg(bias + n); v.y += __ldg(bias + n + 1); }
                *reinterpret_cast<float2*>(orow + n) = v;
                if (WHALF)
                    *reinterpret_cast<__half2*>(o2row + n) = __floats2half2_rn(v.x, v.y);
            }
        }
    }
}

// ---------------- launch -----------------------------------------------------
extern "C" void kernel_launch(void* const* d_in, const int* in_sizes, int n_in,
                              void* d_out, int out_size) {
    const float* x      = (const float*)d_in[0];
    const int*   ei     = (const int*)d_in[1];
    const float* ef     = (const float*)d_in[2];
    const float* W1     = (const float*)d_in[3];
    const float* asrc1  = (const float*)d_in[4];
    const float* adst1  = (const float*)d_in[5];
    const float* aedge1 = (const float*)d_in[6];
    const float* We1    = (const float*)d_in[7];
    const float* b1     = (const float*)d_in[8];
    const float* W2     = (const float*)d_in[9];
    const float* asrc2  = (const float*)d_in[10];
    const float* adst2  = (const float*)d_in[11];
    const float* aedge2 = (const float*)d_in[12];
    const float* We2    = (const float*)d_in[13];
    const float* b2     = (const float*)d_in[14];
    const float* Wf     = (const float*)d_in[15];
    const float* bf     = (const float*)d_in[16];
    const int* src = ei;
    const int* dst = ei + NE;
    float* out = (float*)d_out;

    void* p;
    cudaGetSymbolAddress(&p, g_xw);  float*  xw  = (float*)p;
    cudaGetSymbolAddress(&p, g_xw2); __half* xw2 = (__half*)p;
    cudaGetSymbolAddress(&p, g_Asp); __half* Asp = (__half*)p;
    cudaGetSymbolAddress(&p, g_BtF); __half* BtF = (__half*)p;
    cudaGetSymbolAddress(&p, g_Bt2); __half* Bt2 = (__half*)p;
    cudaGetSymbolAddress(&p, g_Bt1); __half* Bt1 = (__half*)p;

    static bool attr_done = false;
    if (!attr_done) {
        cudaFuncSetAttribute((const void*)k_mma_gemm<true,  false>,
                             cudaFuncAttributeMaxDynamicSharedMemorySize, MMA_SMEM);
        cudaFuncSetAttribute((const void*)k_mma_gemm<false, true>,
                             cudaFuncAttributeMaxDynamicSharedMemorySize, MMA_SMEM);
        attr_done = true;
    }

    // weight conversions (independent of activations)
    k_convB<<<dim3(HC / 32, DIN / 32), dim3(32, 32)>>>(W1, Bt1, DIN, HC);
    k_convB<<<dim3(HC / 32, HC / 32), dim3(32, 32)>>>(W2, Bt2, HC, HC);
    k_convB<<<dim3(DOUT / 32, HC / 32), dim3(32, 32)>>>(Wf, BtF, HC, DOUT);

    // graph structure (CSR by dst)
    k_zero_deg<<<(NN + 255) / 256, 256>>>();
    k_count<<<(NE + 255) / 256, 256>>>(dst);
    k_scan<<<1, 1024>>>();
    k_fill<<<(NE + 255) / 256, 256>>>(dst);

    // ---- layer 1:  xw = x @ W1  (fp16 HMMA, fp32+fp16 outputs) ----
    k_convA<<<(MPAD * DIN + 255) / 256, 256>>>(x, Asp, NN, DIN);
    k_mma_gemm<false, true><<<dim3(MPAD / 128, HC / 128), 128, MMA_SMEM>>>(
        Asp, Bt1, nullptr, xw, xw2, NN, DIN, HC);
    k_al<<<NN, 128>>>(xw, asrc1, adst1);
    k_V<<<1, 256>>>(We1, aedge1);
    k_edgelogits<<<(NE + 255) / 256, 256>>>(ef, src, dst);
    k_aggregate<<<NN, 256>>>(xw2, b1, Asp);   // writes fp16 A for layer 2

    // ---- layer 2:  xw = h1 @ W2 ----
    k_mma_gemm<false, true><<<dim3(MPAD / 128, HC / 128), 128, MMA_SMEM>>>(
        Asp, Bt2, nullptr, xw, xw2, NN, HC, HC);
    k_al<<<NN, 128>>>(xw, asrc2, adst2);
    k_V<<<1, 256>>>(We2, aedge2);
    k_edgelogits<<<(NE + 255) / 256, 256>>>(ef, src, dst);
    k_aggregate<<<NN, 256>>>(xw2, b2, Asp);   // writes fp16 A for final GEMM

    // ---- final linear: out = h2 @ Wf + bf ----
    k_mma_gemm<true, false><<<dim3(MPAD / 128, DOUT / 128), 128, MMA_SMEM>>>(
        Asp, BtF, bf, out, nullptr, NN, HC, DOUT);
}

// round 12
// speedup vs baseline: 6.8566x; 1.0197x over previous
#include <cuda_runtime.h>
#include <cuda_fp16.h>
#include <math.h>
#include <stdint.h>

// Problem constants (fixed shapes per metadata)
constexpr int NN   = 10000;   // nodes
constexpr int NE   = 160000;  // edges
constexpr int DIN  = 128;     // input feature dim
constexpr int EDIM = 16;      // edge feature dim
constexpr int H_   = 4;       // heads
constexpr int C_   = 256;     // channels per head
constexpr int HC   = 1024;    // H*C
constexpr int DOUT = 25088;   // final output dim

constexpr int MPAD = 10112;   // 79 * 128 (M padded)

// ---------------- scratch (static device globals: allocation-free) ----------
__device__ __half g_xw2[NN * HC];         // layer GEMM output (fp16)
__device__ float  g_al_src[NN * H_];
__device__ float  g_al_dst[NN * H_];
__device__ float  g_alpha_s[(size_t)H_ * NE];  // leaky logits, SoA CSR-sorted
__device__ float  g_s_s[(size_t)H_ * NE];      // raw edge logits, SoA CSR-sorted
__device__ float  g_V[EDIM * H_];
__device__ int    g_deg[NN];
__device__ int    g_rowptr[NN + 1];
__device__ int    g_cursor[NN];
__device__ int    g_esorted[NE];
__device__ int    g_src_s[NE];            // src node per sorted position
__device__ int    g_bsum[40];
__device__ int    g_boff[40];
__device__ __half g_Asp[(size_t)MPAD * HC];     // GEMM A operand (fp16)
__device__ __half g_BtF[(size_t)DOUT * HC];     // Wf^T fp16 [25088,1024]
__device__ __half g_Bt2[(size_t)HC * HC];       // W2^T fp16 [1024,1024]
__device__ __half g_Bt1[(size_t)HC * DIN];      // W1^T fp16 [1024,128]

// ---------------- graph structure kernels ----------------------------------
__global__ void k_zero_deg() {
    int i = blockIdx.x * blockDim.x + threadIdx.x;
    if (i < NN) g_deg[i] = 0;
}

__global__ void k_count(const int* __restrict__ dst) {
    int e = blockIdx.x * blockDim.x + threadIdx.x;
    if (e < NE) atomicAdd(&g_deg[dst[e]], 1);
}

// 3-stage parallel scan of g_deg -> g_rowptr/g_cursor
__global__ void k_scanA() {          // per-256-chunk sums
    __shared__ int sh[256];
    int i = blockIdx.x * 256 + threadIdx.x;
    sh[threadIdx.x] = (i < NN) ? g_deg[i] : 0;
    __syncthreads();
    for (int off = 128; off; off >>= 1) {
        if (threadIdx.x < off) sh[threadIdx.x] += sh[threadIdx.x + off];
        __syncthreads();
    }
    if (threadIdx.x == 0) g_bsum[blockIdx.x] = sh[0];
}

__global__ void k_scanB() {          // exclusive scan of 40 block sums
    __shared__ int sh[64];
    int t = threadIdx.x;
    int v = (t < 40) ? g_bsum[t] : 0;
    sh[t] = v;
    __syncthreads();
    for (int off = 1; off < 64; off <<= 1) {
        int x = (t >= off) ? sh[t - off] : 0;
        __syncthreads();
        sh[t] += x;
        __syncthreads();
    }
    if (t < 40) g_boff[t] = sh[t] - v;
    if (t == 39) g_rowptr[NN] = sh[39];
}

__global__ void k_scanC() {          // per-chunk scan + offset
    __shared__ int sh[256];
    int i = blockIdx.x * 256 + threadIdx.x;
    int v = (i < NN) ? g_deg[i] : 0;
    sh[threadIdx.x] = v;
    __syncthreads();
    for (int off = 1; off < 256; off <<= 1) {
        int x = (threadIdx.x >= off) ? sh[threadIdx.x - off] : 0;
        __syncthreads();
        sh[threadIdx.x] += x;
        __syncthreads();
    }
    if (i < NN) {
        int excl = sh[threadIdx.x] - v + g_boff[blockIdx.x];
        g_rowptr[i] = excl;
        g_cursor[i] = excl;
    }
}

__global__ void k_fill(const int* __restrict__ dst) {
    int e = blockIdx.x * blockDim.x + threadIdx.x;
    if (e < NE) {
        int p = atomicAdd(&g_cursor[dst[e]], 1);
        g_esorted[p] = e;
    }
}

// ---------------- attention logit pieces ------------------------------------
// al_src/al_dst from fp16 xw2 (fp32 accumulate)
__global__ void k_al(const __half* __restrict__ xw2,
                     const float* __restrict__ asrc, const float* __restrict__ adst) {
    int n = blockIdx.x;
    int w = threadIdx.x >> 5, l = threadIdx.x & 31;
    const __half2* row = reinterpret_cast<const __half2*>(xw2 + (size_t)n * HC + w * C_);
    const float* as  = asrc + w * C_;
    const float* ad  = adst + w * C_;
    float s = 0.f, d = 0.f;
    for (int c2 = l; c2 < C_ / 2; c2 += 32) {
        __half2 h = row[c2];
        float x0 = __low2float(h), x1 = __high2float(h);
        s += x0 * as[2 * c2] + x1 * as[2 * c2 + 1];
        d += x0 * ad[2 * c2] + x1 * ad[2 * c2 + 1];
    }
#pragma unroll
    for (int off = 16; off; off >>= 1) {
        s += __shfl_xor_sync(0xffffffffu, s, off);
        d += __shfl_xor_sync(0xffffffffu, d, off);
    }
    if (l == 0) { g_al_src[n * H_ + w] = s; g_al_dst[n * H_ + w] = d; }
}

__global__ void k_V(const float* __restrict__ We, const float* __restrict__ aedge) {
    int w = threadIdx.x >> 5, l = threadIdx.x & 31;
    for (int o = w; o < EDIM * H_; o += 8) {
        int d = o / H_, h = o % H_;
        float s = 0.f;
        for (int c = l; c < C_; c += 32)
            s += We[(size_t)d * HC + h * C_ + c] * aedge[h * C_ + c];
#pragma unroll
        for (int off = 16; off; off >>= 1) s += __shfl_xor_sync(0xffffffffu, s, off);
        if (l == 0) g_V[o] = s;
    }
}

// One pass over CSR-sorted positions: edge attn logits (raw + leaky) in sorted
// SoA order + pre-gathered src ids.  No atomics.
__global__ void k_edgelogits(const float* __restrict__ ef, const int* __restrict__ src,
                             const int* __restrict__ dst) {
    int i = blockIdx.x * blockDim.x + threadIdx.x;
    if (i >= NE) return;
    int e  = g_esorted[i];
    int sn = src[e], dn = dst[e];
    g_src_s[i] = sn;
    float ea[EDIM];
    const float4* efp = reinterpret_cast<const float4*>(ef + (size_t)e * EDIM);
#pragma unroll
    for (int q = 0; q < EDIM / 4; q++) {
        float4 v = efp[q];
        ea[q * 4 + 0] = v.x; ea[q * 4 + 1] = v.y; ea[q * 4 + 2] = v.z; ea[q * 4 + 3] = v.w;
    }
#pragma unroll
    for (int h = 0; h < H_; h++) {
        float s = 0.f;
#pragma unroll
        for (int d = 0; d < EDIM; d++) s += ea[d] * g_V[d * H_ + h];
        g_s_s[(size_t)h * NE + i] = s;
        float v = g_al_src[sn * H_ + h] + g_al_dst[dn * H_ + h] + s;
        g_alpha_s[(size_t)h * NE + i] = v > 0.f ? v : 0.2f * v;
    }
}

// ---------------- segment softmax + aggregation (1 block / node) ------------
__global__ void __launch_bounds__(256)
k_aggregate(const __half* __restrict__ xw2, const float* __restrict__ bias,
            __half* __restrict__ outH) {
    int n = blockIdx.x;
    int beg = g_rowptr[n], end = g_rowptr[n + 1];
    __shared__ float sm[H_], ss[H_], sself[H_];
    int t = threadIdx.x, w = t >> 5, l = t & 31;

    // phase 0: esum via CSR reduction -> self-loop leaky logit
    if (w < H_) {
        const float* ssrc = g_s_s + (size_t)w * NE;
        float es = 0.f;
        for (int i = beg + l; i < end; i += 32) es += ssrc[i];
#pragma unroll
        for (int off = 16; off; off >>= 1) es += __shfl_xor_sync(0xffffffffu, es, off);
        if (l == 0) {
            float invd = 1.0f / fmaxf((float)(end - beg), 1.0f);
            float v = g_al_src[n * H_ + w] + g_al_dst[n * H_ + w] + es * invd;
            sself[w] = v > 0.f ? v : 0.2f * v;
        }
    }
    __syncthreads();

    // phase 1: per-head max
    if (w < H_) {
        const float* as = g_alpha_s + (size_t)w * NE;
        float mx = sself[w];
        for (int i = beg + l; i < end; i += 32) mx = fmaxf(mx, as[i]);
#pragma unroll
        for (int off = 16; off; off >>= 1)
            mx = fmaxf(mx, __shfl_xor_sync(0xffffffffu, mx, off));
        if (l == 0) sm[w] = mx;
    }
    __syncthreads();

    // phase 2: exp + sum; overwrite alpha_s with exp values
    if (w < H_) {
        float mm = sm[w];
        float* as = g_alpha_s + (size_t)w * NE;
        float acc = (l == 0) ? expf(sself[w] - mm) : 0.f;
        for (int i = beg + l; i < end; i += 32) {
            float ex = expf(as[i] - mm);
            as[i] = ex;
            acc += ex;
        }
#pragma unroll
        for (int off = 16; off; off >>= 1) acc += __shfl_xor_sync(0xffffffffu, acc, off);
        if (l == 0) ss[w] = acc;
    }
    __syncthreads();

    // phase 3: weighted gather. thread t owns channels 4t..4t+3 (head h = t>>6).
    const int h = t >> 6;
    const float inv = 1.0f / (ss[h] + 1e-16f);
    const float* ash = g_alpha_s + (size_t)h * NE;
    float a0 = 0.f, a1 = 0.f, a2 = 0.f, a3 = 0.f;
    for (int i = beg; i < end; i++) {
        int sn = g_src_s[i];
        float wg = ash[i];
        uint2 rv = *reinterpret_cast<const uint2*>(xw2 + (size_t)sn * HC + 4 * t);
        __half2 p0 = *reinterpret_cast<__half2*>(&rv.x);
        __half2 p1 = *reinterpret_cast<__half2*>(&rv.y);
        a0 += wg * __low2float(p0); a1 += wg * __high2float(p0);
        a2 += wg * __low2float(p1); a3 += wg * __high2float(p1);
    }
    {   // self loop
        float wg = expf(sself[h] - sm[h]);
        uint2 rv = *reinterpret_cast<const uint2*>(xw2 + (size_t)n * HC + 4 * t);
        __half2 p0 = *reinterpret_cast<__half2*>(&rv.x);
        __half2 p1 = *reinterpret_cast<__half2*>(&rv.y);
        a0 += wg * __low2float(p0); a1 += wg * __high2float(p0);
        a2 += wg * __low2float(p1); a3 += wg * __high2float(p1);
    }
    float4 b4 = *reinterpret_cast<const float4*>(bias + 4 * t);
    float v0 = a0 * inv + b4.x, v1 = a1 * inv + b4.y;
    float v2 = a2 * inv + b4.z, v3 = a3 * inv + b4.w;
    v0 = v0 > 0.f ? v0 : expm1f(v0);
    v1 = v1 > 0.f ? v1 : expm1f(v1);
    v2 = v2 > 0.f ? v2 : expm1f(v2);
    v3 = v3 > 0.f ? v3 : expm1f(v3);
    uint2 ov;
    *reinterpret_cast<__half2*>(&ov.x) = __floats2half2_rn(v0, v1);
    *reinterpret_cast<__half2*>(&ov.y) = __floats2half2_rn(v2, v3);
    *reinterpret_cast<uint2*>(outH + (size_t)n * HC + 4 * t) = ov;
}

// ---------------- fp16 conversions ------------------------------------------
__global__ void k_convA(const float* __restrict__ src, __half* __restrict__ dst,
                        int Mv, int K) {
    int i = blockIdx.x * blockDim.x + threadIdx.x;
    if (i >= MPAD * K) return;
    int m = i / K, k = i - m * K;
    float a = (m < Mv) ? src[(size_t)m * K + k] : 0.f;
    dst[(size_t)m * K + k] = __float2half(a);
}

__global__ void k_convB(const float* __restrict__ W, __half* __restrict__ dst,
                        int K, int Nn) {
    __shared__ float t[32][33];
    int n = blockIdx.x * 32 + threadIdx.x;
    int k = blockIdx.y * 32 + threadIdx.y;
    t[threadIdx.y][threadIdx.x] = W[(size_t)k * Nn + n];
    __syncthreads();
    int n2 = blockIdx.x * 32 + threadIdx.y;
    int k2 = blockIdx.y * 32 + threadIdx.x;
    dst[(size_t)n2 * K + k2] = __float2half(t[threadIdx.x][threadIdx.y]);
}

// ---------------- fp16 HMMA GEMM --------------------------------------------
// CTA tile 128x128, 128 threads (4 warps, warp tile 64x64), BK=32,
// 4-stage cp.async pipeline (64 KB smem), 2 CTAs/SM.
// BIAS=true: fp32 out (+bias).  BIAS=false: fp16 out only.

__device__ __forceinline__ uint32_t s2u(const void* p) {
    uint32_t a;
    asm("{ .reg .u64 t; cvta.to.shared.u64 t, %1; cvt.u32.u64 %0, t; }" : "=r"(a) : "l"(p));
    return a;
}

__device__ __forceinline__ void cp16(uint32_t saddr, const void* gptr) {
    asm volatile("cp.async.cg.shared.global [%0], [%1], 16;" :: "r"(saddr), "l"(gptr));
}

#define LDSM4(r, addr) \
    asm volatile("ldmatrix.sync.aligned.m8n8.x4.shared.b16 {%0,%1,%2,%3}, [%4];" \
        : "=r"((r)[0]), "=r"((r)[1]), "=r"((r)[2]), "=r"((r)[3]) : "r"(addr))

#define MMA16816(c, a, b0, b1) \
    asm volatile("mma.sync.aligned.m16n8k16.row.col.f32.f16.f16.f32 " \
        "{%0,%1,%2,%3}, {%4,%5,%6,%7}, {%8,%9}, {%0,%1,%2,%3};" \
        : "+f"((c)[0]), "+f"((c)[1]), "+f"((c)[2]), "+f"((c)[3]) \
        : "r"((a)[0]), "r"((a)[1]), "r"((a)[2]), "r"((a)[3]), "r"(b0), "r"(b1))

constexpr int STAGE_BYTES = 16384;              // A 8KB + B 8KB
constexpr int MMA_SMEM    = 4 * STAGE_BYTES;    // 64 KB

template <bool BIAS>
__global__ void __launch_bounds__(128, 2)
k_mma_gemm(const __half* __restrict__ A, const __half* __restrict__ B,
           const float* __restrict__ bias, float* __restrict__ outF,
           __half* __restrict__ outH, int Mv, int K, int ldo) {
    extern __shared__ char smem[];
    const uint32_t sb = s2u(smem);
    const int tid  = threadIdx.x;
    const int lane = tid & 31, wid = tid >> 5;
    const int wm = (wid & 1) * 64, wn = (wid >> 1) * 64;
    const int bm = blockIdx.x * 128, bn = blockIdx.y * 128;
    const int KITER = K >> 5;

    const __half* ag0 = A + (size_t)bm * K;
    const __half* bg0 = B + (size_t)bn * K;

    auto load_stage = [&](int kt, int slot) {
        const int k0 = kt * 32;
        const uint32_t sa  = sb + slot * STAGE_BYTES;
        const uint32_t sbm = sa + 8192;
#pragma unroll
        for (int i = 0; i < 4; i++) {
            int u = tid + i * 128;
            int row = u >> 2, seg = u & 3;
            uint32_t off = row * 64 + ((seg ^ ((row >> 1) & 3)) << 4);
            cp16(sa  + off, ag0 + (size_t)row * K + k0 + seg * 8);
            cp16(sbm + off, bg0 + (size_t)row * K + k0 + seg * 8);
        }
    };

    float acc[4][8][4];
#pragma unroll
    for (int i = 0; i < 4; i++)
#pragma unroll
        for (int j = 0; j < 8; j++)
#pragma unroll
            for (int r = 0; r < 4; r++) acc[i][j][r] = 0.f;

    load_stage(0, 0);
    asm volatile("cp.async.commit_group;" ::: "memory");
    load_stage(1, 1);
    asm volatile("cp.async.commit_group;" ::: "memory");
    load_stage(2, 2);
    asm volatile("cp.async.commit_group;" ::: "memory");

    for (int kt = 0; kt < KITER; kt++) {
        asm volatile("cp.async.wait_group 2;" ::: "memory");
        __syncthreads();
        if (kt + 3 < KITER) load_stage(kt + 3, (kt + 3) & 3);
        asm volatile("cp.async.commit_group;" ::: "memory");

        const uint32_t sa  = sb + (kt & 3) * STAGE_BYTES;
        const uint32_t sbm = sa + 8192;
#pragma unroll
        for (int ks2 = 0; ks2 < 2; ks2++) {
            uint32_t av[4][4], bv[4][4];
            const int segk = ks2 * 2 + (lane >> 4);
#pragma unroll
            for (int mf = 0; mf < 4; mf++) {
                int row = wm + mf * 16 + (lane & 15);
                LDSM4(av[mf], sa + row * 64 + ((segk ^ ((row >> 1) & 3)) << 4));
            }
#pragma unroll
            for (int p = 0; p < 4; p++) {
                int row = wn + p * 16 + (lane & 15);
                LDSM4(bv[p], sbm + row * 64 + ((segk ^ ((row >> 1) & 3)) << 4));
            }
#pragma unroll
            for (int mf = 0; mf < 4; mf++)
#pragma unroll
                for (int p = 0; p < 4; p++) {
                    MMA16816(acc[mf][p * 2 + 0], av[mf], bv[p][0], bv[p][2]);
                    MMA16816(acc[mf][p * 2 + 1], av[mf], bv[p][1], bv[p][3]);
                }
        }
    }

    // epilogue
    const int r0 = lane >> 2, c0 = (lane & 3) * 2;
#pragma unroll
    for (int mf = 0; mf < 4; mf++) {
#pragma unroll
        for (int half = 0; half < 2; half++) {
            int m = bm + wm + mf * 16 + r0 + half * 8;
            if (m >= Mv) continue;
#pragma unroll
            for (int nf = 0; nf < 8; nf++) {
                int n = bn + wn + nf * 8 + c0;
                float vx = acc[mf][nf][half * 2 + 0];
                float vy = acc[mf][nf][half * 2 + 1];
                if (BIAS) {
                    vx += __ldg(bias + n); vy += __ldg(bias + n + 1);
                    *reinterpret_cast<float2*>(outF + (size_t)m * ldo + n) =
                        make_float2(vx, vy);
                } else {
                    *reinterpret_cast<__half2*>(outH + (size_t)m * ldo + n) =
                        __floats2half2_rn(vx, vy);
                }
            }
        }
    }
}

// ---------------- launch -----------------------------------------------------
extern "C" void kernel_launch(void* const* d_in, const int* in_sizes, int n_in,
                              void* d_out, int out_size) {
    const float* x      = (const float*)d_in[0];
    const int*   ei     = (const int*)d_in[1];
    const float* ef     = (const float*)d_in[2];
    const float* W1     = (const float*)d_in[3];
    const float* asrc1  = (const float*)d_in[4];
    const float* adst1  = (const float*)d_in[5];
    const float* aedge1 = (const float*)d_in[6];
    const float* We1    = (const float*)d_in[7];
    const float* b1     = (const float*)d_in[8];
    const float* W2     = (const float*)d_in[9];
    const float* asrc2  = (const float*)d_in[10];
    const float* adst2  = (const float*)d_in[11];
    const float* aedge2 = (const float*)d_in[12];
    const float* We2    = (const float*)d_in[13];
    const float* b2     = (const float*)d_in[14];
    const float* Wf     = (const float*)d_in[15];
    const float* bf     = (const float*)d_in[16];
    const int* src = ei;
    const int* dst = ei + NE;
    float* out = (float*)d_out;

    void* p;
    cudaGetSymbolAddress(&p, g_xw2); __half* xw2 = (__half*)p;
    cudaGetSymbolAddress(&p, g_Asp); __half* Asp = (__half*)p;
    cudaGetSymbolAddress(&p, g_BtF); __half* BtF = (__half*)p;
    cudaGetSymbolAddress(&p, g_Bt2); __half* Bt2 = (__half*)p;
    cudaGetSymbolAddress(&p, g_Bt1); __half* Bt1 = (__half*)p;

    static bool init_done = false;
    static cudaStream_t s1;
    static cudaEvent_t evFork, evSmall, evBF;
    if (!init_done) {
        cudaFuncSetAttribute((const void*)k_mma_gemm<true>,
                             cudaFuncAttributeMaxDynamicSharedMemorySize, MMA_SMEM);
        cudaFuncSetAttribute((const void*)k_mma_gemm<false>,
                             cudaFuncAttributeMaxDynamicSharedMemorySize, MMA_SMEM);
        cudaStreamCreateWithFlags(&s1, cudaStreamNonBlocking);
        cudaEventCreateWithFlags(&evFork,  cudaEventDisableTiming);
        cudaEventCreateWithFlags(&evSmall, cudaEventDisableTiming);
        cudaEventCreateWithFlags(&evBF,    cudaEventDisableTiming);
        init_done = true;
    }

    // fork side stream: weight conversions + k_V run concurrently
    cudaEventRecord(evFork, 0);
    cudaStreamWaitEvent(s1, evFork, 0);
    k_convB<<<dim3(HC / 32, DIN / 32), dim3(32, 32), 0, s1>>>(W1, Bt1, DIN, HC);
    k_convB<<<dim3(HC / 32, HC / 32), dim3(32, 32), 0, s1>>>(W2, Bt2, HC, HC);
    k_V<<<1, 256, 0, s1>>>(We1, aedge1);
    k_V2_label: ;
    k_V<<<1, 256, 0, s1>>>(We2, aedge2);   // NOTE: overwrites g_V — see fix below
    cudaEventRecord(evSmall, s1);
    k_convB<<<dim3(DOUT / 32, HC / 32), dim3(32, 32), 0, s1>>>(Wf, BtF, HC, DOUT);
    cudaEventRecord(evBF, s1);

    // main stream: CSR build + layer-1 A conversion
    k_zero_deg<<<(NN + 255) / 256, 256>>>();
    k_count<<<(NE + 255) / 256, 256>>>(dst);
    k_scanA<<<40, 256>>>();
    k_scanB<<<1, 64>>>();
    k_scanC<<<40, 256>>>();
    k_fill<<<(NE + 255) / 256, 256>>>(dst);
    k_convA<<<(MPAD * DIN + 255) / 256, 256>>>(x, Asp, NN, DIN);

    cudaStreamWaitEvent(0, evSmall, 0);    // Bt1/Bt2 ready (g_V handled per-layer)

    // ---- layer 1 ----
    k_mma_gemm<false><<<dim3(MPAD / 128, HC / 128), 128, MMA_SMEM>>>(
        Asp, Bt1, nullptr, nullptr, xw2, NN, DIN, HC);
    k_al<<<NN, 128>>>(xw2, asrc1, adst1);
    k_V<<<1, 256>>>(We1, aedge1);          // recompute V1 on main (g_V is shared)
    k_edgelogits<<<(NE + 255) / 256, 256>>>(ef, src, dst);
    k_aggregate<<<NN, 256>>>(xw2, b1, Asp);

    // ---- layer 2 ----
    k_mma_gemm<false><<<dim3(MPAD / 128, HC / 128), 128, MMA_SMEM>>>(
        Asp, Bt2, nullptr, nullptr, xw2, NN, HC, HC);
    k_al<<<NN, 128>>>(xw2, asrc2, adst2);
    k_V<<<1, 256>>>(We2, aedge2);
    k_edgelogits<<<(NE + 255) / 256, 256>>>(ef, src, dst);
    k_aggregate<<<NN, 256>>>(xw2, b2, Asp);

    // ---- final linear: out = h2 @ Wf + bf ----
    cudaStreamWaitEvent(0, evBF, 0);       // BtF ready
    k_mma_gemm<true><<<dim3(MPAD / 128, DOUT / 128), 128, MMA_SMEM>>>(
        Asp, BtF, bf, out, nullptr, NN, HC, DOUT);
}

// round 13
// speedup vs baseline: 6.9321x; 1.0110x over previous
#include <cuda_runtime.h>
#include <cuda_fp16.h>
#include <math.h>
#include <stdint.h>

// Problem constants (fixed shapes per metadata)
constexpr int NN   = 10000;   // nodes
constexpr int NE   = 160000;  // edges
constexpr int DIN  = 128;     // input feature dim
constexpr int EDIM = 16;      // edge feature dim
constexpr int H_   = 4;       // heads
constexpr int C_   = 256;     // channels per head
constexpr int HC   = 1024;    // H*C
constexpr int DOUT = 25088;   // final output dim

constexpr int MPAD = 10112;   // 79 * 128 (M padded)

// ---------------- scratch (static device globals: allocation-free) ----------
__device__ __half g_xw2[NN * HC];         // layer GEMM output (fp16)
__device__ float  g_al_src[NN * H_];
__device__ float  g_al_dst[NN * H_];
__device__ float  g_alpha_s[(size_t)H_ * NE];  // leaky logits, SoA CSR-sorted
__device__ float  g_s1[(size_t)H_ * NE];       // raw edge logits layer1 (SoA)
__device__ float  g_s2[(size_t)H_ * NE];       // raw edge logits layer2 (SoA)
__device__ float  g_V1[EDIM * H_];
__device__ float  g_V2[EDIM * H_];
__device__ int    g_deg[NN];
__device__ int    g_rowptr[NN + 1];
__device__ int    g_cursor[NN];
__device__ int    g_esorted[NE];
__device__ int    g_src_s[NE];            // src node per sorted position
__device__ int    g_dst_s[NE];            // dst node per sorted position
__device__ int    g_bsum[40];
__device__ int    g_boff[40];
__device__ __half g_Asp[(size_t)MPAD * HC];     // GEMM A operand (fp16)
__device__ __half g_BtF[(size_t)DOUT * HC];     // Wf^T fp16 [25088,1024]
__device__ __half g_Bt2[(size_t)HC * HC];       // W2^T fp16 [1024,1024]
__device__ __half g_Bt1[(size_t)HC * DIN];      // W1^T fp16 [1024,128]

// ---------------- graph structure kernels ----------------------------------
__global__ void k_zero_deg() {
    int i = blockIdx.x * blockDim.x + threadIdx.x;
    if (i < NN) g_deg[i] = 0;
}

__global__ void k_count(const int* __restrict__ dst) {
    int e = blockIdx.x * blockDim.x + threadIdx.x;
    if (e < NE) atomicAdd(&g_deg[dst[e]], 1);
}

// 3-stage parallel scan of g_deg -> g_rowptr/g_cursor
__global__ void k_scanA() {
    __shared__ int sh[256];
    int i = blockIdx.x * 256 + threadIdx.x;
    sh[threadIdx.x] = (i < NN) ? g_deg[i] : 0;
    __syncthreads();
    for (int off = 128; off; off >>= 1) {
        if (threadIdx.x < off) sh[threadIdx.x] += sh[threadIdx.x + off];
        __syncthreads();
    }
    if (threadIdx.x == 0) g_bsum[blockIdx.x] = sh[0];
}

__global__ void k_scanB() {
    __shared__ int sh[64];
    int t = threadIdx.x;
    int v = (t < 40) ? g_bsum[t] : 0;
    sh[t] = v;
    __syncthreads();
    for (int off = 1; off < 64; off <<= 1) {
        int x = (t >= off) ? sh[t - off] : 0;
        __syncthreads();
        sh[t] += x;
        __syncthreads();
    }
    if (t < 40) g_boff[t] = sh[t] - v;
    if (t == 39) g_rowptr[NN] = sh[39];
}

__global__ void k_scanC() {
    __shared__ int sh[256];
    int i = blockIdx.x * 256 + threadIdx.x;
    int v = (i < NN) ? g_deg[i] : 0;
    sh[threadIdx.x] = v;
    __syncthreads();
    for (int off = 1; off < 256; off <<= 1) {
        int x = (threadIdx.x >= off) ? sh[threadIdx.x - off] : 0;
        __syncthreads();
        sh[threadIdx.x] += x;
        __syncthreads();
    }
    if (i < NN) {
        int excl = sh[threadIdx.x] - v + g_boff[blockIdx.x];
        g_rowptr[i] = excl;
        g_cursor[i] = excl;
    }
}

__global__ void k_fill(const int* __restrict__ dst) {
    int e = blockIdx.x * blockDim.x + threadIdx.x;
    if (e < NE) {
        int p = atomicAdd(&g_cursor[dst[e]], 1);
        g_esorted[p] = e;
    }
}

// ---------------- attention logit pieces ------------------------------------
__global__ void k_al(const __half* __restrict__ xw2,
                     const float* __restrict__ asrc, const float* __restrict__ adst) {
    int n = blockIdx.x;
    int w = threadIdx.x >> 5, l = threadIdx.x & 31;
    const __half2* row = reinterpret_cast<const __half2*>(xw2 + (size_t)n * HC + w * C_);
    const float* as  = asrc + w * C_;
    const float* ad  = adst + w * C_;
    float s = 0.f, d = 0.f;
    for (int c2 = l; c2 < C_ / 2; c2 += 32) {
        __half2 h = row[c2];
        float x0 = __low2float(h), x1 = __high2float(h);
        s += x0 * as[2 * c2] + x1 * as[2 * c2 + 1];
        d += x0 * ad[2 * c2] + x1 * ad[2 * c2 + 1];
    }
#pragma unroll
    for (int off = 16; off; off >>= 1) {
        s += __shfl_xor_sync(0xffffffffu, s, off);
        d += __shfl_xor_sync(0xffffffffu, d, off);
    }
    if (l == 0) { g_al_src[n * H_ + w] = s; g_al_dst[n * H_ + w] = d; }
}

__global__ void k_V(const float* __restrict__ We, const float* __restrict__ aedge,
                    float* __restrict__ Vout) {
    int w = threadIdx.x >> 5, l = threadIdx.x & 31;
    for (int o = w; o < EDIM * H_; o += 8) {
        int d = o / H_, h = o % H_;
        float s = 0.f;
        for (int c = l; c < C_; c += 32)
            s += We[(size_t)d * HC + h * C_ + c] * aedge[h * C_ + c];
#pragma unroll
        for (int off = 16; off; off >>= 1) s += __shfl_xor_sync(0xffffffffu, s, off);
        if (l == 0) Vout[o] = s;
    }
}

// One pass over CSR-sorted positions (layer-independent): gathers edge
// features once, emits src/dst ids + raw edge logits for BOTH layers.
__global__ void k_edgeprep(const float* __restrict__ ef, const int* __restrict__ src,
                           const int* __restrict__ dst) {
    __shared__ float sV1[EDIM * H_], sV2[EDIM * H_];
    if (threadIdx.x < EDIM * H_) {
        sV1[threadIdx.x] = g_V1[threadIdx.x];
        sV2[threadIdx.x] = g_V2[threadIdx.x];
    }
    __syncthreads();
    int i = blockIdx.x * blockDim.x + threadIdx.x;
    if (i >= NE) return;
    int e  = g_esorted[i];
    g_src_s[i] = src[e];
    g_dst_s[i] = dst[e];
    float ea[EDIM];
    const float4* efp = reinterpret_cast<const float4*>(ef + (size_t)e * EDIM);
#pragma unroll
    for (int q = 0; q < EDIM / 4; q++) {
        float4 v = efp[q];
        ea[q * 4 + 0] = v.x; ea[q * 4 + 1] = v.y; ea[q * 4 + 2] = v.z; ea[q * 4 + 3] = v.w;
    }
#pragma unroll
    for (int h = 0; h < H_; h++) {
        float s1 = 0.f, s2 = 0.f;
#pragma unroll
        for (int d = 0; d < EDIM; d++) {
            s1 += ea[d] * sV1[d * H_ + h];
            s2 += ea[d] * sV2[d * H_ + h];
        }
        g_s1[(size_t)h * NE + i] = s1;
        g_s2[(size_t)h * NE + i] = s2;
    }
}

// Per-layer: alpha = leaky(al_src[sn] + al_dst[dn] + s).  All coalesced except
// the small L2-resident al_* float4 gathers.
__global__ void k_alphaL(const float* __restrict__ sL) {
    int i = blockIdx.x * blockDim.x + threadIdx.x;
    if (i >= NE) return;
    float4 as = *reinterpret_cast<const float4*>(g_al_src + g_src_s[i] * H_);
    float4 ad = *reinterpret_cast<const float4*>(g_al_dst + g_dst_s[i] * H_);
    float base[H_] = {as.x + ad.x, as.y + ad.y, as.z + ad.z, as.w + ad.w};
#pragma unroll
    for (int h = 0; h < H_; h++) {
        float v = base[h] + sL[(size_t)h * NE + i];
        g_alpha_s[(size_t)h * NE + i] = v > 0.f ? v : 0.2f * v;
    }
}

// ---------------- segment softmax + aggregation (1 block / node) ------------
__global__ void __launch_bounds__(256)
k_aggregate(const __half* __restrict__ xw2, const float* __restrict__ sL,
            const float* __restrict__ bias, __half* __restrict__ outH) {
    int n = blockIdx.x;
    int beg = g_rowptr[n], end = g_rowptr[n + 1];
    __shared__ float sm[H_], ss[H_], sself[H_];
    int t = threadIdx.x, w = t >> 5, l = t & 31;

    // phase 0+1 fused: esum (raw s) and max (leaky alpha) in one pass
    if (w < H_) {
        const float* ssrc = sL + (size_t)w * NE;
        const float* as   = g_alpha_s + (size_t)w * NE;
        float es = 0.f, mx = -1e30f;
        for (int i = beg + l; i < end; i += 32) {
            es += ssrc[i];
            mx = fmaxf(mx, as[i]);
        }
#pragma unroll
        for (int off = 16; off; off >>= 1) {
            es += __shfl_xor_sync(0xffffffffu, es, off);
            mx = fmaxf(mx, __shfl_xor_sync(0xffffffffu, mx, off));
        }
        if (l == 0) {
            float invd = 1.0f / fmaxf((float)(end - beg), 1.0f);
            float v = g_al_src[n * H_ + w] + g_al_dst[n * H_ + w] + es * invd;
            v = v > 0.f ? v : 0.2f * v;
            sself[w] = v;
            sm[w] = fmaxf(mx, v);
        }
    }
    __syncthreads();

    // phase 2: exp + sum; overwrite alpha_s with exp values
    if (w < H_) {
        float mm = sm[w];
        float* as = g_alpha_s + (size_t)w * NE;
        float acc = (l == 0) ? expf(sself[w] - mm) : 0.f;
        for (int i = beg + l; i < end; i += 32) {
            float ex = expf(as[i] - mm);
            as[i] = ex;
            acc += ex;
        }
#pragma unroll
        for (int off = 16; off; off >>= 1) acc += __shfl_xor_sync(0xffffffffu, acc, off);
        if (l == 0) ss[w] = acc;
    }
    __syncthreads();

    // phase 3: weighted gather. thread t owns channels 4t..4t+3 (head h = t>>6).
    const int h = t >> 6;
    const float inv = 1.0f / (ss[h] + 1e-16f);
    const float* ash = g_alpha_s + (size_t)h * NE;
    float a0 = 0.f, a1 = 0.f, a2 = 0.f, a3 = 0.f;
    for (int i = beg; i < end; i++) {
        int sn = g_src_s[i];
        float wg = ash[i];
        uint2 rv = *reinterpret_cast<const uint2*>(xw2 + (size_t)sn * HC + 4 * t);
        __half2 p0 = *reinterpret_cast<__half2*>(&rv.x);
        __half2 p1 = *reinterpret_cast<__half2*>(&rv.y);
        a0 += wg * __low2float(p0); a1 += wg * __high2float(p0);
        a2 += wg * __low2float(p1); a3 += wg * __high2float(p1);
    }
    {   // self loop
        float wg = expf(sself[h] - sm[h]);
        uint2 rv = *reinterpret_cast<const uint2*>(xw2 + (size_t)n * HC + 4 * t);
        __half2 p0 = *reinterpret_cast<__half2*>(&rv.x);
        __half2 p1 = *reinterpret_cast<__half2*>(&rv.y);
        a0 += wg * __low2float(p0); a1 += wg * __high2float(p0);
        a2 += wg * __low2float(p1); a3 += wg * __high2float(p1);
    }
    float4 b4 = *reinterpret_cast<const float4*>(bias + 4 * t);
    float v0 = a0 * inv + b4.x, v1 = a1 * inv + b4.y;
    float v2 = a2 * inv + b4.z, v3 = a3 * inv + b4.w;
    v0 = v0 > 0.f ? v0 : expm1f(v0);
    v1 = v1 > 0.f ? v1 : expm1f(v1);
    v2 = v2 > 0.f ? v2 : expm1f(v2);
    v3 = v3 > 0.f ? v3 : expm1f(v3);
    uint2 ov;
    *reinterpret_cast<__half2*>(&ov.x) = __floats2half2_rn(v0, v1);
    *reinterpret_cast<__half2*>(&ov.y) = __floats2half2_rn(v2, v3);
    *reinterpret_cast<uint2*>(outH + (size_t)n * HC + 4 * t) = ov;
}

// ---------------- fp16 conversions ------------------------------------------
__global__ void k_convA(const float* __restrict__ src, __half* __restrict__ dst,
                        int Mv, int K) {
    int i = blockIdx.x * blockDim.x + threadIdx.x;
    if (i >= MPAD * K) return;
    int m = i / K, k = i - m * K;
    float a = (m < Mv) ? src[(size_t)m * K + k] : 0.f;
    dst[(size_t)m * K + k] = __float2half(a);
}

__global__ void k_convB(const float* __restrict__ W, __half* __restrict__ dst,
                        int K, int Nn) {
    __shared__ float t[32][33];
    int n = blockIdx.x * 32 + threadIdx.x;
    int k = blockIdx.y * 32 + threadIdx.y;
    t[threadIdx.y][threadIdx.x] = W[(size_t)k * Nn + n];
    __syncthreads();
    int n2 = blockIdx.x * 32 + threadIdx.y;
    int k2 = blockIdx.y * 32 + threadIdx.x;
    dst[(size_t)n2 * K + k2] = __float2half(t[threadIdx.x][threadIdx.y]);
}

// ---------------- fp16 HMMA GEMM --------------------------------------------
// CTA tile 128x128, 128 threads (4 warps, warp tile 64x64), BK=32,
// 4-stage cp.async pipeline (64 KB smem), 2 CTAs/SM.

__device__ __forceinline__ uint32_t s2u(const void* p) {
    uint32_t a;
    asm("{ .reg .u64 t; cvta.to.shared.u64 t, %1; cvt.u32.u64 %0, t; }" : "=r"(a) : "l"(p));
    return a;
}

__device__ __forceinline__ void cp16(uint32_t saddr, const void* gptr) {
    asm volatile("cp.async.cg.shared.global [%0], [%1], 16;" :: "r"(saddr), "l"(gptr));
}

#define LDSM4(r, addr) \
    asm volatile("ldmatrix.sync.aligned.m8n8.x4.shared.b16 {%0,%1,%2,%3}, [%4];" \
        : "=r"((r)[0]), "=r"((r)[1]), "=r"((r)[2]), "=r"((r)[3]) : "r"(addr))

#define MMA16816(c, a, b0, b1) \
    asm volatile("mma.sync.aligned.m16n8k16.row.col.f32.f16.f16.f32 " \
        "{%0,%1,%2,%3}, {%4,%5,%6,%7}, {%8,%9}, {%0,%1,%2,%3};" \
        : "+f"((c)[0]), "+f"((c)[1]), "+f"((c)[2]), "+f"((c)[3]) \
        : "r"((a)[0]), "r"((a)[1]), "r"((a)[2]), "r"((a)[3]), "r"(b0), "r"(b1))

constexpr int STAGE_BYTES = 16384;              // A 8KB + B 8KB
constexpr int MMA_SMEM    = 4 * STAGE_BYTES;    // 64 KB

template <bool BIAS>
__global__ void __launch_bounds__(128, 2)
k_mma_gemm(const __half* __restrict__ A, const __half* __restrict__ B,
           const float* __restrict__ bias, float* __restrict__ outF,
           __half* __restrict__ outH, int Mv, int K, int ldo) {
    extern __shared__ char smem[];
    const uint32_t sb = s2u(smem);
    const int tid  = threadIdx.x;
    const int lane = tid & 31, wid = tid >> 5;
    const int wm = (wid & 1) * 64, wn = (wid >> 1) * 64;
    const int bm = blockIdx.x * 128, bn = blockIdx.y * 128;
    const int KITER = K >> 5;

    const __half* ag0 = A + (size_t)bm * K;
    const __half* bg0 = B + (size_t)bn * K;

    auto load_stage = [&](int kt, int slot) {
        const int k0 = kt * 32;
        const uint32_t sa  = sb + slot * STAGE_BYTES;
        const uint32_t sbm = sa + 8192;
#pragma unroll
        for (int i = 0; i < 4; i++) {
            int u = tid + i * 128;
            int row = u >> 2, seg = u & 3;
            uint32_t off = row * 64 + ((seg ^ ((row >> 1) & 3)) << 4);
            cp16(sa  + off, ag0 + (size_t)row * K + k0 + seg * 8);
            cp16(sbm + off, bg0 + (size_t)row * K + k0 + seg * 8);
        }
    };

    float acc[4][8][4];
#pragma unroll
    for (int i = 0; i < 4; i++)
#pragma unroll
        for (int j = 0; j < 8; j++)
#pragma unroll
            for (int r = 0; r < 4; r++) acc[i][j][r] = 0.f;

    load_stage(0, 0);
    asm volatile("cp.async.commit_group;" ::: "memory");
    load_stage(1, 1);
    asm volatile("cp.async.commit_group;" ::: "memory");
    load_stage(2, 2);
    asm volatile("cp.async.commit_group;" ::: "memory");

    for (int kt = 0; kt < KITER; kt++) {
        asm volatile("cp.async.wait_group 2;" ::: "memory");
        __syncthreads();
        if (kt + 3 < KITER) load_stage(kt + 3, (kt + 3) & 3);
        asm volatile("cp.async.commit_group;" ::: "memory");

        const uint32_t sa  = sb + (kt & 3) * STAGE_BYTES;
        const uint32_t sbm = sa + 8192;
#pragma unroll
        for (int ks2 = 0; ks2 < 2; ks2++) {
            uint32_t av[4][4], bv[4][4];
            const int segk = ks2 * 2 + (lane >> 4);
#pragma unroll
            for (int mf = 0; mf < 4; mf++) {
                int row = wm + mf * 16 + (lane & 15);
                LDSM4(av[mf], sa + row * 64 + ((segk ^ ((row >> 1) & 3)) << 4));
            }
#pragma unroll
            for (int p = 0; p < 4; p++) {
                int row = wn + p * 16 + (lane & 15);
                LDSM4(bv[p], sbm + row * 64 + ((segk ^ ((row >> 1) & 3)) << 4));
            }
#pragma unroll
            for (int mf = 0; mf < 4; mf++)
#pragma unroll
                for (int p = 0; p < 4; p++) {
                    MMA16816(acc[mf][p * 2 + 0], av[mf], bv[p][0], bv[p][2]);
                    MMA16816(acc[mf][p * 2 + 1], av[mf], bv[p][1], bv[p][3]);
                }
        }
    }

    // epilogue
    const int r0 = lane >> 2, c0 = (lane & 3) * 2;
#pragma unroll
    for (int mf = 0; mf < 4; mf++) {
#pragma unroll
        for (int half = 0; half < 2; half++) {
            int m = bm + wm + mf * 16 + r0 + half * 8;
            if (m >= Mv) continue;
#pragma unroll
            for (int nf = 0; nf < 8; nf++) {
                int n = bn + wn + nf * 8 + c0;
                float vx = acc[mf][nf][half * 2 + 0];
                float vy = acc[mf][nf][half * 2 + 1];
                if (BIAS) {
                    vx += __ldg(bias + n); vy += __ldg(bias + n + 1);
                    *reinterpret_cast<float2*>(outF + (size_t)m * ldo + n) =
                        make_float2(vx, vy);
                } else {
                    *reinterpret_cast<__half2*>(outH + (size_t)m * ldo + n) =
                        __floats2half2_rn(vx, vy);
                }
            }
        }
    }
}

// ---------------- launch -----------------------------------------------------
extern "C" void kernel_launch(void* const* d_in, const int* in_sizes, int n_in,
                              void* d_out, int out_size) {
    const float* x      = (const float*)d_in[0];
    const int*   ei     = (const int*)d_in[1];
    const float* ef     = (const float*)d_in[2];
    const float* W1     = (const float*)d_in[3];
    const float* asrc1  = (const float*)d_in[4];
    const float* adst1  = (const float*)d_in[5];
    const float* aedge1 = (const float*)d_in[6];
    const float* We1    = (const float*)d_in[7];
    const float* b1     = (const float*)d_in[8];
    const float* W2     = (const float*)d_in[9];
    const float* asrc2  = (const float*)d_in[10];
    const float* adst2  = (const float*)d_in[11];
    const float* aedge2 = (const float*)d_in[12];
    const float* We2    = (const float*)d_in[13];
    const float* b2     = (const float*)d_in[14];
    const float* Wf     = (const float*)d_in[15];
    const float* bf     = (const float*)d_in[16];
    const int* src = ei;
    const int* dst = ei + NE;
    float* out = (float*)d_out;

    void* p;
    cudaGetSymbolAddress(&p, g_xw2); __half* xw2 = (__half*)p;
    cudaGetSymbolAddress(&p, g_Asp); __half* Asp = (__half*)p;
    cudaGetSymbolAddress(&p, g_BtF); __half* BtF = (__half*)p;
    cudaGetSymbolAddress(&p, g_Bt2); __half* Bt2 = (__half*)p;
    cudaGetSymbolAddress(&p, g_Bt1); __half* Bt1 = (__half*)p;
    cudaGetSymbolAddress(&p, g_V1);  float* V1  = (float*)p;
    cudaGetSymbolAddress(&p, g_V2);  float* V2  = (float*)p;
    cudaGetSymbolAddress(&p, g_s1);  float* s1p = (float*)p;
    cudaGetSymbolAddress(&p, g_s2);  float* s2p = (float*)p;

    static bool init_done = false;
    static cudaStream_t s1;
    static cudaEvent_t evFork, evB12, evPre, evBF;
    if (!init_done) {
        cudaFuncSetAttribute((const void*)k_mma_gemm<true>,
                             cudaFuncAttributeMaxDynamicSharedMemorySize, MMA_SMEM);
        cudaFuncSetAttribute((const void*)k_mma_gemm<false>,
                             cudaFuncAttributeMaxDynamicSharedMemorySize, MMA_SMEM);
        cudaStreamCreateWithFlags(&s1, cudaStreamNonBlocking);
        cudaEventCreateWithFlags(&evFork, cudaEventDisableTiming);
        cudaEventCreateWithFlags(&evB12,  cudaEventDisableTiming);
        cudaEventCreateWithFlags(&evPre,  cudaEventDisableTiming);
        cudaEventCreateWithFlags(&evBF,   cudaEventDisableTiming);
        init_done = true;
    }

    // fork side stream
    cudaEventRecord(evFork, 0);
    cudaStreamWaitEvent(s1, evFork, 0);

    // side: layer weights first (GEMM1 needs Bt1)
    k_convB<<<dim3(HC / 32, DIN / 32), dim3(32, 32), 0, s1>>>(W1, Bt1, DIN, HC);
    k_convB<<<dim3(HC / 32, HC / 32), dim3(32, 32), 0, s1>>>(W2, Bt2, HC, HC);
    cudaEventRecord(evB12, s1);
    // side: V's + CSR + edge prep (layer-activation independent)
    k_V<<<1, 256, 0, s1>>>(We1, aedge1, V1);
    k_V<<<1, 256, 0, s1>>>(We2, aedge2, V2);
    k_zero_deg<<<(NN + 255) / 256, 256, 0, s1>>>();
    k_count<<<(NE + 255) / 256, 256, 0, s1>>>(dst);
    k_scanA<<<40, 256, 0, s1>>>();
    k_scanB<<<1, 64, 0, s1>>>();
    k_scanC<<<40, 256, 0, s1>>>();
    k_fill<<<(NE + 255) / 256, 256, 0, s1>>>(dst);
    k_edgeprep<<<(NE + 255) / 256, 256, 0, s1>>>(ef, src, dst);
    cudaEventRecord(evPre, s1);
    // side: big final-weight conversion (joins before final GEMM)
    k_convB<<<dim3(DOUT / 32, HC / 32), dim3(32, 32), 0, s1>>>(Wf, BtF, HC, DOUT);
    cudaEventRecord(evBF, s1);

    // main: layer-1 A conversion overlaps all of the above
    k_convA<<<(MPAD * DIN + 255) / 256, 256>>>(x, Asp, NN, DIN);

    // ---- layer 1 ----
    cudaStreamWaitEvent(0, evB12, 0);
    k_mma_gemm<false><<<dim3(MPAD / 128, HC / 128), 128, MMA_SMEM>>>(
        Asp, Bt1, nullptr, nullptr, xw2, NN, DIN, HC);
    k_al<<<NN, 128>>>(xw2, asrc1, adst1);
    cudaStreamWaitEvent(0, evPre, 0);
    k_alphaL<<<(NE + 255) / 256, 256>>>(s1p);
    k_aggregate<<<NN, 256>>>(xw2, s1p, b1, Asp);

    // ---- layer 2 ----
    k_mma_gemm<false><<<dim3(MPAD / 128, HC / 128), 128, MMA_SMEM>>>(
        Asp, Bt2, nullptr, nullptr, xw2, NN, HC, HC);
    k_al<<<NN, 128>>>(xw2, asrc2, adst2);
    k_alphaL<<<(NE + 255) / 256, 256>>>(s2p);
    k_aggregate<<<NN, 256>>>(xw2, s2p, b2, Asp);

    // ---- final linear: out = h2 @ Wf + bf ----
    cudaStreamWaitEvent(0, evBF, 0);
    k_mma_gemm<true><<<dim3(MPAD / 128, DOUT / 128), 128, MMA_SMEM>>>(
        Asp, BtF, bf, out, nullptr, NN, HC, DOUT);
}

// round 14
// speedup vs baseline: 6.9373x; 1.0007x over previous
#include <cuda_runtime.h>
#include <cuda_fp16.h>
#include <math.h>
#include <stdint.h>

// Problem constants (fixed shapes per metadata)
constexpr int NN   = 10000;   // nodes
constexpr int NE   = 160000;  // edges
constexpr int DIN  = 128;     // input feature dim
constexpr int EDIM = 16;      // edge feature dim
constexpr int H_   = 4;       // heads
constexpr int C_   = 256;     // channels per head
constexpr int HC   = 1024;    // H*C
constexpr int DOUT = 25088;   // final output dim

constexpr int MPAD = 10112;   // 79 * 128 (M padded)

// ---------------- scratch (static device globals: allocation-free) ----------
__device__ __half g_xw2[NN * HC];         // layer GEMM output (fp16)
__device__ float  g_al_src[NN * H_];
__device__ float  g_al_dst[NN * H_];
__device__ float  g_exp_s[(size_t)H_ * NE];    // exp(alpha-max), SoA CSR-sorted
__device__ float  g_s1[(size_t)H_ * NE];       // raw edge logits layer1 (SoA)
__device__ float  g_s2[(size_t)H_ * NE];       // raw edge logits layer2 (SoA)
__device__ float  g_V1[EDIM * H_];
__device__ float  g_V2[EDIM * H_];
__device__ int    g_deg[NN];
__device__ int    g_rowptr[NN + 1];
__device__ int    g_cursor[NN];
__device__ int    g_esorted[NE];
__device__ int    g_src_s[NE];            // src node per sorted position
__device__ int    g_bsum[40];
__device__ int    g_boff[40];
__device__ __half g_Asp[(size_t)MPAD * HC];     // GEMM A operand (fp16)
__device__ __half g_BtF[(size_t)DOUT * HC];     // Wf^T fp16 [25088,1024]
__device__ __half g_Bt2[(size_t)HC * HC];       // W2^T fp16 [1024,1024]
__device__ __half g_Bt1[(size_t)HC * DIN];      // W1^T fp16 [1024,128]

// ---------------- graph structure kernels ----------------------------------
__global__ void k_zero_deg() {
    int i = blockIdx.x * blockDim.x + threadIdx.x;
    if (i < NN) g_deg[i] = 0;
}

__global__ void k_count(const int* __restrict__ dst) {
    int e = blockIdx.x * blockDim.x + threadIdx.x;
    if (e < NE) atomicAdd(&g_deg[dst[e]], 1);
}

// 3-stage parallel scan of g_deg -> g_rowptr/g_cursor
__global__ void k_scanA() {
    __shared__ int sh[256];
    int i = blockIdx.x * 256 + threadIdx.x;
    sh[threadIdx.x] = (i < NN) ? g_deg[i] : 0;
    __syncthreads();
    for (int off = 128; off; off >>= 1) {
        if (threadIdx.x < off) sh[threadIdx.x] += sh[threadIdx.x + off];
        __syncthreads();
    }
    if (threadIdx.x == 0) g_bsum[blockIdx.x] = sh[0];
}

__global__ void k_scanB() {
    __shared__ int sh[64];
    int t = threadIdx.x;
    int v = (t < 40) ? g_bsum[t] : 0;
    sh[t] = v;
    __syncthreads();
    for (int off = 1; off < 64; off <<= 1) {
        int x = (t >= off) ? sh[t - off] : 0;
        __syncthreads();
        sh[t] += x;
        __syncthreads();
    }
    if (t < 40) g_boff[t] = sh[t] - v;
    if (t == 39) g_rowptr[NN] = sh[39];
}

__global__ void k_scanC() {
    __shared__ int sh[256];
    int i = blockIdx.x * 256 + threadIdx.x;
    int v = (i < NN) ? g_deg[i] : 0;
    sh[threadIdx.x] = v;
    __syncthreads();
    for (int off = 1; off < 256; off <<= 1) {
        int x = (threadIdx.x >= off) ? sh[threadIdx.x - off] : 0;
        __syncthreads();
        sh[threadIdx.x] += x;
        __syncthreads();
    }
    if (i < NN) {
        int excl = sh[threadIdx.x] - v + g_boff[blockIdx.x];
        g_rowptr[i] = excl;
        g_cursor[i] = excl;
    }
}

__global__ void k_fill(const int* __restrict__ dst) {
    int e = blockIdx.x * blockDim.x + threadIdx.x;
    if (e < NE) {
        int p = atomicAdd(&g_cursor[dst[e]], 1);
        g_esorted[p] = e;
    }
}

// ---------------- attention logit pieces ------------------------------------
__global__ void k_al(const __half* __restrict__ xw2,
                     const float* __restrict__ asrc, const float* __restrict__ adst) {
    int n = blockIdx.x;
    int w = threadIdx.x >> 5, l = threadIdx.x & 31;
    const __half2* row = reinterpret_cast<const __half2*>(xw2 + (size_t)n * HC + w * C_);
    const float* as  = asrc + w * C_;
    const float* ad  = adst + w * C_;
    float s = 0.f, d = 0.f;
    for (int c2 = l; c2 < C_ / 2; c2 += 32) {
        __half2 h = row[c2];
        float x0 = __low2float(h), x1 = __high2float(h);
        s += x0 * as[2 * c2] + x1 * as[2 * c2 + 1];
        d += x0 * ad[2 * c2] + x1 * ad[2 * c2 + 1];
    }
#pragma unroll
    for (int off = 16; off; off >>= 1) {
        s += __shfl_xor_sync(0xffffffffu, s, off);
        d += __shfl_xor_sync(0xffffffffu, d, off);
    }
    if (l == 0) { g_al_src[n * H_ + w] = s; g_al_dst[n * H_ + w] = d; }
}

__global__ void k_V(const float* __restrict__ We, const float* __restrict__ aedge,
                    float* __restrict__ Vout) {
    int w = threadIdx.x >> 5, l = threadIdx.x & 31;
    for (int o = w; o < EDIM * H_; o += 8) {
        int d = o / H_, h = o % H_;
        float s = 0.f;
        for (int c = l; c < C_; c += 32)
            s += We[(size_t)d * HC + h * C_ + c] * aedge[h * C_ + c];
#pragma unroll
        for (int off = 16; off; off >>= 1) s += __shfl_xor_sync(0xffffffffu, s, off);
        if (l == 0) Vout[o] = s;
    }
}

// One pass over CSR-sorted positions (layer-independent): gathers edge
// features once, emits src ids + raw edge logits for BOTH layers.
__global__ void k_edgeprep(const float* __restrict__ ef, const int* __restrict__ src) {
    __shared__ float sV1[EDIM * H_], sV2[EDIM * H_];
    if (threadIdx.x < EDIM * H_) {
        sV1[threadIdx.x] = g_V1[threadIdx.x];
        sV2[threadIdx.x] = g_V2[threadIdx.x];
    }
    __syncthreads();
    int i = blockIdx.x * blockDim.x + threadIdx.x;
    if (i >= NE) return;
    int e  = g_esorted[i];
    g_src_s[i] = src[e];
    float ea[EDIM];
    const float4* efp = reinterpret_cast<const float4*>(ef + (size_t)e * EDIM);
#pragma unroll
    for (int q = 0; q < EDIM / 4; q++) {
        float4 v = efp[q];
        ea[q * 4 + 0] = v.x; ea[q * 4 + 1] = v.y; ea[q * 4 + 2] = v.z; ea[q * 4 + 3] = v.w;
    }
#pragma unroll
    for (int h = 0; h < H_; h++) {
        float s1 = 0.f, s2 = 0.f;
#pragma unroll
        for (int d = 0; d < EDIM; d++) {
            s1 += ea[d] * sV1[d * H_ + h];
            s2 += ea[d] * sV2[d * H_ + h];
        }
        g_s1[(size_t)h * NE + i] = s1;
        g_s2[(size_t)h * NE + i] = s2;
    }
}

// ---------------- segment softmax + aggregation (1 block / node) ------------
// Alpha is recomputed on the fly from raw logits (no separate alpha pass):
//   alpha[i,h] = leaky(al_src[src_s[i]][h] + al_dst[n][h] + sL[h][i])
// Phase 0/1: esum + max.  Phase 2: exp store + sum.  Phase 3: weighted gather.
__global__ void __launch_bounds__(256)
k_aggregate(const __half* __restrict__ xw2, const float* __restrict__ sL,
            const float* __restrict__ bias, __half* __restrict__ outH) {
    int n = blockIdx.x;
    int beg = g_rowptr[n], end = g_rowptr[n + 1];
    __shared__ float sm[H_], ss[H_], sself[H_];
    int t = threadIdx.x, w = t >> 5, l = t & 31;

    // phase 0+1 fused: esum (raw s) and max (leaky alpha, computed on the fly)
    if (w < H_) {
        const float* ssrc = sL + (size_t)w * NE;
        const float ald = g_al_dst[n * H_ + w];
        float es = 0.f, mx = -1e30f;
        for (int i = beg + l; i < end; i += 32) {
            float s = ssrc[i];
            es += s;
            float a = g_al_src[g_src_s[i] * H_ + w] + ald + s;
            a = a > 0.f ? a : 0.2f * a;
            mx = fmaxf(mx, a);
        }
#pragma unroll
        for (int off = 16; off; off >>= 1) {
            es += __shfl_xor_sync(0xffffffffu, es, off);
            mx = fmaxf(mx, __shfl_xor_sync(0xffffffffu, mx, off));
        }
        if (l == 0) {
            float invd = 1.0f / fmaxf((float)(end - beg), 1.0f);
            float v = g_al_src[n * H_ + w] + ald + es * invd;
            v = v > 0.f ? v : 0.2f * v;
            sself[w] = v;
            sm[w] = fmaxf(mx, v);
        }
    }
    __syncthreads();

    // phase 2: recompute alpha, exp, store exp for phase 3; accumulate sum
    if (w < H_) {
        float mm = sm[w];
        const float* ssrc = sL + (size_t)w * NE;
        const float ald = g_al_dst[n * H_ + w];
        float* ex_out = g_exp_s + (size_t)w * NE;
        float acc = (l == 0) ? expf(sself[w] - mm) : 0.f;
        for (int i = beg + l; i < end; i += 32) {
            float a = g_al_src[g_src_s[i] * H_ + w] + ald + ssrc[i];
            a = a > 0.f ? a : 0.2f * a;
            float ex = expf(a - mm);
            ex_out[i] = ex;
            acc += ex;
        }
#pragma unroll
        for (int off = 16; off; off >>= 1) acc += __shfl_xor_sync(0xffffffffu, acc, off);
        if (l == 0) ss[w] = acc;
    }
    __syncthreads();

    // phase 3: weighted gather. thread t owns channels 4t..4t+3 (head h = t>>6).
    const int h = t >> 6;
    const float inv = 1.0f / (ss[h] + 1e-16f);
    const float* exh = g_exp_s + (size_t)h * NE;
    float a0 = 0.f, a1 = 0.f, a2 = 0.f, a3 = 0.f;
    for (int i = beg; i < end; i++) {
        int sn = g_src_s[i];
        float wg = exh[i];
        uint2 rv = *reinterpret_cast<const uint2*>(xw2 + (size_t)sn * HC + 4 * t);
        __half2 p0 = *reinterpret_cast<__half2*>(&rv.x);
        __half2 p1 = *reinterpret_cast<__half2*>(&rv.y);
        a0 += wg * __low2float(p0); a1 += wg * __high2float(p0);
        a2 += wg * __low2float(p1); a3 += wg * __high2float(p1);
    }
    {   // self loop
        float wg = expf(sself[h] - sm[h]);
        uint2 rv = *reinterpret_cast<const uint2*>(xw2 + (size_t)n * HC + 4 * t);
        __half2 p0 = *reinterpret_cast<__half2*>(&rv.x);
        __half2 p1 = *reinterpret_cast<__half2*>(&rv.y);
        a0 += wg * __low2float(p0); a1 += wg * __high2float(p0);
        a2 += wg * __low2float(p1); a3 += wg * __high2float(p1);
    }
    float4 b4 = *reinterpret_cast<const float4*>(bias + 4 * t);
    float v0 = a0 * inv + b4.x, v1 = a1 * inv + b4.y;
    float v2 = a2 * inv + b4.z, v3 = a3 * inv + b4.w;
    v0 = v0 > 0.f ? v0 : expm1f(v0);
    v1 = v1 > 0.f ? v1 : expm1f(v1);
    v2 = v2 > 0.f ? v2 : expm1f(v2);
    v3 = v3 > 0.f ? v3 : expm1f(v3);
    uint2 ov;
    *reinterpret_cast<__half2*>(&ov.x) = __floats2half2_rn(v0, v1);
    *reinterpret_cast<__half2*>(&ov.y) = __floats2half2_rn(v2, v3);
    *reinterpret_cast<uint2*>(outH + (size_t)n * HC + 4 * t) = ov;
}

// ---------------- fp16 conversions ------------------------------------------
__global__ void k_convA(const float* __restrict__ src, __half* __restrict__ dst,
                        int Mv, int K) {
    int i = blockIdx.x * blockDim.x + threadIdx.x;
    if (i >= MPAD * K) return;
    int m = i / K, k = i - m * K;
    float a = (m < Mv) ? src[(size_t)m * K + k] : 0.f;
    dst[(size_t)m * K + k] = __float2half(a);
}

__global__ void k_convB(const float* __restrict__ W, __half* __restrict__ dst,
                        int K, int Nn) {
    __shared__ float t[32][33];
    int n = blockIdx.x * 32 + threadIdx.x;
    int k = blockIdx.y * 32 + threadIdx.y;
    t[threadIdx.y][threadIdx.x] = W[(size_t)k * Nn + n];
    __syncthreads();
    int n2 = blockIdx.x * 32 + threadIdx.y;
    int k2 = blockIdx.y * 32 + threadIdx.x;
    dst[(size_t)n2 * K + k2] = __float2half(t[threadIdx.x][threadIdx.y]);
}

// ---------------- fp16 HMMA GEMM --------------------------------------------
// CTA tile 128x128, 128 threads (4 warps, warp tile 64x64), BK=32,
// 4-stage cp.async pipeline (64 KB smem), 2 CTAs/SM.

__device__ __forceinline__ uint32_t s2u(const void* p) {
    uint32_t a;
    asm("{ .reg .u64 t; cvta.to.shared.u64 t, %1; cvt.u32.u64 %0, t; }" : "=r"(a) : "l"(p));
    return a;
}

__device__ __forceinline__ void cp16(uint32_t saddr, const void* gptr) {
    asm volatile("cp.async.cg.shared.global [%0], [%1], 16;" :: "r"(saddr), "l"(gptr));
}

#define LDSM4(r, addr) \
    asm volatile("ldmatrix.sync.aligned.m8n8.x4.shared.b16 {%0,%1,%2,%3}, [%4];" \
        : "=r"((r)[0]), "=r"((r)[1]), "=r"((r)[2]), "=r"((r)[3]) : "r"(addr))

#define MMA16816(c, a, b0, b1) \
    asm volatile("mma.sync.aligned.m16n8k16.row.col.f32.f16.f16.f32 " \
        "{%0,%1,%2,%3}, {%4,%5,%6,%7}, {%8,%9}, {%0,%1,%2,%3};" \
        : "+f"((c)[0]), "+f"((c)[1]), "+f"((c)[2]), "+f"((c)[3]) \
        : "r"((a)[0]), "r"((a)[1]), "r"((a)[2]), "r"((a)[3]), "r"(b0), "r"(b1))

constexpr int STAGE_BYTES = 16384;              // A 8KB + B 8KB
constexpr int MMA_SMEM    = 4 * STAGE_BYTES;    // 64 KB

template <bool BIAS>
__global__ void __launch_bounds__(128, 2)
k_mma_gemm(const __half* __restrict__ A, const __half* __restrict__ B,
           const float* __restrict__ bias, float* __restrict__ outF,
           __half* __restrict__ outH, int Mv, int K, int ldo) {
    extern __shared__ char smem[];
    const uint32_t sb = s2u(smem);
    const int tid  = threadIdx.x;
    const int lane = tid & 31, wid = tid >> 5;
    const int wm = (wid & 1) * 64, wn = (wid >> 1) * 64;
    const int bm = blockIdx.x * 128, bn = blockIdx.y * 128;
    const int KITER = K >> 5;

    const __half* ag0 = A + (size_t)bm * K;
    const __half* bg0 = B + (size_t)bn * K;

    auto load_stage = [&](int kt, int slot) {
        const int k0 = kt * 32;
        const uint32_t sa  = sb + slot * STAGE_BYTES;
        const uint32_t sbm = sa + 8192;
#pragma unroll
        for (int i = 0; i < 4; i++) {
            int u = tid + i * 128;
            int row = u >> 2, seg = u & 3;
            uint32_t off = row * 64 + ((seg ^ ((row >> 1) & 3)) << 4);
            cp16(sa  + off, ag0 + (size_t)row * K + k0 + seg * 8);
            cp16(sbm + off, bg0 + (size_t)row * K + k0 + seg * 8);
        }
    };

    float acc[4][8][4];
#pragma unroll
    for (int i = 0; i < 4; i++)
#pragma unroll
        for (int j = 0; j < 8; j++)
#pragma unroll
            for (int r = 0; r < 4; r++) acc[i][j][r] = 0.f;

    load_stage(0, 0);
    asm volatile("cp.async.commit_group;" ::: "memory");
    load_stage(1, 1);
    asm volatile("cp.async.commit_group;" ::: "memory");
    load_stage(2, 2);
    asm volatile("cp.async.commit_group;" ::: "memory");

    for (int kt = 0; kt < KITER; kt++) {
        asm volatile("cp.async.wait_group 2;" ::: "memory");
        __syncthreads();
        if (kt + 3 < KITER) load_stage(kt + 3, (kt + 3) & 3);
        asm volatile("cp.async.commit_group;" ::: "memory");

        const uint32_t sa  = sb + (kt & 3) * STAGE_BYTES;
        const uint32_t sbm = sa + 8192;
#pragma unroll
        for (int ks2 = 0; ks2 < 2; ks2++) {
            uint32_t av[4][4], bv[4][4];
            const int segk = ks2 * 2 + (lane >> 4);
#pragma unroll
            for (int mf = 0; mf < 4; mf++) {
                int row = wm + mf * 16 + (lane & 15);
                LDSM4(av[mf], sa + row * 64 + ((segk ^ ((row >> 1) & 3)) << 4));
            }
#pragma unroll
            for (int p = 0; p < 4; p++) {
                int row = wn + p * 16 + (lane & 15);
                LDSM4(bv[p], sbm + row * 64 + ((segk ^ ((row >> 1) & 3)) << 4));
            }
#pragma unroll
            for (int mf = 0; mf < 4; mf++)
#pragma unroll
                for (int p = 0; p < 4; p++) {
                    MMA16816(acc[mf][p * 2 + 0], av[mf], bv[p][0], bv[p][2]);
                    MMA16816(acc[mf][p * 2 + 1], av[mf], bv[p][1], bv[p][3]);
                }
        }
    }

    // epilogue
    const int r0 = lane >> 2, c0 = (lane & 3) * 2;
#pragma unroll
    for (int mf = 0; mf < 4; mf++) {
#pragma unroll
        for (int half = 0; half < 2; half++) {
            int m = bm + wm + mf * 16 + r0 + half * 8;
            if (m >= Mv) continue;
#pragma unroll
            for (int nf = 0; nf < 8; nf++) {
                int n = bn + wn + nf * 8 + c0;
                float vx = acc[mf][nf][half * 2 + 0];
                float vy = acc[mf][nf][half * 2 + 1];
                if (BIAS) {
                    vx += __ldg(bias + n); vy += __ldg(bias + n + 1);
                    *reinterpret_cast<float2*>(outF + (size_t)m * ldo + n) =
                        make_float2(vx, vy);
                } else {
                    *reinterpret_cast<__half2*>(outH + (size_t)m * ldo + n) =
                        __floats2half2_rn(vx, vy);
                }
            }
        }
    }
}

// ---------------- launch -----------------------------------------------------
extern "C" void kernel_launch(void* const* d_in, const int* in_sizes, int n_in,
                              void* d_out, int out_size) {
    const float* x      = (const float*)d_in[0];
    const int*   ei     = (const int*)d_in[1];
    const float* ef     = (const float*)d_in[2];
    const float* W1     = (const float*)d_in[3];
    const float* asrc1  = (const float*)d_in[4];
    const float* adst1  = (const float*)d_in[5];
    const float* aedge1 = (const float*)d_in[6];
    const float* We1    = (const float*)d_in[7];
    const float* b1     = (const float*)d_in[8];
    const float* W2     = (const float*)d_in[9];
    const float* asrc2  = (const float*)d_in[10];
    const float* adst2  = (const float*)d_in[11];
    const float* aedge2 = (const float*)d_in[12];
    const float* We2    = (const float*)d_in[13];
    const float* b2     = (const float*)d_in[14];
    const float* Wf     = (const float*)d_in[15];
    const float* bf     = (const float*)d_in[16];
    const int* src = ei;
    const int* dst = ei + NE;
    float* out = (float*)d_out;

    void* p;
    cudaGetSymbolAddress(&p, g_xw2); __half* xw2 = (__half*)p;
    cudaGetSymbolAddress(&p, g_Asp); __half* Asp = (__half*)p;
    cudaGetSymbolAddress(&p, g_BtF); __half* BtF = (__half*)p;
    cudaGetSymbolAddress(&p, g_Bt2); __half* Bt2 = (__half*)p;
    cudaGetSymbolAddress(&p, g_Bt1); __half* Bt1 = (__half*)p;
    cudaGetSymbolAddress(&p, g_V1);  float* V1  = (float*)p;
    cudaGetSymbolAddress(&p, g_V2);  float* V2  = (float*)p;
    cudaGetSymbolAddress(&p, g_s1);  float* s1p = (float*)p;
    cudaGetSymbolAddress(&p, g_s2);  float* s2p = (float*)p;

    static bool init_done = false;
    static cudaStream_t s1;
    static cudaEvent_t evFork, evB12, evPre, evBF;
    if (!init_done) {
        cudaFuncSetAttribute((const void*)k_mma_gemm<true>,
                             cudaFuncAttributeMaxDynamicSharedMemorySize, MMA_SMEM);
        cudaFuncSetAttribute((const void*)k_mma_gemm<false>,
                             cudaFuncAttributeMaxDynamicSharedMemorySize, MMA_SMEM);
        cudaStreamCreateWithFlags(&s1, cudaStreamNonBlocking);
        cudaEventCreateWithFlags(&evFork, cudaEventDisableTiming);
        cudaEventCreateWithFlags(&evB12,  cudaEventDisableTiming);
        cudaEventCreateWithFlags(&evPre,  cudaEventDisableTiming);
        cudaEventCreateWithFlags(&evBF,   cudaEventDisableTiming);
        init_done = true;
    }

    // fork side stream
    cudaEventRecord(evFork, 0);
    cudaStreamWaitEvent(s1, evFork, 0);

    // side: layer weights first (GEMM1 needs Bt1)
    k_convB<<<dim3(HC / 32, DIN / 32), dim3(32, 32), 0, s1>>>(W1, Bt1, DIN, HC);
    k_convB<<<dim3(HC / 32, HC / 32), dim3(32, 32), 0, s1>>>(W2, Bt2, HC, HC);
    cudaEventRecord(evB12, s1);
    // side: V's + CSR + edge prep (layer-activation independent)
    k_V<<<1, 256, 0, s1>>>(We1, aedge1, V1);
    k_V<<<1, 256, 0, s1>>>(We2, aedge2, V2);
    k_zero_deg<<<(NN + 255) / 256, 256, 0, s1>>>();
    k_count<<<(NE + 255) / 256, 256, 0, s1>>>(dst);
    k_scanA<<<40, 256, 0, s1>>>();
    k_scanB<<<1, 64, 0, s1>>>();
    k_scanC<<<40, 256, 0, s1>>>();
    k_fill<<<(NE + 255) / 256, 256, 0, s1>>>(dst);
    k_edgeprep<<<(NE + 255) / 256, 256, 0, s1>>>(ef, src);
    cudaEventRecord(evPre, s1);
    // side: big final-weight conversion (joins before final GEMM)
    k_convB<<<dim3(DOUT / 32, HC / 32), dim3(32, 32), 0, s1>>>(Wf, BtF, HC, DOUT);
    cudaEventRecord(evBF, s1);

    // main: layer-1 A conversion overlaps all of the above
    k_convA<<<(MPAD * DIN + 255) / 256, 256>>>(x, Asp, NN, DIN);

    // ---- layer 1 ----
    cudaStreamWaitEvent(0, evB12, 0);
    k_mma_gemm<false><<<dim3(MPAD / 128, HC / 128), 128, MMA_SMEM>>>(
        Asp, Bt1, nullptr, nullptr, xw2, NN, DIN, HC);
    k_al<<<NN, 128>>>(xw2, asrc1, adst1);
    cudaStreamWaitEvent(0, evPre, 0);
    k_aggregate<<<NN, 256>>>(xw2, s1p, b1, Asp);

    // ---- layer 2 ----
    k_mma_gemm<false><<<dim3(MPAD / 128, HC / 128), 128, MMA_SMEM>>>(
        Asp, Bt2, nullptr, nullptr, xw2, NN, HC, HC);
    k_al<<<NN, 128>>>(xw2, asrc2, adst2);
    k_aggregate<<<NN, 256>>>(xw2, s2p, b2, Asp);

    // ---- final linear: out = h2 @ Wf + bf ----
    cudaStreamWaitEvent(0, evBF, 0);
    k_mma_gemm<true><<<dim3(MPAD / 128, DOUT / 128), 128, MMA_SMEM>>>(
        Asp, BtF, bf, out, nullptr, NN, HC, DOUT);
}

// round 15
// speedup vs baseline: 6.9557x; 1.0027x over previous
#include <cuda_runtime.h>
#include <cuda_fp16.h>
#include <math.h>
#include <stdint.h>

// Problem constants (fixed shapes per metadata)
constexpr int NN   = 10000;   // nodes
constexpr int NE   = 160000;  // edges
constexpr int DIN  = 128;     // input feature dim
constexpr int EDIM = 16;      // edge feature dim
constexpr int H_   = 4;       // heads
constexpr int C_   = 256;     // channels per head
constexpr int HC   = 1024;    // H*C
constexpr int DOUT = 25088;   // final output dim

constexpr int MPAD = 10112;   // 79 * 128 (M padded)

// ---------------- scratch (static device globals: allocation-free) ----------
__device__ __half g_xw2[NN * HC];         // layer GEMM output (fp16)
__device__ float  g_al_src[NN * H_];
__device__ float  g_al_dst[NN * H_];
__device__ float  g_exp_s[(size_t)H_ * NE];    // exp(alpha-max), SoA CSR-sorted
__device__ float  g_s1[(size_t)H_ * NE];       // raw edge logits layer1 (SoA)
__device__ float  g_s2[(size_t)H_ * NE];       // raw edge logits layer2 (SoA)
__device__ float  g_V1[EDIM * H_];
__device__ float  g_V2[EDIM * H_];
__device__ int    g_deg[NN];
__device__ int    g_rowptr[NN + 1];
__device__ int    g_cursor[NN];
__device__ int    g_esorted[NE];
__device__ int    g_src_s[NE];            // src node per sorted position
__device__ int    g_bsum[40];
__device__ int    g_boff[40];
__device__ __half g_Asp[(size_t)MPAD * HC];     // GEMM A operand (fp16)
__device__ __half g_BtF[(size_t)DOUT * HC];     // Wf^T fp16 [25088,1024]
__device__ __half g_Bt2[(size_t)HC * HC];       // W2^T fp16 [1024,1024]
__device__ __half g_Bt1[(size_t)HC * DIN];      // W1^T fp16 [1024,128]

// ---------------- graph structure kernels ----------------------------------
__global__ void k_zero_deg() {
    int i = blockIdx.x * blockDim.x + threadIdx.x;
    if (i < NN) g_deg[i] = 0;
}

__global__ void k_zero_al() {
    int i = blockIdx.x * blockDim.x + threadIdx.x;
    if (i < NN * H_) { g_al_src[i] = 0.f; g_al_dst[i] = 0.f; }
}

__global__ void k_count(const int* __restrict__ dst) {
    int e = blockIdx.x * blockDim.x + threadIdx.x;
    if (e < NE) atomicAdd(&g_deg[dst[e]], 1);
}

// 3-stage parallel scan of g_deg -> g_rowptr/g_cursor
__global__ void k_scanA() {
    __shared__ int sh[256];
    int i = blockIdx.x * 256 + threadIdx.x;
    sh[threadIdx.x] = (i < NN) ? g_deg[i] : 0;
    __syncthreads();
    for (int off = 128; off; off >>= 1) {
        if (threadIdx.x < off) sh[threadIdx.x] += sh[threadIdx.x + off];
        __syncthreads();
    }
    if (threadIdx.x == 0) g_bsum[blockIdx.x] = sh[0];
}

__global__ void k_scanB() {
    __shared__ int sh[64];
    int t = threadIdx.x;
    int v = (t < 40) ? g_bsum[t] : 0;
    sh[t] = v;
    __syncthreads();
    for (int off = 1; off < 64; off <<= 1) {
        int x = (t >= off) ? sh[t - off] : 0;
        __syncthreads();
        sh[t] += x;
        __syncthreads();
    }
    if (t < 40) g_boff[t] = sh[t] - v;
    if (t == 39) g_rowptr[NN] = sh[39];
}

__global__ void k_scanC() {
    __shared__ int sh[256];
    int i = blockIdx.x * 256 + threadIdx.x;
    int v = (i < NN) ? g_deg[i] : 0;
    sh[threadIdx.x] = v;
    __syncthreads();
    for (int off = 1; off < 256; off <<= 1) {
        int x = (threadIdx.x >= off) ? sh[threadIdx.x - off] : 0;
        __syncthreads();
        sh[threadIdx.x] += x;
        __syncthreads();
    }
    if (i < NN) {
        int excl = sh[threadIdx.x] - v + g_boff[blockIdx.x];
        g_rowptr[i] = excl;
        g_cursor[i] = excl;
    }
}

__global__ void k_fill(const int* __restrict__ dst) {
    int e = blockIdx.x * blockDim.x + threadIdx.x;
    if (e < NE) {
        int p = atomicAdd(&g_cursor[dst[e]], 1);
        g_esorted[p] = e;
    }
}

// ---------------- attention logit pieces ------------------------------------
__global__ void k_V(const float* __restrict__ We, const float* __restrict__ aedge,
                    float* __restrict__ Vout) {
    int w = threadIdx.x >> 5, l = threadIdx.x & 31;
    for (int o = w; o < EDIM * H_; o += 8) {
        int d = o / H_, h = o % H_;
        float s = 0.f;
        for (int c = l; c < C_; c += 32)
            s += We[(size_t)d * HC + h * C_ + c] * aedge[h * C_ + c];
#pragma unroll
        for (int off = 16; off; off >>= 1) s += __shfl_xor_sync(0xffffffffu, s, off);
        if (l == 0) Vout[o] = s;
    }
}

// One pass over CSR-sorted positions (layer-independent): gathers edge
// features once, emits src ids + raw edge logits for BOTH layers.
__global__ void k_edgeprep(const float* __restrict__ ef, const int* __restrict__ src) {
    __shared__ float sV1[EDIM * H_], sV2[EDIM * H_];
    if (threadIdx.x < EDIM * H_) {
        sV1[threadIdx.x] = g_V1[threadIdx.x];
        sV2[threadIdx.x] = g_V2[threadIdx.x];
    }
    __syncthreads();
    int i = blockIdx.x * blockDim.x + threadIdx.x;
    if (i >= NE) return;
    int e  = g_esorted[i];
    g_src_s[i] = src[e];
    float ea[EDIM];
    const float4* efp = reinterpret_cast<const float4*>(ef + (size_t)e * EDIM);
#pragma unroll
    for (int q = 0; q < EDIM / 4; q++) {
        float4 v = efp[q];
        ea[q * 4 + 0] = v.x; ea[q * 4 + 1] = v.y; ea[q * 4 + 2] = v.z; ea[q * 4 + 3] = v.w;
    }
#pragma unroll
    for (int h = 0; h < H_; h++) {
        float s1 = 0.f, s2 = 0.f;
#pragma unroll
        for (int d = 0; d < EDIM; d++) {
            s1 += ea[d] * sV1[d * H_ + h];
            s2 += ea[d] * sV2[d * H_ + h];
        }
        g_s1[(size_t)h * NE + i] = s1;
        g_s2[(size_t)h * NE + i] = s2;
    }
}

// ---------------- segment softmax + aggregation (1 block / node) ------------
// Alpha recomputed from raw logits on the fly.  8 warps: warp w handles head
// (w&3), slice (w>>2) of the CSR range in phases 0-2; phase 3 uses all 256
// threads for the channel-parallel gather.
__global__ void __launch_bounds__(256)
k_aggregate(const __half* __restrict__ xw2, const float* __restrict__ sL,
            const float* __restrict__ bias, __half* __restrict__ outH) {
    int n = blockIdx.x;
    int beg = g_rowptr[n], end = g_rowptr[n + 1];
    __shared__ float sm[H_], ss[H_], sself[H_];
    __shared__ float p_es[2][H_], p_mx[2][H_], p_ac[2][H_];
    int t = threadIdx.x, w = t >> 5, l = t & 31;
    const int hh = w & 3, sl = w >> 2;

    // phase 0+1 fused: esum (raw s) + max (leaky alpha) over this warp's slice
    {
        const float* ssrc = sL + (size_t)hh * NE;
        const float ald = g_al_dst[n * H_ + hh];
        float es = 0.f, mx = -1e30f;
        for (int i = beg + l + 32 * sl; i < end; i += 64) {
            float s = ssrc[i];
            es += s;
            float a = g_al_src[g_src_s[i] * H_ + hh] + ald + s;
            a = a > 0.f ? a : 0.2f * a;
            mx = fmaxf(mx, a);
        }
#pragma unroll
        for (int off = 16; off; off >>= 1) {
            es += __shfl_xor_sync(0xffffffffu, es, off);
            mx = fmaxf(mx, __shfl_xor_sync(0xffffffffu, mx, off));
        }
        if (l == 0) { p_es[sl][hh] = es; p_mx[sl][hh] = mx; }
    }
    __syncthreads();
    if (t < H_) {
        float es = p_es[0][t] + p_es[1][t];
        float mx = fmaxf(p_mx[0][t], p_mx[1][t]);
        float invd = 1.0f / fmaxf((float)(end - beg), 1.0f);
        float v = g_al_src[n * H_ + t] + g_al_dst[n * H_ + t] + es * invd;
        v = v > 0.f ? v : 0.2f * v;
        sself[t] = v;
        sm[t] = fmaxf(mx, v);
    }
    __syncthreads();

    // phase 2: recompute alpha, exp, store exp; accumulate sum over slice
    {
        float mm = sm[hh];
        const float* ssrc = sL + (size_t)hh * NE;
        const float ald = g_al_dst[n * H_ + hh];
        float* ex_out = g_exp_s + (size_t)hh * NE;
        float acc = 0.f;
        for (int i = beg + l + 32 * sl; i < end; i += 64) {
            float a = g_al_src[g_src_s[i] * H_ + hh] + ald + ssrc[i];
            a = a > 0.f ? a : 0.2f * a;
            float ex = expf(a - mm);
            ex_out[i] = ex;
            acc += ex;
        }
#pragma unroll
        for (int off = 16; off; off >>= 1) acc += __shfl_xor_sync(0xffffffffu, acc, off);
        if (l == 0) p_ac[sl][hh] = acc;
    }
    __syncthreads();
    if (t < H_)
        ss[t] = p_ac[0][t] + p_ac[1][t] + expf(sself[t] - sm[t]);
    __syncthreads();

    // phase 3: weighted gather. thread t owns channels 4t..4t+3 (head h = t>>6).
    const int h = t >> 6;
    const float inv = 1.0f / (ss[h] + 1e-16f);
    const float* exh = g_exp_s + (size_t)h * NE;
    float a0 = 0.f, a1 = 0.f, a2 = 0.f, a3 = 0.f;
    for (int i = beg; i < end; i++) {
        int sn = g_src_s[i];
        float wg = exh[i];
        uint2 rv = *reinterpret_cast<const uint2*>(xw2 + (size_t)sn * HC + 4 * t);
        __half2 p0 = *reinterpret_cast<__half2*>(&rv.x);
        __half2 p1 = *reinterpret_cast<__half2*>(&rv.y);
        a0 += wg * __low2float(p0); a1 += wg * __high2float(p0);
        a2 += wg * __low2float(p1); a3 += wg * __high2float(p1);
    }
    {   // self loop
        float wg = expf(sself[h] - sm[h]);
        uint2 rv = *reinterpret_cast<const uint2*>(xw2 + (size_t)n * HC + 4 * t);
        __half2 p0 = *reinterpret_cast<__half2*>(&rv.x);
        __half2 p1 = *reinterpret_cast<__half2*>(&rv.y);
        a0 += wg * __low2float(p0); a1 += wg * __high2float(p0);
        a2 += wg * __low2float(p1); a3 += wg * __high2float(p1);
    }
    float4 b4 = *reinterpret_cast<const float4*>(bias + 4 * t);
    float v0 = a0 * inv + b4.x, v1 = a1 * inv + b4.y;
    float v2 = a2 * inv + b4.z, v3 = a3 * inv + b4.w;
    v0 = v0 > 0.f ? v0 : expm1f(v0);
    v1 = v1 > 0.f ? v1 : expm1f(v1);
    v2 = v2 > 0.f ? v2 : expm1f(v2);
    v3 = v3 > 0.f ? v3 : expm1f(v3);
    uint2 ov;
    *reinterpret_cast<__half2*>(&ov.x) = __floats2half2_rn(v0, v1);
    *reinterpret_cast<__half2*>(&ov.y) = __floats2half2_rn(v2, v3);
    *reinterpret_cast<uint2*>(outH + (size_t)n * HC + 4 * t) = ov;
}

// ---------------- fp16 conversions ------------------------------------------
__global__ void k_convA(const float* __restrict__ src, __half* __restrict__ dst,
                        int Mv, int K) {
    int i = blockIdx.x * blockDim.x + threadIdx.x;
    if (i >= MPAD * K) return;
    int m = i / K, k = i - m * K;
    float a = (m < Mv) ? src[(size_t)m * K + k] : 0.f;
    dst[(size_t)m * K + k] = __float2half(a);
}

__global__ void k_convB(const float* __restrict__ W, __half* __restrict__ dst,
                        int K, int Nn) {
    __shared__ float t[32][33];
    int n = blockIdx.x * 32 + threadIdx.x;
    int k = blockIdx.y * 32 + threadIdx.y;
    t[threadIdx.y][threadIdx.x] = W[(size_t)k * Nn + n];
    __syncthreads();
    int n2 = blockIdx.x * 32 + threadIdx.y;
    int k2 = blockIdx.y * 32 + threadIdx.x;
    dst[(size_t)n2 * K + k2] = __float2half(t[threadIdx.x][threadIdx.y]);
}

// ---------------- fp16 HMMA GEMM --------------------------------------------
// CTA tile 128x128, 128 threads (4 warps, warp tile 64x64), BK=32,
// 4-stage cp.async pipeline (64 KB smem), 2 CTAs/SM.
// AL=true: additionally accumulates al_src/al_dst row-dot-products into
// global via quad-reduce + atomicAdd (fuses the old k_al pass).

__device__ __forceinline__ uint32_t s2u(const void* p) {
    uint32_t a;
    asm("{ .reg .u64 t; cvta.to.shared.u64 t, %1; cvt.u32.u64 %0, t; }" : "=r"(a) : "l"(p));
    return a;
}

__device__ __forceinline__ void cp16(uint32_t saddr, const void* gptr) {
    asm volatile("cp.async.cg.shared.global [%0], [%1], 16;" :: "r"(saddr), "l"(gptr));
}

#define LDSM4(r, addr) \
    asm volatile("ldmatrix.sync.aligned.m8n8.x4.shared.b16 {%0,%1,%2,%3}, [%4];" \
        : "=r"((r)[0]), "=r"((r)[1]), "=r"((r)[2]), "=r"((r)[3]) : "r"(addr))

#define MMA16816(c, a, b0, b1) \
    asm volatile("mma.sync.aligned.m16n8k16.row.col.f32.f16.f16.f32 " \
        "{%0,%1,%2,%3}, {%4,%5,%6,%7}, {%8,%9}, {%0,%1,%2,%3};" \
        : "+f"((c)[0]), "+f"((c)[1]), "+f"((c)[2]), "+f"((c)[3]) \
        : "r"((a)[0]), "r"((a)[1]), "r"((a)[2]), "r"((a)[3]), "r"(b0), "r"(b1))

constexpr int STAGE_BYTES = 16384;              // A 8KB + B 8KB
constexpr int MMA_SMEM    = 4 * STAGE_BYTES;    // 64 KB

template <bool BIAS, bool AL>
__global__ void __launch_bounds__(128, 2)
k_mma_gemm(const __half* __restrict__ A, const __half* __restrict__ B,
           const float* __restrict__ bias, float* __restrict__ outF,
           __half* __restrict__ outH, const float* __restrict__ asv,
           const float* __restrict__ adv, int Mv, int K, int ldo) {
    extern __shared__ char smem[];
    const uint32_t sb = s2u(smem);
    const int tid  = threadIdx.x;
    const int lane = tid & 31, wid = tid >> 5;
    const int wm = (wid & 1) * 64, wn = (wid >> 1) * 64;
    const int bm = blockIdx.x * 128, bn = blockIdx.y * 128;
    const int KITER = K >> 5;

    const __half* ag0 = A + (size_t)bm * K;
    const __half* bg0 = B + (size_t)bn * K;

    auto load_stage = [&](int kt, int slot) {
        const int k0 = kt * 32;
        const uint32_t sa  = sb + slot * STAGE_BYTES;
        const uint32_t sbm = sa + 8192;
#pragma unroll
        for (int i = 0; i < 4; i++) {
            int u = tid + i * 128;
            int row = u >> 2, seg = u & 3;
            uint32_t off = row * 64 + ((seg ^ ((row >> 1) & 3)) << 4);
            cp16(sa  + off, ag0 + (size_t)row * K + k0 + seg * 8);
            cp16(sbm + off, bg0 + (size_t)row * K + k0 + seg * 8);
        }
    };

    float acc[4][8][4];
#pragma unroll
    for (int i = 0; i < 4; i++)
#pragma unroll
        for (int j = 0; j < 8; j++)
#pragma unroll
            for (int r = 0; r < 4; r++) acc[i][j][r] = 0.f;

    load_stage(0, 0);
    asm volatile("cp.async.commit_group;" ::: "memory");
    load_stage(1, 1);
    asm volatile("cp.async.commit_group;" ::: "memory");
    load_stage(2, 2);
    asm volatile("cp.async.commit_group;" ::: "memory");

    for (int kt = 0; kt < KITER; kt++) {
        asm volatile("cp.async.wait_group 2;" ::: "memory");
        __syncthreads();
        if (kt + 3 < KITER) load_stage(kt + 3, (kt + 3) & 3);
        asm volatile("cp.async.commit_group;" ::: "memory");

        const uint32_t sa  = sb + (kt & 3) * STAGE_BYTES;
        const uint32_t sbm = sa + 8192;
#pragma unroll
        for (int ks2 = 0; ks2 < 2; ks2++) {
            uint32_t av[4][4], bv[4][4];
            const int segk = ks2 * 2 + (lane >> 4);
#pragma unroll
            for (int mf = 0; mf < 4; mf++) {
                int row = wm + mf * 16 + (lane & 15);
                LDSM4(av[mf], sa + row * 64 + ((segk ^ ((row >> 1) & 3)) << 4));
            }
#pragma unroll
            for (int p = 0; p < 4; p++) {
                int row = wn + p * 16 + (lane & 15);
                LDSM4(bv[p], sbm + row * 64 + ((segk ^ ((row >> 1) & 3)) << 4));
            }
#pragma unroll
            for (int mf = 0; mf < 4; mf++)
#pragma unroll
                for (int p = 0; p < 4; p++) {
                    MMA16816(acc[mf][p * 2 + 0], av[mf], bv[p][0], bv[p][2]);
                    MMA16816(acc[mf][p * 2 + 1], av[mf], bv[p][1], bv[p][3]);
                }
        }
    }

    // epilogue
    const int r0 = lane >> 2, c0 = (lane & 3) * 2;

    // attention-vector column slices for fused al (AL only)
    float avv[8][2], dvv[8][2];
    if (AL) {
#pragma unroll
        for (int nf = 0; nf < 8; nf++) {
            int nn = bn + wn + nf * 8 + c0;
            avv[nf][0] = __ldg(asv + nn); avv[nf][1] = __ldg(asv + nn + 1);
            dvv[nf][0] = __ldg(adv + nn); dvv[nf][1] = __ldg(adv + nn + 1);
        }
    }
    const int head = (bn + wn) >> 8;   // 64-col warp tile lies in one head

#pragma unroll
    for (int mf = 0; mf < 4; mf++) {
#pragma unroll
        for (int half = 0; half < 2; half++) {
            int m = bm + wm + mf * 16 + r0 + half * 8;
            float pa = 0.f, pd = 0.f;
            if (m < Mv) {
#pragma unroll
                for (int nf = 0; nf < 8; nf++) {
                    int n = bn + wn + nf * 8 + c0;
                    float vx = acc[mf][nf][half * 2 + 0];
                    float vy = acc[mf][nf][half * 2 + 1];
                    if (AL) {
                        pa += vx * avv[nf][0] + vy * avv[nf][1];
                        pd += vx * dvv[nf][0] + vy * dvv[nf][1];
                    }
                    if (BIAS) {
                        vx += __ldg(bias + n); vy += __ldg(bias + n + 1);
                        *reinterpret_cast<float2*>(outF + (size_t)m * ldo + n) =
                            make_float2(vx, vy);
                    } else {
                        *reinterpret_cast<__half2*>(outH + (size_t)m * ldo + n) =
                            __floats2half2_rn(vx, vy);
                    }
                }
            }
            if (AL) {
                pa += __shfl_xor_sync(0xffffffffu, pa, 1);
                pa += __shfl_xor_sync(0xffffffffu, pa, 2);
                pd += __shfl_xor_sync(0xffffffffu, pd, 1);
                pd += __shfl_xor_sync(0xffffffffu, pd, 2);
                if ((lane & 3) == 0 && m < Mv) {
                    atomicAdd(&g_al_src[m * H_ + head], pa);
                    atomicAdd(&g_al_dst[m * H_ + head], pd);
                }
            }
        }
    }
}

// ---------------- launch -----------------------------------------------------
extern "C" void kernel_launch(void* const* d_in, const int* in_sizes, int n_in,
                              void* d_out, int out_size) {
    const float* x      = (const float*)d_in[0];
    const int*   ei     = (const int*)d_in[1];
    const float* ef     = (const float*)d_in[2];
    const float* W1     = (const float*)d_in[3];
    const float* asrc1  = (const float*)d_in[4];
    const float* adst1  = (const float*)d_in[5];
    const float* aedge1 = (const float*)d_in[6];
    const float* We1    = (const float*)d_in[7];
    const float* b1     = (const float*)d_in[8];
    const float* W2     = (const float*)d_in[9];
    const float* asrc2  = (const float*)d_in[10];
    const float* adst2  = (const float*)d_in[11];
    const float* aedge2 = (const float*)d_in[12];
    const float* We2    = (const float*)d_in[13];
    const float* b2     = (const float*)d_in[14];
    const float* Wf     = (const float*)d_in[15];
    const float* bf     = (const float*)d_in[16];
    const int* src = ei;
    const int* dst = ei + NE;
    float* out = (float*)d_out;

    void* p;
    cudaGetSymbolAddress(&p, g_xw2); __half* xw2 = (__half*)p;
    cudaGetSymbolAddress(&p, g_Asp); __half* Asp = (__half*)p;
    cudaGetSymbolAddress(&p, g_BtF); __half* BtF = (__half*)p;
    cudaGetSymbolAddress(&p, g_Bt2); __half* Bt2 = (__half*)p;
    cudaGetSymbolAddress(&p, g_Bt1); __half* Bt1 = (__half*)p;
    cudaGetSymbolAddress(&p, g_V1);  float* V1  = (float*)p;
    cudaGetSymbolAddress(&p, g_V2);  float* V2  = (float*)p;
    cudaGetSymbolAddress(&p, g_s1);  float* s1p = (float*)p;
    cudaGetSymbolAddress(&p, g_s2);  float* s2p = (float*)p;

    static bool init_done = false;
    static cudaStream_t s1;
    static cudaEvent_t evFork, evB12, evPre, evBF;
    if (!init_done) {
        cudaFuncSetAttribute((const void*)k_mma_gemm<true, false>,
                             cudaFuncAttributeMaxDynamicSharedMemorySize, MMA_SMEM);
        cudaFuncSetAttribute((const void*)k_mma_gemm<false, true>,
                             cudaFuncAttributeMaxDynamicSharedMemorySize, MMA_SMEM);
        cudaStreamCreateWithFlags(&s1, cudaStreamNonBlocking);
        cudaEventCreateWithFlags(&evFork, cudaEventDisableTiming);
        cudaEventCreateWithFlags(&evB12,  cudaEventDisableTiming);
        cudaEventCreateWithFlags(&evPre,  cudaEventDisableTiming);
        cudaEventCreateWithFlags(&evBF,   cudaEventDisableTiming);
        init_done = true;
    }

    // fork side stream
    cudaEventRecord(evFork, 0);
    cudaStreamWaitEvent(s1, evFork, 0);

    // side: layer weights first (GEMM1 needs Bt1)
    k_convB<<<dim3(HC / 32, DIN / 32), dim3(32, 32), 0, s1>>>(W1, Bt1, DIN, HC);
    k_convB<<<dim3(HC / 32, HC / 32), dim3(32, 32), 0, s1>>>(W2, Bt2, HC, HC);
    cudaEventRecord(evB12, s1);
    // side: V's + CSR + edge prep (layer-activation independent)
    k_V<<<1, 256, 0, s1>>>(We1, aedge1, V1);
    k_V<<<1, 256, 0, s1>>>(We2, aedge2, V2);
    k_zero_deg<<<(NN + 255) / 256, 256, 0, s1>>>();
    k_count<<<(NE + 255) / 256, 256, 0, s1>>>(dst);
    k_scanA<<<40, 256, 0, s1>>>();
    k_scanB<<<1, 64, 0, s1>>>();
    k_scanC<<<40, 256, 0, s1>>>();
    k_fill<<<(NE + 255) / 256, 256, 0, s1>>>(dst);
    k_edgeprep<<<(NE + 255) / 256, 256, 0, s1>>>(ef, src);
    cudaEventRecord(evPre, s1);
    // side: big final-weight conversion (joins before final GEMM)
    k_convB<<<dim3(DOUT / 32, HC / 32), dim3(32, 32), 0, s1>>>(Wf, BtF, HC, DOUT);
    cudaEventRecord(evBF, s1);

    // main: layer-1 A conversion + al zeroing overlap all of the above
    k_convA<<<(MPAD * DIN + 255) / 256, 256>>>(x, Asp, NN, DIN);
    k_zero_al<<<(NN * H_ + 255) / 256, 256>>>();

    // ---- layer 1 (GEMM fuses al_src/al_dst accumulation) ----
    cudaStreamWaitEvent(0, evB12, 0);
    k_mma_gemm<false, true><<<dim3(MPAD / 128, HC / 128), 128, MMA_SMEM>>>(
        Asp, Bt1, nullptr, nullptr, xw2, asrc1, adst1, NN, DIN, HC);
    cudaStreamWaitEvent(0, evPre, 0);
    k_aggregate<<<NN, 256>>>(xw2, s1p, b1, Asp);

    // ---- layer 2 ----
    k_zero_al<<<(NN * H_ + 255) / 256, 256>>>();
    k_mma_gemm<false, true><<<dim3(MPAD / 128, HC / 128), 128, MMA_SMEM>>>(
        Asp, Bt2, nullptr, nullptr, xw2, asrc2, adst2, NN, HC, HC);
    k_aggregate<<<NN, 256>>>(xw2, s2p, b2, Asp);

    // ---- final linear: out = h2 @ Wf + bf ----
    cudaStreamWaitEvent(0, evBF, 0);
    k_mma_gemm<true, false><<<dim3(MPAD / 128, DOUT / 128), 128, MMA_SMEM>>>(
        Asp, BtF, bf, out, nullptr, nullptr, nullptr, NN, HC, DOUT);
}